// round 8
// baseline (speedup 1.0000x reference)
#include <cuda_runtime.h>
#include <cuda_bf16.h>
#include <math.h>
#include <cstdint>

// Problem constants
#define Bsz   4
#define Ssz   2048
#define Dsz   1024
#define Hsz   16
#define DKsz  64
#define DFFsz 4096
#define Msz   (Bsz*Ssz)   // 8192 rows

typedef __nv_bfloat16 bf16;

// ---------------- scratch (static device globals; no allocation) ----------------
__device__ float g_tmp [(size_t)Msz*Dsz];
__device__ float g_x1  [(size_t)Msz*Dsz];
__device__ float g_gate[(size_t)Msz*Hsz];

__device__ bf16 g_xh [(size_t)Msz*Dsz],   g_xl [(size_t)Msz*Dsz];
__device__ bf16 g_qh [(size_t)Msz*Dsz],   g_ql [(size_t)Msz*Dsz];
__device__ bf16 g_kh [(size_t)Msz*Dsz],   g_kl [(size_t)Msz*Dsz];
__device__ bf16 g_vh [(size_t)Msz*Dsz],   g_vl [(size_t)Msz*Dsz];
__device__ bf16 g_ctxh[(size_t)Msz*Dsz],  g_ctxl[(size_t)Msz*Dsz];
__device__ bf16 g_x1h[(size_t)Msz*Dsz],   g_x1l[(size_t)Msz*Dsz];
__device__ bf16 g_ffh[(size_t)Msz*DFFsz], g_ffl[(size_t)Msz*DFFsz];
__device__ bf16 g_wqh[(size_t)Dsz*Dsz],   g_wql[(size_t)Dsz*Dsz];
__device__ bf16 g_wkh[(size_t)Dsz*Dsz],   g_wkl[(size_t)Dsz*Dsz];
__device__ bf16 g_wvh[(size_t)Dsz*Dsz],   g_wvl[(size_t)Dsz*Dsz];
__device__ bf16 g_woh[(size_t)Dsz*Dsz],   g_wol[(size_t)Dsz*Dsz];
__device__ bf16 g_w1h[(size_t)Dsz*DFFsz], g_w1l[(size_t)Dsz*DFFsz];
__device__ bf16 g_w2h[(size_t)DFFsz*Dsz], g_w2l[(size_t)DFFsz*Dsz];

// ---------------- small helpers ----------------
__device__ __forceinline__ void cp16(uint32_t dst, const void* src) {
    asm volatile("cp.async.ca.shared.global [%0], [%1], 16;\n" :: "r"(dst), "l"(src));
}
__device__ __forceinline__ void cp_commit() {
    asm volatile("cp.async.commit_group;\n");
}
__device__ __forceinline__ void cp_wait0() {
    asm volatile("cp.async.wait_group 0;\n");
}
__device__ __forceinline__ void cp_wait1() {
    asm volatile("cp.async.wait_group 1;\n");
}
__device__ __forceinline__ void ldsm4(uint32_t* r, uint32_t addr) {
    asm volatile("ldmatrix.sync.aligned.m8n8.x4.shared.b16 {%0,%1,%2,%3}, [%4];"
                 : "=r"(r[0]), "=r"(r[1]), "=r"(r[2]), "=r"(r[3]) : "r"(addr));
}
__device__ __forceinline__ void ldsm4t(uint32_t& r0, uint32_t& r1,
                                       uint32_t& r2, uint32_t& r3, uint32_t addr) {
    asm volatile("ldmatrix.sync.aligned.m8n8.x4.trans.shared.b16 {%0,%1,%2,%3}, [%4];"
                 : "=r"(r0), "=r"(r1), "=r"(r2), "=r"(r3) : "r"(addr));
}
__device__ __forceinline__ void mma16816(float* ac, const uint32_t* a,
                                         uint32_t b0, uint32_t b1) {
    asm volatile(
        "mma.sync.aligned.m16n8k16.row.col.f32.bf16.bf16.f32 "
        "{%0,%1,%2,%3},{%4,%5,%6,%7},{%8,%9},{%0,%1,%2,%3};"
        : "+f"(ac[0]), "+f"(ac[1]), "+f"(ac[2]), "+f"(ac[3])
        : "r"(a[0]), "r"(a[1]), "r"(a[2]), "r"(a[3]), "r"(b0), "r"(b1));
}
__device__ __forceinline__ void pack_pair(float a, float b, uint32_t& hi, uint32_t& lo) {
    bf16 ha = __float2bfloat16(a), hb = __float2bfloat16(b);
    bf16 la = __float2bfloat16(a - __bfloat162float(ha));
    bf16 lb = __float2bfloat16(b - __bfloat162float(hb));
    __nv_bfloat162 th = __halves2bfloat162(ha, hb);
    __nv_bfloat162 tl = __halves2bfloat162(la, lb);
    hi = *(uint32_t*)&th; lo = *(uint32_t*)&tl;
}

// ---------------- fused split of x + all 6 weights (one launch) ----------------
struct SplitArgs {
    const float* src[7];
    bf16* hi[7];
    bf16* lo[7];
};
__global__ __launch_bounds__(256)
void split_all_kernel(SplitArgs a)
{
    int bid = blockIdx.x;
    int seg, base;
    if      (bid < 8192)  { seg = 0; base = 0; }
    else if (bid < 9216)  { seg = 1; base = 8192; }
    else if (bid < 10240) { seg = 2; base = 9216; }
    else if (bid < 11264) { seg = 3; base = 10240; }
    else if (bid < 12288) { seg = 4; base = 11264; }
    else if (bid < 16384) { seg = 5; base = 12288; }
    else                  { seg = 6; base = 16384; }
    size_t i = (size_t)(bid - base) * 256 + threadIdx.x;
    float4 v = ((const float4*)a.src[seg])[i];
    uint32_t h0, l0, h1, l1;
    pack_pair(v.x, v.y, h0, l0);
    pack_pair(v.z, v.w, h1, l1);
    uint32_t* hp = (uint32_t*)a.hi[seg];
    uint32_t* lp = (uint32_t*)a.lo[seg];
    hp[2*i] = h0; hp[2*i+1] = h1;
    lp[2*i] = l0; lp[2*i+1] = l1;
}

// ---------------- bf16x3 tensor-core GEMM core ----------
// BM=128, BN=64, BK=16, 128 threads (4 warps 2x2, warp tile 64x32), 3-stage cp.async.
// acc = Ah*Wh + Al*Wh + Ah*Wl. mode bits: 1=GELU, 2=write fp32 C, 4=write bf16 Ch/Cl
#define APAD 24   // A row: 16 elems + 8 pad (48B stride)
#define WPAD 72   // W row: 64 elems + 8 pad (144B stride; 144 mod 128 = 16 -> conflict-free)
#define NSTG 3
#define SA_B (128*APAD*2)   // 6144 B per A buffer
#define SW_B (16*WPAD*2)    // 2304 B per W buffer
#define GEMM_SMEM (3*SA_B*2 + 3*SW_B*2)   // 50688

__device__ __forceinline__
void gemm_core(const bf16* __restrict__ Ah, const bf16* __restrict__ Al,
               const bf16* __restrict__ Wh, const bf16* __restrict__ Wl,
               const float* __restrict__ bias, float* __restrict__ C,
               bf16* __restrict__ Ch, bf16* __restrict__ Cl,
               int N, int K, int mode, int row0, int col0)
{
    extern __shared__ __align__(16) char gdsm[];
    const uint32_t aAh = (uint32_t)__cvta_generic_to_shared(gdsm);
    const uint32_t aAl = aAh + 3*SA_B;
    const uint32_t aWh = aAl + 3*SA_B;
    const uint32_t aWl = aWh + 3*SW_B;

    const int tid = threadIdx.x;

    // A: thread t loads row t (16 elems = 2 cp16 per buffer)
    const char* pAh = (const char*)(Ah + (size_t)(row0 + tid) * K);
    const char* pAl = (const char*)(Al + (size_t)(row0 + tid) * K);
    // W: thread t loads k-row t>>3, col8 = (t&7)*8 (1 cp16 per buffer)
    const char* pWh = (const char*)(Wh + (size_t)(tid>>3) * N + col0 + (tid&7)*8);
    const char* pWl = (const char*)(Wl + (size_t)(tid>>3) * N + col0 + (tid&7)*8);

    const uint32_t dA = (uint32_t)(tid * APAD * 2);
    const uint32_t dW = (uint32_t)(((tid>>3) * WPAD + (tid&7)*8) * 2);

    float acc[4][4][4];
    #pragma unroll
    for (int i = 0; i < 4; i++)
        #pragma unroll
        for (int j = 0; j < 4; j++)
            #pragma unroll
            for (int t = 0; t < 4; t++) acc[i][j][t] = 0.0f;

    const int wid = tid >> 5, lane = tid & 31;
    const int wm = wid & 1;        // M offset wm*64
    const int wn = wid >> 1;       // N offset wn*32
    const uint32_t offA0 = (uint32_t)(((wm*64 + (lane & 15)) * APAD + (lane >> 4)*8) * 2);
    const uint32_t offB0 = (uint32_t)(((lane & 15) * WPAD + wn*32 + (lane>>4)*8) * 2);

    const int nit = K / 16;

    auto load_stage = [&](int st, int it2) {
        size_t ka = (size_t)it2 * 16 * 2;
        size_t kw = (size_t)it2 * 16 * (size_t)N * 2;
        uint32_t sa = aAh + (uint32_t)st*SA_B + dA;
        cp16(sa, pAh + ka);
        cp16(sa + 16, pAh + ka + 16);
        uint32_t sl = aAl + (uint32_t)st*SA_B + dA;
        cp16(sl, pAl + ka);
        cp16(sl + 16, pAl + ka + 16);
        cp16(aWh + (uint32_t)st*SW_B + dW, pWh + kw);
        cp16(aWl + (uint32_t)st*SW_B + dW, pWl + kw);
        cp_commit();
    };

    load_stage(0, 0);
    load_stage(1, 1);

    for (int it = 0; it < nit; ++it) {
        if (it == nit - 1) cp_wait0(); else cp_wait1();
        __syncthreads();
        if (it + 2 < nit)
            load_stage((it + 2) % NSTG, it + 2);
        const uint32_t s = (uint32_t)(it % NSTG);

        uint32_t afh[4][4], afl[4][4];
        #pragma unroll
        for (int mi = 0; mi < 4; mi++)
            ldsm4(afh[mi], aAh + s*SA_B + offA0 + mi*16*APAD*2);
        #pragma unroll
        for (int mi = 0; mi < 4; mi++)
            ldsm4(afl[mi], aAl + s*SA_B + offA0 + mi*16*APAD*2);

        uint32_t bfr[4][2];
        #pragma unroll
        for (int ng = 0; ng < 2; ng++)
            ldsm4t(bfr[2*ng][0], bfr[2*ng][1], bfr[2*ng+1][0], bfr[2*ng+1][1],
                   aWh + s*SW_B + offB0 + (uint32_t)(ng*16*2));
        #pragma unroll
        for (int mi = 0; mi < 4; mi++)
            #pragma unroll
            for (int ni = 0; ni < 4; ni++) {
                mma16816(acc[mi][ni], afh[mi], bfr[ni][0], bfr[ni][1]);
                mma16816(acc[mi][ni], afl[mi], bfr[ni][0], bfr[ni][1]);
            }
        #pragma unroll
        for (int ng = 0; ng < 2; ng++)
            ldsm4t(bfr[2*ng][0], bfr[2*ng][1], bfr[2*ng+1][0], bfr[2*ng+1][1],
                   aWl + s*SW_B + offB0 + (uint32_t)(ng*16*2));
        #pragma unroll
        for (int mi = 0; mi < 4; mi++)
            #pragma unroll
            for (int ni = 0; ni < 4; ni++)
                mma16816(acc[mi][ni], afh[mi], bfr[ni][0], bfr[ni][1]);
    }

    #pragma unroll
    for (int mi = 0; mi < 4; mi++) {
        #pragma unroll
        for (int ni = 0; ni < 4; ni++) {
            int c = col0 + wn*32 + ni*8 + (lane & 3)*2;
            float bx = bias[c], by = bias[c + 1];
            #pragma unroll
            for (int rh = 0; rh < 2; rh++) {
                size_t r = (size_t)(row0 + wm*64 + mi*16 + (lane >> 2) + rh*8);
                float v0 = acc[mi][ni][2*rh]     + bx;
                float v1 = acc[mi][ni][2*rh + 1] + by;
                if (mode & 1) {
                    v0 = 0.5f * v0 * (1.0f + erff(v0 * 0.70710678118654752f));
                    v1 = 0.5f * v1 * (1.0f + erff(v1 * 0.70710678118654752f));
                }
                if (mode & 2) {
                    float2 o; o.x = v0; o.y = v1;
                    *(float2*)&C[r * N + c] = o;
                }
                if (mode & 4) {
                    uint32_t hp, lp;
                    pack_pair(v0, v1, hp, lp);
                    *(uint32_t*)&Ch[r * N + c] = hp;
                    *(uint32_t*)&Cl[r * N + c] = lp;
                }
            }
        }
    }
}

__global__ __launch_bounds__(128, 3)
void gemm_bf16x3_kernel(const bf16* __restrict__ Ah, const bf16* __restrict__ Al,
                        const bf16* __restrict__ Wh, const bf16* __restrict__ Wl,
                        const float* __restrict__ bias, float* __restrict__ C,
                        bf16* __restrict__ Ch, bf16* __restrict__ Cl,
                        int N, int K, int mode)
{
    gemm_core(Ah, Al, Wh, Wl, bias, C, Ch, Cl, N, K, mode,
              blockIdx.y * 128, blockIdx.x * 64);
}

// merged Q/K/V projection: blockIdx.z selects weight/output set
struct QKVArgs {
    const bf16* Wh[3];
    const bf16* Wl[3];
    const float* bias[3];
    bf16* Ch[3];
    bf16* Cl[3];
};
__global__ __launch_bounds__(128, 3)
void qkv_gemm_kernel(const bf16* __restrict__ Ah, const bf16* __restrict__ Al,
                     QKVArgs a)
{
    int z = blockIdx.z;
    gemm_core(Ah, Al, a.Wh[z], a.Wl[z], a.bias[z], nullptr, a.Ch[z], a.Cl[z],
              Dsz, Dsz, 4, blockIdx.y * 128, blockIdx.x * 64);
}

// ---------------- sigmoid gate ----------------------
__global__ __launch_bounds__(256)
void gate_kernel(const float* __restrict__ x, const float* __restrict__ wg,
                 const float* __restrict__ bg, float* __restrict__ gate)
{
    __shared__ float wgs[Dsz][8];
    int hg = blockIdx.y;
    int tid = threadIdx.x;
    for (int idx = tid; idx < Dsz*8; idx += 256)
        wgs[idx >> 3][idx & 7] = wg[(idx >> 3) * Hsz + hg*8 + (idx & 7)];
    __syncthreads();

    int h = tid & 7, r = tid >> 3;
    int m = blockIdx.x * 32 + r;
    const float4* xr = (const float4*)(x + (size_t)m * Dsz);
    float s = 0.0f;
    #pragma unroll 4
    for (int d4 = 0; d4 < Dsz/4; d4++) {
        float4 xv = xr[d4];
        s = fmaf(xv.x, wgs[d4*4 + 0][h], s);
        s = fmaf(xv.y, wgs[d4*4 + 1][h], s);
        s = fmaf(xv.z, wgs[d4*4 + 2][h], s);
        s = fmaf(xv.w, wgs[d4*4 + 3][h], s);
    }
    s += bg[hg*8 + h];
    gate[(size_t)m * Hsz + hg*8 + h] = 1.0f / (1.0f + __expf(-s));
}

// ---------------- tensor-core flash attention ----------------
#define FPAD 72
#define KV_STRIDE (64*FPAD)
#define STAGE_ELEMS (4*KV_STRIDE)
#define FLASH_SMEM (2*STAGE_ELEMS*2 + 2*64*4)

__global__ __launch_bounds__(128, 3)
void flash_tc_kernel(const bf16* __restrict__ Qh, const bf16* __restrict__ Ql,
                     const bf16* __restrict__ Kh, const bf16* __restrict__ Kl,
                     const bf16* __restrict__ Vh, const bf16* __restrict__ Vl,
                     const float* __restrict__ gate, const int* __restrict__ mask,
                     bf16* __restrict__ Ch, bf16* __restrict__ Cl)
{
    extern __shared__ __align__(16) char dynsmem[];
    int* smsk = (int*)(dynsmem + (size_t)2*STAGE_ELEMS*2);

    const int tid = threadIdx.x, lane = tid & 31, warp = tid >> 5;
    const int qt = blockIdx.x, h = blockIdx.y, b = blockIdx.z;
    const size_t rowbase = (size_t)b * Ssz;
    const size_t hoff = (size_t)h * DKsz;

    const uint32_t sbase = (uint32_t)__cvta_generic_to_shared(dynsmem);
    const uint32_t mbase = (uint32_t)__cvta_generic_to_shared(smsk);

    {
        int r = tid >> 1;
        size_t gq = (rowbase + qt*64 + r) * Dsz + hoff;
        #pragma unroll
        for (int j = 0; j < 4; j++) {
            int c8 = (tid & 1)*4 + j;
            uint32_t dof = (uint32_t)((r*FPAD + c8*8)*2);
            cp16(sbase + 0*KV_STRIDE*2 + dof, Qh + gq + c8*8);
            cp16(sbase + 1*KV_STRIDE*2 + dof, Ql + gq + c8*8);
        }
        cp_commit(); cp_wait0();
    }
    __syncthreads();

    uint32_t qfh[4][4], qfl[4][4];
    {
        uint32_t arow = (uint32_t)((warp*16 + (lane&15))*FPAD*2);
        #pragma unroll
        for (int ks = 0; ks < 4; ks++) {
            uint32_t acol = (uint32_t)((16*ks + (lane>>4)*8)*2);
            ldsm4(qfh[ks], sbase + 0*KV_STRIDE*2 + arow + acol);
            ldsm4(qfl[ks], sbase + 1*KV_STRIDE*2 + arow + acol);
        }
    }
    __syncthreads();

    float oacc[8][4];
    #pragma unroll
    for (int i = 0; i < 8; i++)
        #pragma unroll
        for (int j = 0; j < 4; j++) oacc[i][j] = 0.0f;
    float m0 = -1e30f, m1 = -1e30f, l0 = 0.0f, l1 = 0.0f;

    const int r_ld = tid >> 1;
    const int cbase = (tid & 1)*4;

    {
        size_t g = (rowbase + r_ld) * Dsz + hoff;
        #pragma unroll
        for (int j = 0; j < 4; j++) {
            int c8 = cbase + j;
            uint32_t dof = (uint32_t)((r_ld*FPAD + c8*8)*2);
            cp16(sbase + 0*KV_STRIDE*2 + dof, Kh + g + c8*8);
            cp16(sbase + 1*KV_STRIDE*2 + dof, Kl + g + c8*8);
            cp16(sbase + 2*KV_STRIDE*2 + dof, Vh + g + c8*8);
            cp16(sbase + 3*KV_STRIDE*2 + dof, Vl + g + c8*8);
        }
        if (tid < 16) cp16(mbase + tid*16, mask + rowbase + tid*4);
        cp_commit();
    }

    const int col0 = 2*(lane & 3);

    for (int kt = 0; kt < Ssz/64; kt++) {
        cp_wait0();
        __syncthreads();
        if (kt + 1 < Ssz/64) {
            int st = (kt + 1) & 1;
            size_t g = (rowbase + (kt+1)*64 + r_ld) * Dsz + hoff;
            uint32_t sb = sbase + (uint32_t)(st*STAGE_ELEMS*2);
            #pragma unroll
            for (int j = 0; j < 4; j++) {
                int c8 = cbase + j;
                uint32_t dof = (uint32_t)((r_ld*FPAD + c8*8)*2);
                cp16(sb + 0*KV_STRIDE*2 + dof, Kh + g + c8*8);
                cp16(sb + 1*KV_STRIDE*2 + dof, Kl + g + c8*8);
                cp16(sb + 2*KV_STRIDE*2 + dof, Vh + g + c8*8);
                cp16(sb + 3*KV_STRIDE*2 + dof, Vl + g + c8*8);
            }
            if (tid < 16) cp16(mbase + st*256 + tid*16, mask + rowbase + (kt+1)*64 + tid*4);
            cp_commit();
        }
        const int st = kt & 1;
        const uint32_t kb = sbase + (uint32_t)(st*STAGE_ELEMS*2);

        float sc[8][4];
        #pragma unroll
        for (int i = 0; i < 8; i++)
            #pragma unroll
            for (int j = 0; j < 4; j++) sc[i][j] = 0.0f;

        const uint32_t brow = (uint32_t)(((lane&7) + ((lane>>1)&8)) * FPAD * 2);
        const uint32_t bcol = (uint32_t)((lane & 8) * 2);
        #pragma unroll
        for (int ng = 0; ng < 4; ng++) {
            #pragma unroll
            for (int ks = 0; ks < 4; ks++) {
                uint32_t ba = kb + brow + (uint32_t)(16*ng*FPAD*2) + bcol + (uint32_t)(16*ks*2);
                uint32_t bh4[4], bl4[4];
                ldsm4(bh4, ba);
                ldsm4(bl4, ba + KV_STRIDE*2);
                mma16816(sc[2*ng],   qfh[ks], bh4[0], bh4[1]);
                mma16816(sc[2*ng+1], qfh[ks], bh4[2], bh4[3]);
                mma16816(sc[2*ng],   qfl[ks], bh4[0], bh4[1]);
                mma16816(sc[2*ng+1], qfl[ks], bh4[2], bh4[3]);
                mma16816(sc[2*ng],   qfh[ks], bl4[0], bl4[1]);
                mma16816(sc[2*ng+1], qfh[ks], bl4[2], bl4[3]);
            }
        }

        const int* mk = smsk + st*64;
        float mx0 = -1e30f, mx1 = -1e30f;
        #pragma unroll
        for (int ni = 0; ni < 8; ni++) {
            int c = 8*ni + col0;
            bool z0 = (mk[c] == 0), z1 = (mk[c+1] == 0);
            sc[ni][0] = z0 ? -1e9f : sc[ni][0]*0.125f;
            sc[ni][1] = z1 ? -1e9f : sc[ni][1]*0.125f;
            sc[ni][2] = z0 ? -1e9f : sc[ni][2]*0.125f;
            sc[ni][3] = z1 ? -1e9f : sc[ni][3]*0.125f;
            mx0 = fmaxf(mx0, fmaxf(sc[ni][0], sc[ni][1]));
            mx1 = fmaxf(mx1, fmaxf(sc[ni][2], sc[ni][3]));
        }
        mx0 = fmaxf(mx0, __shfl_xor_sync(0xffffffffu, mx0, 1));
        mx0 = fmaxf(mx0, __shfl_xor_sync(0xffffffffu, mx0, 2));
        mx1 = fmaxf(mx1, __shfl_xor_sync(0xffffffffu, mx1, 1));
        mx1 = fmaxf(mx1, __shfl_xor_sync(0xffffffffu, mx1, 2));
        float mn0 = fmaxf(m0, mx0), mn1 = fmaxf(m1, mx1);
        float al0 = __expf(m0 - mn0), al1 = __expf(m1 - mn1);
        float rs0 = 0.0f, rs1 = 0.0f;
        #pragma unroll
        for (int ni = 0; ni < 8; ni++) {
            sc[ni][0] = __expf(sc[ni][0] - mn0);
            sc[ni][1] = __expf(sc[ni][1] - mn0);
            sc[ni][2] = __expf(sc[ni][2] - mn1);
            sc[ni][3] = __expf(sc[ni][3] - mn1);
            rs0 += sc[ni][0] + sc[ni][1];
            rs1 += sc[ni][2] + sc[ni][3];
        }
        rs0 += __shfl_xor_sync(0xffffffffu, rs0, 1);
        rs0 += __shfl_xor_sync(0xffffffffu, rs0, 2);
        rs1 += __shfl_xor_sync(0xffffffffu, rs1, 1);
        rs1 += __shfl_xor_sync(0xffffffffu, rs1, 2);
        l0 = l0*al0 + rs0; l1 = l1*al1 + rs1;
        m0 = mn0; m1 = mn1;
        #pragma unroll
        for (int ni = 0; ni < 8; ni++) {
            oacc[ni][0] *= al0; oacc[ni][1] *= al0;
            oacc[ni][2] *= al1; oacc[ni][3] *= al1;
        }

        const uint32_t vrow0 = (uint32_t)((lane&15)*FPAD*2);
        const uint32_t vcol0 = (uint32_t)(((lane>>4)*8)*2);
        #pragma unroll
        for (int ki = 0; ki < 4; ki++) {
            uint32_t ph[4], pl[4];
            pack_pair(sc[2*ki][0],   sc[2*ki][1],   ph[0], pl[0]);
            pack_pair(sc[2*ki][2],   sc[2*ki][3],   ph[1], pl[1]);
            pack_pair(sc[2*ki+1][0], sc[2*ki+1][1], ph[2], pl[2]);
            pack_pair(sc[2*ki+1][2], sc[2*ki+1][3], ph[3], pl[3]);
            uint32_t va0 = kb + 2*KV_STRIDE*2 + vrow0 + (uint32_t)(16*ki*FPAD*2) + vcol0;
            #pragma unroll
            for (int ngd = 0; ngd < 4; ngd++) {
                uint32_t vh4[4], vl4[4];
                ldsm4t(vh4[0], vh4[1], vh4[2], vh4[3], va0 + (uint32_t)(16*ngd*2));
                ldsm4t(vl4[0], vl4[1], vl4[2], vl4[3], va0 + KV_STRIDE*2 + (uint32_t)(16*ngd*2));
                mma16816(oacc[2*ngd],   ph, vh4[0], vh4[1]);
                mma16816(oacc[2*ngd+1], ph, vh4[2], vh4[3]);
                mma16816(oacc[2*ngd],   ph, vl4[0], vl4[1]);
                mma16816(oacc[2*ngd+1], ph, vl4[2], vl4[3]);
                mma16816(oacc[2*ngd],   pl, vh4[0], vh4[1]);
                mma16816(oacc[2*ngd+1], pl, vh4[2], vh4[3]);
            }
        }
    }

    int q0 = qt*64 + warp*16 + (lane >> 2);
    float f0 = gate[(rowbase + q0)*Hsz + h] / l0;
    float f1 = gate[(rowbase + q0 + 8)*Hsz + h] / l1;
    #pragma unroll
    for (int ni = 0; ni < 8; ni++) {
        size_t o0 = (rowbase + q0) * Dsz + hoff + 8*ni + col0;
        size_t o1 = o0 + (size_t)8 * Dsz;
        uint32_t hp, lp;
        pack_pair(oacc[ni][0]*f0, oacc[ni][1]*f0, hp, lp);
        *(uint32_t*)&Ch[o0] = hp;
        *(uint32_t*)&Cl[o0] = lp;
        pack_pair(oacc[ni][2]*f1, oacc[ni][3]*f1, hp, lp);
        *(uint32_t*)&Ch[o1] = hp;
        *(uint32_t*)&Cl[o1] = lp;
    }
}

// ---------------- fused residual add + LayerNorm (+ optional bf16 split out) ----
__global__ __launch_bounds__(256)
void add_ln_kernel(const float* __restrict__ a, const float* __restrict__ bsrc,
                   const float* __restrict__ g, const float* __restrict__ beta,
                   float* __restrict__ out, bf16* __restrict__ oh, bf16* __restrict__ ol)
{
    int row = blockIdx.x;
    int tid = threadIdx.x;
    __shared__ float buf[Dsz];
    __shared__ float rsum[8], rsq[8];

    size_t base = (size_t)row * Dsz;
    float ls = 0.0f, lq = 0.0f;
    for (int d = tid; d < Dsz; d += 256) {
        float v = a[base + d] + bsrc[base + d];
        buf[d] = v;
        ls += v; lq += v * v;
    }
    int warp = tid >> 5, lane = tid & 31;
    for (int off = 16; off; off >>= 1) {
        ls += __shfl_xor_sync(0xffffffffu, ls, off);
        lq += __shfl_xor_sync(0xffffffffu, lq, off);
    }
    if (lane == 0) { rsum[warp] = ls; rsq[warp] = lq; }
    __syncthreads();
    float ts = 0.0f, tq = 0.0f;
    #pragma unroll
    for (int w = 0; w < 8; w++) { ts += rsum[w]; tq += rsq[w]; }
    float mean = ts * (1.0f / Dsz);
    float var  = tq * (1.0f / Dsz) - mean * mean;
    float rstd = rsqrtf(var + 1e-5f);
    for (int d = tid; d < Dsz; d += 256) {
        float v = (buf[d] - mean) * rstd * g[d] + beta[d];
        out[base + d] = v;
        if (oh) {
            bf16 hv = __float2bfloat16(v);
            oh[base + d] = hv;
            ol[base + d] = __float2bfloat16(v - __bfloat162float(hv));
        }
    }
}

// ---------------- launch ----------------
extern "C" void kernel_launch(void* const* d_in, const int* in_sizes, int n_in,
                              void* d_out, int out_size)
{
    const float* x     = (const float*)d_in[0];
    const float* w_q   = (const float*)d_in[1];
    const float* b_q   = (const float*)d_in[2];
    const float* w_k   = (const float*)d_in[3];
    const float* b_k   = (const float*)d_in[4];
    const float* w_v   = (const float*)d_in[5];
    const float* b_v   = (const float*)d_in[6];
    const float* w_o   = (const float*)d_in[7];
    const float* b_o   = (const float*)d_in[8];
    const float* w_g   = (const float*)d_in[9];
    const float* b_g   = (const float*)d_in[10];
    const float* w1    = (const float*)d_in[11];
    const float* b1    = (const float*)d_in[12];
    const float* w2    = (const float*)d_in[13];
    const float* b2    = (const float*)d_in[14];
    const float* g1    = (const float*)d_in[15];
    const float* beta1 = (const float*)d_in[16];
    const float* g2    = (const float*)d_in[17];
    const float* beta2 = (const float*)d_in[18];
    const int*   mask  = (const int*)  d_in[19];
    float* out = (float*)d_out;

    float *tmp, *x1, *gate;
    cudaGetSymbolAddress((void**)&tmp,  g_tmp);
    cudaGetSymbolAddress((void**)&x1,   g_x1);
    cudaGetSymbolAddress((void**)&gate, g_gate);

    bf16 *xh,*xl,*qh,*ql,*kh,*kl,*vh,*vl,*ctxh,*ctxl,*x1h,*x1l,*ffh,*ffl;
    bf16 *wqh,*wql,*wkh,*wkl,*wvh,*wvl,*woh,*wol,*w1h,*w1l,*w2h,*w2l;
    cudaGetSymbolAddress((void**)&xh,  g_xh);   cudaGetSymbolAddress((void**)&xl,  g_xl);
    cudaGetSymbolAddress((void**)&qh,  g_qh);   cudaGetSymbolAddress((void**)&ql,  g_ql);
    cudaGetSymbolAddress((void**)&kh,  g_kh);   cudaGetSymbolAddress((void**)&kl,  g_kl);
    cudaGetSymbolAddress((void**)&vh,  g_vh);   cudaGetSymbolAddress((void**)&vl,  g_vl);
    cudaGetSymbolAddress((void**)&ctxh,g_ctxh); cudaGetSymbolAddress((void**)&ctxl,g_ctxl);
    cudaGetSymbolAddress((void**)&x1h, g_x1h);  cudaGetSymbolAddress((void**)&x1l, g_x1l);
    cudaGetSymbolAddress((void**)&ffh, g_ffh);  cudaGetSymbolAddress((void**)&ffl, g_ffl);
    cudaGetSymbolAddress((void**)&wqh, g_wqh);  cudaGetSymbolAddress((void**)&wql, g_wql);
    cudaGetSymbolAddress((void**)&wkh, g_wkh);  cudaGetSymbolAddress((void**)&wkl, g_wkl);
    cudaGetSymbolAddress((void**)&wvh, g_wvh);  cudaGetSymbolAddress((void**)&wvl, g_wvl);
    cudaGetSymbolAddress((void**)&woh, g_woh);  cudaGetSymbolAddress((void**)&wol, g_wol);
    cudaGetSymbolAddress((void**)&w1h, g_w1h);  cudaGetSymbolAddress((void**)&w1l, g_w1l);
    cudaGetSymbolAddress((void**)&w2h, g_w2h);  cudaGetSymbolAddress((void**)&w2l, g_w2l);

    cudaFuncSetAttribute(flash_tc_kernel,
                         cudaFuncAttributeMaxDynamicSharedMemorySize, FLASH_SMEM);
    cudaFuncSetAttribute(gemm_bf16x3_kernel,
                         cudaFuncAttributeMaxDynamicSharedMemorySize, GEMM_SMEM);
    cudaFuncSetAttribute(qkv_gemm_kernel,
                         cudaFuncAttributeMaxDynamicSharedMemorySize, GEMM_SMEM);

    // 0: fused split of x + all weights
    SplitArgs sa;
    sa.src[0] = x;   sa.hi[0] = xh;  sa.lo[0] = xl;
    sa.src[1] = w_q; sa.hi[1] = wqh; sa.lo[1] = wql;
    sa.src[2] = w_k; sa.hi[2] = wkh; sa.lo[2] = wkl;
    sa.src[3] = w_v; sa.hi[3] = wvh; sa.lo[3] = wvl;
    sa.src[4] = w_o; sa.hi[4] = woh; sa.lo[4] = wol;
    sa.src[5] = w1;  sa.hi[5] = w1h; sa.lo[5] = w1l;
    sa.src[6] = w2;  sa.hi[6] = w2h; sa.lo[6] = w2l;
    split_all_kernel<<<20480, 256>>>(sa);

    // 1: merged QKV GEMM
    QKVArgs qa;
    qa.Wh[0] = wqh; qa.Wl[0] = wql; qa.bias[0] = b_q; qa.Ch[0] = qh; qa.Cl[0] = ql;
    qa.Wh[1] = wkh; qa.Wl[1] = wkl; qa.bias[1] = b_k; qa.Ch[1] = kh; qa.Cl[1] = kl;
    qa.Wh[2] = wvh; qa.Wl[2] = wvl; qa.bias[2] = b_v; qa.Ch[2] = vh; qa.Cl[2] = vl;
    qkv_gemm_kernel<<<dim3(Dsz/64, Msz/128, 3), 128, GEMM_SMEM>>>(xh, xl, qa);

    // 2: gate
    gate_kernel<<<dim3(Msz/32, 2), 256>>>(x, w_g, b_g, gate);

    // 3: flash attention
    flash_tc_kernel<<<dim3(Ssz/64, Hsz, Bsz), 128, FLASH_SMEM>>>(
        qh, ql, kh, kl, vh, vl, gate, mask, ctxh, ctxl);

    dim3 gSq(Dsz/64, Msz/128);       // (16, 64)
    dim3 gF1(DFFsz/64, Msz/128);     // (64, 64)

    // 4-8: O-proj, LN1, FF1, FF2, LN2
    gemm_bf16x3_kernel<<<gSq, 128, GEMM_SMEM>>>(ctxh, ctxl, woh, wol, b_o, tmp, nullptr, nullptr, Dsz, Dsz, 2);
    add_ln_kernel<<<Msz, 256>>>(x, tmp, g1, beta1, x1, x1h, x1l);
    gemm_bf16x3_kernel<<<gF1, 128, GEMM_SMEM>>>(x1h, x1l, w1h, w1l, b1, nullptr, ffh, ffl, DFFsz, Dsz, 5);
    gemm_bf16x3_kernel<<<gSq, 128, GEMM_SMEM>>>(ffh, ffl, w2h, w2l, b2, tmp, nullptr, nullptr, Dsz, DFFsz, 2);
    add_ln_kernel<<<Msz, 256>>>(x1, tmp, g2, beta2, out, nullptr, nullptr);
}

// round 9
// speedup vs baseline: 1.0719x; 1.0719x over previous
#include <cuda_runtime.h>
#include <cuda_bf16.h>
#include <math.h>
#include <cstdint>

// Problem constants
#define Bsz   4
#define Ssz   2048
#define Dsz   1024
#define Hsz   16
#define DKsz  64
#define DFFsz 4096
#define Msz   (Bsz*Ssz)   // 8192 rows

typedef __nv_bfloat16 bf16;

// ---------------- scratch (static device globals; no allocation) ----------------
__device__ float g_tmp [(size_t)Msz*Dsz];
__device__ float g_x1  [(size_t)Msz*Dsz];
__device__ float g_gate[(size_t)Msz*Hsz];

__device__ bf16 g_xh [(size_t)Msz*Dsz],   g_xl [(size_t)Msz*Dsz];
__device__ bf16 g_qh [(size_t)Msz*Dsz],   g_ql [(size_t)Msz*Dsz];
__device__ bf16 g_kh [(size_t)Msz*Dsz],   g_kl [(size_t)Msz*Dsz];
__device__ bf16 g_vh [(size_t)Msz*Dsz],   g_vl [(size_t)Msz*Dsz];
__device__ bf16 g_ctxh[(size_t)Msz*Dsz],  g_ctxl[(size_t)Msz*Dsz];
__device__ bf16 g_x1h[(size_t)Msz*Dsz],   g_x1l[(size_t)Msz*Dsz];
__device__ bf16 g_ffh[(size_t)Msz*DFFsz], g_ffl[(size_t)Msz*DFFsz];
__device__ bf16 g_wqh[(size_t)Dsz*Dsz],   g_wql[(size_t)Dsz*Dsz];
__device__ bf16 g_wkh[(size_t)Dsz*Dsz],   g_wkl[(size_t)Dsz*Dsz];
__device__ bf16 g_wvh[(size_t)Dsz*Dsz],   g_wvl[(size_t)Dsz*Dsz];
__device__ bf16 g_woh[(size_t)Dsz*Dsz],   g_wol[(size_t)Dsz*Dsz];
__device__ bf16 g_w1h[(size_t)Dsz*DFFsz], g_w1l[(size_t)Dsz*DFFsz];
__device__ bf16 g_w2h[(size_t)DFFsz*Dsz], g_w2l[(size_t)DFFsz*Dsz];

// ---------------- small helpers ----------------
__device__ __forceinline__ void cp16(uint32_t dst, const void* src) {
    asm volatile("cp.async.ca.shared.global [%0], [%1], 16;\n" :: "r"(dst), "l"(src));
}
__device__ __forceinline__ void cp_commit() {
    asm volatile("cp.async.commit_group;\n");
}
__device__ __forceinline__ void cp_wait0() {
    asm volatile("cp.async.wait_group 0;\n");
}
__device__ __forceinline__ void cp_wait1() {
    asm volatile("cp.async.wait_group 1;\n");
}
__device__ __forceinline__ void cp_wait2() {
    asm volatile("cp.async.wait_group 2;\n");
}
__device__ __forceinline__ void ldsm4(uint32_t* r, uint32_t addr) {
    asm volatile("ldmatrix.sync.aligned.m8n8.x4.shared.b16 {%0,%1,%2,%3}, [%4];"
                 : "=r"(r[0]), "=r"(r[1]), "=r"(r[2]), "=r"(r[3]) : "r"(addr));
}
__device__ __forceinline__ void ldsm4t(uint32_t& r0, uint32_t& r1,
                                       uint32_t& r2, uint32_t& r3, uint32_t addr) {
    asm volatile("ldmatrix.sync.aligned.m8n8.x4.trans.shared.b16 {%0,%1,%2,%3}, [%4];"
                 : "=r"(r0), "=r"(r1), "=r"(r2), "=r"(r3) : "r"(addr));
}
__device__ __forceinline__ void mma16816(float* ac, const uint32_t* a,
                                         uint32_t b0, uint32_t b1) {
    asm volatile(
        "mma.sync.aligned.m16n8k16.row.col.f32.bf16.bf16.f32 "
        "{%0,%1,%2,%3},{%4,%5,%6,%7},{%8,%9},{%0,%1,%2,%3};"
        : "+f"(ac[0]), "+f"(ac[1]), "+f"(ac[2]), "+f"(ac[3])
        : "r"(a[0]), "r"(a[1]), "r"(a[2]), "r"(a[3]), "r"(b0), "r"(b1));
}
__device__ __forceinline__ void pack_pair(float a, float b, uint32_t& hi, uint32_t& lo) {
    bf16 ha = __float2bfloat16(a), hb = __float2bfloat16(b);
    bf16 la = __float2bfloat16(a - __bfloat162float(ha));
    bf16 lb = __float2bfloat16(b - __bfloat162float(hb));
    __nv_bfloat162 th = __halves2bfloat162(ha, hb);
    __nv_bfloat162 tl = __halves2bfloat162(la, lb);
    hi = *(uint32_t*)&th; lo = *(uint32_t*)&tl;
}

// ---------------- fused split of x + all 6 weights (one launch) ----------------
struct SplitArgs {
    const float* src[7];
    bf16* hi[7];
    bf16* lo[7];
};
__global__ __launch_bounds__(256)
void split_all_kernel(SplitArgs a)
{
    int bid = blockIdx.x;
    int seg, base;
    if      (bid < 8192)  { seg = 0; base = 0; }
    else if (bid < 9216)  { seg = 1; base = 8192; }
    else if (bid < 10240) { seg = 2; base = 9216; }
    else if (bid < 11264) { seg = 3; base = 10240; }
    else if (bid < 12288) { seg = 4; base = 11264; }
    else if (bid < 16384) { seg = 5; base = 12288; }
    else                  { seg = 6; base = 16384; }
    size_t i = (size_t)(bid - base) * 256 + threadIdx.x;
    float4 v = ((const float4*)a.src[seg])[i];
    uint32_t h0, l0, h1, l1;
    pack_pair(v.x, v.y, h0, l0);
    pack_pair(v.z, v.w, h1, l1);
    uint32_t* hp = (uint32_t*)a.hi[seg];
    uint32_t* lp = (uint32_t*)a.lo[seg];
    hp[2*i] = h0; hp[2*i+1] = h1;
    lp[2*i] = l0; lp[2*i+1] = l1;
}

// ---------------- bf16x3 tensor-core GEMM core (4-stage cp.async) ----------
// BM=BN=128, BK=16, 256 threads = 8 warps (2 M x 4 N), warp tile 64x32.
// acc = Ah*Wh + Al*Wh + Ah*Wl. mode bits: 1=GELU, 2=write fp32 C, 4=write bf16 Ch/Cl
#define APAD 24   // 16 + 8 bf16 pad
#define WPAD 136  // 128 + 8 pad
#define NSTG 4
#define SA_B (128*APAD*2)   // 6144 B per A stage buffer
#define SW_B (16*WPAD*2)    // 4352 B per W stage buffer
#define GEMM_SMEM (NSTG*(2*SA_B + 2*SW_B))   // 83968

__device__ __forceinline__
void gemm_core(const bf16* __restrict__ Ah, const bf16* __restrict__ Al,
               const bf16* __restrict__ Wh, const bf16* __restrict__ Wl,
               const float* __restrict__ bias, float* __restrict__ C,
               bf16* __restrict__ Ch, bf16* __restrict__ Cl,
               int N, int K, int mode, int row0, int col0)
{
    extern __shared__ __align__(16) char gdsm[];
    const uint32_t aAh = (uint32_t)__cvta_generic_to_shared(gdsm);
    const uint32_t aAl = aAh + NSTG*SA_B;
    const uint32_t aWh = aAl + NSTG*SA_B;
    const uint32_t aWl = aWh + NSTG*SW_B;

    const int tid = threadIdx.x;

    const char* pAh = (const char*)(Ah + (size_t)(row0 + (tid>>1)) * K + (tid&1)*8);
    const char* pAl = (const char*)(Al + (size_t)(row0 + (tid>>1)) * K + (tid&1)*8);
    const char* pWh = (const char*)(Wh + (size_t)(tid>>4) * N + col0 + (tid&15)*8);
    const char* pWl = (const char*)(Wl + (size_t)(tid>>4) * N + col0 + (tid&15)*8);

    const uint32_t dA = ((tid>>1)*APAD + (tid&1)*8) * 2;
    const uint32_t dW = ((tid>>4)*WPAD + (tid&15)*8) * 2;

    float acc[4][4][4];
    #pragma unroll
    for (int i = 0; i < 4; i++)
        #pragma unroll
        for (int j = 0; j < 4; j++)
            #pragma unroll
            for (int t = 0; t < 4; t++) acc[i][j][t] = 0.0f;

    const int wid = tid >> 5, lane = tid & 31;
    const int wm = wid & 1;       // M offset wm*64
    const int wn = wid >> 1;      // N offset wn*32
    const int lrow = lane & 15, lk = (lane >> 4) * 8;
    const uint32_t offA0 = (uint32_t)(((wm*64 + lrow) * APAD + lk) * 2);
    const uint32_t offB0 = (uint32_t)(((lane & 15) * WPAD + wn*32 + (lane>>4)*8) * 2);

    const int nit = K / 16;

    auto load_stage = [&](int st, int it2) {
        size_t ka = (size_t)it2 * 16 * 2;
        size_t kw = (size_t)it2 * 16 * (size_t)N * 2;
        cp16(aAh + (uint32_t)st*SA_B + dA, pAh + ka);
        cp16(aAl + (uint32_t)st*SA_B + dA, pAl + ka);
        cp16(aWh + (uint32_t)st*SW_B + dW, pWh + kw);
        cp16(aWl + (uint32_t)st*SW_B + dW, pWl + kw);
        cp_commit();
    };

    // prologue: stages 0, 1, 2
    load_stage(0, 0);
    load_stage(1, 1);
    load_stage(2, 2);

    for (int it = 0; it < nit; ++it) {
        int rem = nit - 1 - it;
        if (rem >= 2) cp_wait2();
        else if (rem == 1) cp_wait1();
        else cp_wait0();
        __syncthreads();
        if (it + 3 < nit)
            load_stage((it + 3) & 3, it + 3);
        const uint32_t s = (uint32_t)(it & 3);

        uint32_t afh[4][4], afl[4][4];
        #pragma unroll
        for (int mi = 0; mi < 4; mi++)
            ldsm4(afh[mi], aAh + s*SA_B + offA0 + mi*16*APAD*2);
        #pragma unroll
        for (int mi = 0; mi < 4; mi++)
            ldsm4(afl[mi], aAl + s*SA_B + offA0 + mi*16*APAD*2);

        uint32_t bfr[4][2];
        #pragma unroll
        for (int ng = 0; ng < 2; ng++)
            ldsm4t(bfr[2*ng][0], bfr[2*ng][1], bfr[2*ng+1][0], bfr[2*ng+1][1],
                   aWh + s*SW_B + offB0 + (uint32_t)(ng*16*2));
        #pragma unroll
        for (int mi = 0; mi < 4; mi++)
            #pragma unroll
            for (int ni = 0; ni < 4; ni++) {
                mma16816(acc[mi][ni], afh[mi], bfr[ni][0], bfr[ni][1]);
                mma16816(acc[mi][ni], afl[mi], bfr[ni][0], bfr[ni][1]);
            }
        #pragma unroll
        for (int ng = 0; ng < 2; ng++)
            ldsm4t(bfr[2*ng][0], bfr[2*ng][1], bfr[2*ng+1][0], bfr[2*ng+1][1],
                   aWl + s*SW_B + offB0 + (uint32_t)(ng*16*2));
        #pragma unroll
        for (int mi = 0; mi < 4; mi++)
            #pragma unroll
            for (int ni = 0; ni < 4; ni++)
                mma16816(acc[mi][ni], afh[mi], bfr[ni][0], bfr[ni][1]);
    }

    #pragma unroll
    for (int mi = 0; mi < 4; mi++) {
        #pragma unroll
        for (int ni = 0; ni < 4; ni++) {
            int c = col0 + wn*32 + ni*8 + (lane & 3)*2;
            float bx = bias[c], by = bias[c + 1];
            #pragma unroll
            for (int rh = 0; rh < 2; rh++) {
                size_t r = (size_t)(row0 + wm*64 + mi*16 + (lane >> 2) + rh*8);
                float v0 = acc[mi][ni][2*rh]     + bx;
                float v1 = acc[mi][ni][2*rh + 1] + by;
                if (mode & 1) {
                    v0 = 0.5f * v0 * (1.0f + erff(v0 * 0.70710678118654752f));
                    v1 = 0.5f * v1 * (1.0f + erff(v1 * 0.70710678118654752f));
                }
                if (mode & 2) {
                    float2 o; o.x = v0; o.y = v1;
                    *(float2*)&C[r * N + c] = o;
                }
                if (mode & 4) {
                    uint32_t hp, lp;
                    pack_pair(v0, v1, hp, lp);
                    *(uint32_t*)&Ch[r * N + c] = hp;
                    *(uint32_t*)&Cl[r * N + c] = lp;
                }
            }
        }
    }
}

__global__ __launch_bounds__(256)
void gemm_bf16x3_kernel(const bf16* __restrict__ Ah, const bf16* __restrict__ Al,
                        const bf16* __restrict__ Wh, const bf16* __restrict__ Wl,
                        const float* __restrict__ bias, float* __restrict__ C,
                        bf16* __restrict__ Ch, bf16* __restrict__ Cl,
                        int N, int K, int mode)
{
    gemm_core(Ah, Al, Wh, Wl, bias, C, Ch, Cl, N, K, mode,
              blockIdx.y * 128, blockIdx.x * 128);
}

// merged Q/K/V projection: blockIdx.z selects weight/output set
struct QKVArgs {
    const bf16* Wh[3];
    const bf16* Wl[3];
    const float* bias[3];
    bf16* Ch[3];
    bf16* Cl[3];
};
__global__ __launch_bounds__(256)
void qkv_gemm_kernel(const bf16* __restrict__ Ah, const bf16* __restrict__ Al,
                     QKVArgs a)
{
    int z = blockIdx.z;
    gemm_core(Ah, Al, a.Wh[z], a.Wl[z], a.bias[z], nullptr, a.Ch[z], a.Cl[z],
              Dsz, Dsz, 4, blockIdx.y * 128, blockIdx.x * 128);
}

// ---------------- sigmoid gate ----------------------
__global__ __launch_bounds__(256)
void gate_kernel(const float* __restrict__ x, const float* __restrict__ wg,
                 const float* __restrict__ bg, float* __restrict__ gate)
{
    __shared__ float wgs[Dsz][8];
    int hg = blockIdx.y;
    int tid = threadIdx.x;
    for (int idx = tid; idx < Dsz*8; idx += 256)
        wgs[idx >> 3][idx & 7] = wg[(idx >> 3) * Hsz + hg*8 + (idx & 7)];
    __syncthreads();

    int h = tid & 7, r = tid >> 3;
    int m = blockIdx.x * 32 + r;
    const float4* xr = (const float4*)(x + (size_t)m * Dsz);
    float s = 0.0f;
    #pragma unroll 4
    for (int d4 = 0; d4 < Dsz/4; d4++) {
        float4 xv = xr[d4];
        s = fmaf(xv.x, wgs[d4*4 + 0][h], s);
        s = fmaf(xv.y, wgs[d4*4 + 1][h], s);
        s = fmaf(xv.z, wgs[d4*4 + 2][h], s);
        s = fmaf(xv.w, wgs[d4*4 + 3][h], s);
    }
    s += bg[hg*8 + h];
    gate[(size_t)m * Hsz + hg*8 + h] = 1.0f / (1.0f + __expf(-s));
}

// ---------------- tensor-core flash attention ----------------
#define FPAD 72
#define KV_STRIDE (64*FPAD)
#define STAGE_ELEMS (4*KV_STRIDE)
#define FLASH_SMEM (2*STAGE_ELEMS*2 + 2*64*4)

__global__ __launch_bounds__(128, 3)
void flash_tc_kernel(const bf16* __restrict__ Qh, const bf16* __restrict__ Ql,
                     const bf16* __restrict__ Kh, const bf16* __restrict__ Kl,
                     const bf16* __restrict__ Vh, const bf16* __restrict__ Vl,
                     const float* __restrict__ gate, const int* __restrict__ mask,
                     bf16* __restrict__ Ch, bf16* __restrict__ Cl)
{
    extern __shared__ __align__(16) char dynsmem[];
    int* smsk = (int*)(dynsmem + (size_t)2*STAGE_ELEMS*2);

    const int tid = threadIdx.x, lane = tid & 31, warp = tid >> 5;
    const int qt = blockIdx.x, h = blockIdx.y, b = blockIdx.z;
    const size_t rowbase = (size_t)b * Ssz;
    const size_t hoff = (size_t)h * DKsz;

    const uint32_t sbase = (uint32_t)__cvta_generic_to_shared(dynsmem);
    const uint32_t mbase = (uint32_t)__cvta_generic_to_shared(smsk);

    {
        int r = tid >> 1;
        size_t gq = (rowbase + qt*64 + r) * Dsz + hoff;
        #pragma unroll
        for (int j = 0; j < 4; j++) {
            int c8 = (tid & 1)*4 + j;
            uint32_t dof = (uint32_t)((r*FPAD + c8*8)*2);
            cp16(sbase + 0*KV_STRIDE*2 + dof, Qh + gq + c8*8);
            cp16(sbase + 1*KV_STRIDE*2 + dof, Ql + gq + c8*8);
        }
        cp_commit(); cp_wait0();
    }
    __syncthreads();

    uint32_t qfh[4][4], qfl[4][4];
    {
        uint32_t arow = (uint32_t)((warp*16 + (lane&15))*FPAD*2);
        #pragma unroll
        for (int ks = 0; ks < 4; ks++) {
            uint32_t acol = (uint32_t)((16*ks + (lane>>4)*8)*2);
            ldsm4(qfh[ks], sbase + 0*KV_STRIDE*2 + arow + acol);
            ldsm4(qfl[ks], sbase + 1*KV_STRIDE*2 + arow + acol);
        }
    }
    __syncthreads();

    float oacc[8][4];
    #pragma unroll
    for (int i = 0; i < 8; i++)
        #pragma unroll
        for (int j = 0; j < 4; j++) oacc[i][j] = 0.0f;
    float m0 = -1e30f, m1 = -1e30f, l0 = 0.0f, l1 = 0.0f;

    const int r_ld = tid >> 1;
    const int cbase = (tid & 1)*4;

    {
        size_t g = (rowbase + r_ld) * Dsz + hoff;
        #pragma unroll
        for (int j = 0; j < 4; j++) {
            int c8 = cbase + j;
            uint32_t dof = (uint32_t)((r_ld*FPAD + c8*8)*2);
            cp16(sbase + 0*KV_STRIDE*2 + dof, Kh + g + c8*8);
            cp16(sbase + 1*KV_STRIDE*2 + dof, Kl + g + c8*8);
            cp16(sbase + 2*KV_STRIDE*2 + dof, Vh + g + c8*8);
            cp16(sbase + 3*KV_STRIDE*2 + dof, Vl + g + c8*8);
        }
        if (tid < 16) cp16(mbase + tid*16, mask + rowbase + tid*4);
        cp_commit();
    }

    const int col0 = 2*(lane & 3);

    for (int kt = 0; kt < Ssz/64; kt++) {
        cp_wait0();
        __syncthreads();
        if (kt + 1 < Ssz/64) {
            int st = (kt + 1) & 1;
            size_t g = (rowbase + (kt+1)*64 + r_ld) * Dsz + hoff;
            uint32_t sb = sbase + (uint32_t)(st*STAGE_ELEMS*2);
            #pragma unroll
            for (int j = 0; j < 4; j++) {
                int c8 = cbase + j;
                uint32_t dof = (uint32_t)((r_ld*FPAD + c8*8)*2);
                cp16(sb + 0*KV_STRIDE*2 + dof, Kh + g + c8*8);
                cp16(sb + 1*KV_STRIDE*2 + dof, Kl + g + c8*8);
                cp16(sb + 2*KV_STRIDE*2 + dof, Vh + g + c8*8);
                cp16(sb + 3*KV_STRIDE*2 + dof, Vl + g + c8*8);
            }
            if (tid < 16) cp16(mbase + st*256 + tid*16, mask + rowbase + (kt+1)*64 + tid*4);
            cp_commit();
        }
        const int st = kt & 1;
        const uint32_t kb = sbase + (uint32_t)(st*STAGE_ELEMS*2);

        float sc[8][4];
        #pragma unroll
        for (int i = 0; i < 8; i++)
            #pragma unroll
            for (int j = 0; j < 4; j++) sc[i][j] = 0.0f;

        const uint32_t brow = (uint32_t)(((lane&7) + ((lane>>1)&8)) * FPAD * 2);
        const uint32_t bcol = (uint32_t)((lane & 8) * 2);
        #pragma unroll
        for (int ng = 0; ng < 4; ng++) {
            #pragma unroll
            for (int ks = 0; ks < 4; ks++) {
                uint32_t ba = kb + brow + (uint32_t)(16*ng*FPAD*2) + bcol + (uint32_t)(16*ks*2);
                uint32_t bh4[4], bl4[4];
                ldsm4(bh4, ba);
                ldsm4(bl4, ba + KV_STRIDE*2);
                mma16816(sc[2*ng],   qfh[ks], bh4[0], bh4[1]);
                mma16816(sc[2*ng+1], qfh[ks], bh4[2], bh4[3]);
                mma16816(sc[2*ng],   qfl[ks], bh4[0], bh4[1]);
                mma16816(sc[2*ng+1], qfl[ks], bh4[2], bh4[3]);
                mma16816(sc[2*ng],   qfh[ks], bl4[0], bl4[1]);
                mma16816(sc[2*ng+1], qfh[ks], bl4[2], bl4[3]);
            }
        }

        const int* mk = smsk + st*64;
        float mx0 = -1e30f, mx1 = -1e30f;
        #pragma unroll
        for (int ni = 0; ni < 8; ni++) {
            int c = 8*ni + col0;
            bool z0 = (mk[c] == 0), z1 = (mk[c+1] == 0);
            sc[ni][0] = z0 ? -1e9f : sc[ni][0]*0.125f;
            sc[ni][1] = z1 ? -1e9f : sc[ni][1]*0.125f;
            sc[ni][2] = z0 ? -1e9f : sc[ni][2]*0.125f;
            sc[ni][3] = z1 ? -1e9f : sc[ni][3]*0.125f;
            mx0 = fmaxf(mx0, fmaxf(sc[ni][0], sc[ni][1]));
            mx1 = fmaxf(mx1, fmaxf(sc[ni][2], sc[ni][3]));
        }
        mx0 = fmaxf(mx0, __shfl_xor_sync(0xffffffffu, mx0, 1));
        mx0 = fmaxf(mx0, __shfl_xor_sync(0xffffffffu, mx0, 2));
        mx1 = fmaxf(mx1, __shfl_xor_sync(0xffffffffu, mx1, 1));
        mx1 = fmaxf(mx1, __shfl_xor_sync(0xffffffffu, mx1, 2));
        float mn0 = fmaxf(m0, mx0), mn1 = fmaxf(m1, mx1);
        float al0 = __expf(m0 - mn0), al1 = __expf(m1 - mn1);
        float rs0 = 0.0f, rs1 = 0.0f;
        #pragma unroll
        for (int ni = 0; ni < 8; ni++) {
            sc[ni][0] = __expf(sc[ni][0] - mn0);
            sc[ni][1] = __expf(sc[ni][1] - mn0);
            sc[ni][2] = __expf(sc[ni][2] - mn1);
            sc[ni][3] = __expf(sc[ni][3] - mn1);
            rs0 += sc[ni][0] + sc[ni][1];
            rs1 += sc[ni][2] + sc[ni][3];
        }
        rs0 += __shfl_xor_sync(0xffffffffu, rs0, 1);
        rs0 += __shfl_xor_sync(0xffffffffu, rs0, 2);
        rs1 += __shfl_xor_sync(0xffffffffu, rs1, 1);
        rs1 += __shfl_xor_sync(0xffffffffu, rs1, 2);
        l0 = l0*al0 + rs0; l1 = l1*al1 + rs1;
        m0 = mn0; m1 = mn1;
        #pragma unroll
        for (int ni = 0; ni < 8; ni++) {
            oacc[ni][0] *= al0; oacc[ni][1] *= al0;
            oacc[ni][2] *= al1; oacc[ni][3] *= al1;
        }

        const uint32_t vrow0 = (uint32_t)((lane&15)*FPAD*2);
        const uint32_t vcol0 = (uint32_t)(((lane>>4)*8)*2);
        #pragma unroll
        for (int ki = 0; ki < 4; ki++) {
            uint32_t ph[4], pl[4];
            pack_pair(sc[2*ki][0],   sc[2*ki][1],   ph[0], pl[0]);
            pack_pair(sc[2*ki][2],   sc[2*ki][3],   ph[1], pl[1]);
            pack_pair(sc[2*ki+1][0], sc[2*ki+1][1], ph[2], pl[2]);
            pack_pair(sc[2*ki+1][2], sc[2*ki+1][3], ph[3], pl[3]);
            uint32_t va0 = kb + 2*KV_STRIDE*2 + vrow0 + (uint32_t)(16*ki*FPAD*2) + vcol0;
            #pragma unroll
            for (int ngd = 0; ngd < 4; ngd++) {
                uint32_t vh4[4], vl4[4];
                ldsm4t(vh4[0], vh4[1], vh4[2], vh4[3], va0 + (uint32_t)(16*ngd*2));
                ldsm4t(vl4[0], vl4[1], vl4[2], vl4[3], va0 + KV_STRIDE*2 + (uint32_t)(16*ngd*2));
                mma16816(oacc[2*ngd],   ph, vh4[0], vh4[1]);
                mma16816(oacc[2*ngd+1], ph, vh4[2], vh4[3]);
                mma16816(oacc[2*ngd],   ph, vl4[0], vl4[1]);
                mma16816(oacc[2*ngd+1], ph, vl4[2], vl4[3]);
                mma16816(oacc[2*ngd],   pl, vh4[0], vh4[1]);
                mma16816(oacc[2*ngd+1], pl, vh4[2], vh4[3]);
            }
        }
    }

    int q0 = qt*64 + warp*16 + (lane >> 2);
    float f0 = gate[(rowbase + q0)*Hsz + h] / l0;
    float f1 = gate[(rowbase + q0 + 8)*Hsz + h] / l1;
    #pragma unroll
    for (int ni = 0; ni < 8; ni++) {
        size_t o0 = (rowbase + q0) * Dsz + hoff + 8*ni + col0;
        size_t o1 = o0 + (size_t)8 * Dsz;
        uint32_t hp, lp;
        pack_pair(oacc[ni][0]*f0, oacc[ni][1]*f0, hp, lp);
        *(uint32_t*)&Ch[o0] = hp;
        *(uint32_t*)&Cl[o0] = lp;
        pack_pair(oacc[ni][2]*f1, oacc[ni][3]*f1, hp, lp);
        *(uint32_t*)&Ch[o1] = hp;
        *(uint32_t*)&Cl[o1] = lp;
    }
}

// ---------------- fused residual add + LayerNorm (+ optional bf16 split out) ----
__global__ __launch_bounds__(256)
void add_ln_kernel(const float* __restrict__ a, const float* __restrict__ bsrc,
                   const float* __restrict__ g, const float* __restrict__ beta,
                   float* __restrict__ out, bf16* __restrict__ oh, bf16* __restrict__ ol)
{
    int row = blockIdx.x;
    int tid = threadIdx.x;
    __shared__ float buf[Dsz];
    __shared__ float rsum[8], rsq[8];

    size_t base = (size_t)row * Dsz;
    float ls = 0.0f, lq = 0.0f;
    for (int d = tid; d < Dsz; d += 256) {
        float v = a[base + d] + bsrc[base + d];
        buf[d] = v;
        ls += v; lq += v * v;
    }
    int warp = tid >> 5, lane = tid & 31;
    for (int off = 16; off; off >>= 1) {
        ls += __shfl_xor_sync(0xffffffffu, ls, off);
        lq += __shfl_xor_sync(0xffffffffu, lq, off);
    }
    if (lane == 0) { rsum[warp] = ls; rsq[warp] = lq; }
    __syncthreads();
    float ts = 0.0f, tq = 0.0f;
    #pragma unroll
    for (int w = 0; w < 8; w++) { ts += rsum[w]; tq += rsq[w]; }
    float mean = ts * (1.0f / Dsz);
    float var  = tq * (1.0f / Dsz) - mean * mean;
    float rstd = rsqrtf(var + 1e-5f);
    for (int d = tid; d < Dsz; d += 256) {
        float v = (buf[d] - mean) * rstd * g[d] + beta[d];
        out[base + d] = v;
        if (oh) {
            bf16 hv = __float2bfloat16(v);
            oh[base + d] = hv;
            ol[base + d] = __float2bfloat16(v - __bfloat162float(hv));
        }
    }
}

// ---------------- launch ----------------
extern "C" void kernel_launch(void* const* d_in, const int* in_sizes, int n_in,
                              void* d_out, int out_size)
{
    const float* x     = (const float*)d_in[0];
    const float* w_q   = (const float*)d_in[1];
    const float* b_q   = (const float*)d_in[2];
    const float* w_k   = (const float*)d_in[3];
    const float* b_k   = (const float*)d_in[4];
    const float* w_v   = (const float*)d_in[5];
    const float* b_v   = (const float*)d_in[6];
    const float* w_o   = (const float*)d_in[7];
    const float* b_o   = (const float*)d_in[8];
    const float* w_g   = (const float*)d_in[9];
    const float* b_g   = (const float*)d_in[10];
    const float* w1    = (const float*)d_in[11];
    const float* b1    = (const float*)d_in[12];
    const float* w2    = (const float*)d_in[13];
    const float* b2    = (const float*)d_in[14];
    const float* g1    = (const float*)d_in[15];
    const float* beta1 = (const float*)d_in[16];
    const float* g2    = (const float*)d_in[17];
    const float* beta2 = (const float*)d_in[18];
    const int*   mask  = (const int*)  d_in[19];
    float* out = (float*)d_out;

    float *tmp, *x1, *gate;
    cudaGetSymbolAddress((void**)&tmp,  g_tmp);
    cudaGetSymbolAddress((void**)&x1,   g_x1);
    cudaGetSymbolAddress((void**)&gate, g_gate);

    bf16 *xh,*xl,*qh,*ql,*kh,*kl,*vh,*vl,*ctxh,*ctxl,*x1h,*x1l,*ffh,*ffl;
    bf16 *wqh,*wql,*wkh,*wkl,*wvh,*wvl,*woh,*wol,*w1h,*w1l,*w2h,*w2l;
    cudaGetSymbolAddress((void**)&xh,  g_xh);   cudaGetSymbolAddress((void**)&xl,  g_xl);
    cudaGetSymbolAddress((void**)&qh,  g_qh);   cudaGetSymbolAddress((void**)&ql,  g_ql);
    cudaGetSymbolAddress((void**)&kh,  g_kh);   cudaGetSymbolAddress((void**)&kl,  g_kl);
    cudaGetSymbolAddress((void**)&vh,  g_vh);   cudaGetSymbolAddress((void**)&vl,  g_vl);
    cudaGetSymbolAddress((void**)&ctxh,g_ctxh); cudaGetSymbolAddress((void**)&ctxl,g_ctxl);
    cudaGetSymbolAddress((void**)&x1h, g_x1h);  cudaGetSymbolAddress((void**)&x1l, g_x1l);
    cudaGetSymbolAddress((void**)&ffh, g_ffh);  cudaGetSymbolAddress((void**)&ffl, g_ffl);
    cudaGetSymbolAddress((void**)&wqh, g_wqh);  cudaGetSymbolAddress((void**)&wql, g_wql);
    cudaGetSymbolAddress((void**)&wkh, g_wkh);  cudaGetSymbolAddress((void**)&wkl, g_wkl);
    cudaGetSymbolAddress((void**)&wvh, g_wvh);  cudaGetSymbolAddress((void**)&wvl, g_wvl);
    cudaGetSymbolAddress((void**)&woh, g_woh);  cudaGetSymbolAddress((void**)&wol, g_wol);
    cudaGetSymbolAddress((void**)&w1h, g_w1h);  cudaGetSymbolAddress((void**)&w1l, g_w1l);
    cudaGetSymbolAddress((void**)&w2h, g_w2h);  cudaGetSymbolAddress((void**)&w2l, g_w2l);

    cudaFuncSetAttribute(flash_tc_kernel,
                         cudaFuncAttributeMaxDynamicSharedMemorySize, FLASH_SMEM);
    cudaFuncSetAttribute(gemm_bf16x3_kernel,
                         cudaFuncAttributeMaxDynamicSharedMemorySize, GEMM_SMEM);
    cudaFuncSetAttribute(qkv_gemm_kernel,
                         cudaFuncAttributeMaxDynamicSharedMemorySize, GEMM_SMEM);

    // 0: fused split of x + all weights
    SplitArgs sa;
    sa.src[0] = x;   sa.hi[0] = xh;  sa.lo[0] = xl;
    sa.src[1] = w_q; sa.hi[1] = wqh; sa.lo[1] = wql;
    sa.src[2] = w_k; sa.hi[2] = wkh; sa.lo[2] = wkl;
    sa.src[3] = w_v; sa.hi[3] = wvh; sa.lo[3] = wvl;
    sa.src[4] = w_o; sa.hi[4] = woh; sa.lo[4] = wol;
    sa.src[5] = w1;  sa.hi[5] = w1h; sa.lo[5] = w1l;
    sa.src[6] = w2;  sa.hi[6] = w2h; sa.lo[6] = w2l;
    split_all_kernel<<<20480, 256>>>(sa);

    // 1: merged QKV GEMM
    QKVArgs qa;
    qa.Wh[0] = wqh; qa.Wl[0] = wql; qa.bias[0] = b_q; qa.Ch[0] = qh; qa.Cl[0] = ql;
    qa.Wh[1] = wkh; qa.Wl[1] = wkl; qa.bias[1] = b_k; qa.Ch[1] = kh; qa.Cl[1] = kl;
    qa.Wh[2] = wvh; qa.Wl[2] = wvl; qa.bias[2] = b_v; qa.Ch[2] = vh; qa.Cl[2] = vl;
    qkv_gemm_kernel<<<dim3(Dsz/128, Msz/128, 3), 256, GEMM_SMEM>>>(xh, xl, qa);

    // 2: gate
    gate_kernel<<<dim3(Msz/32, 2), 256>>>(x, w_g, b_g, gate);

    // 3: flash attention
    flash_tc_kernel<<<dim3(Ssz/64, Hsz, Bsz), 128, FLASH_SMEM>>>(
        qh, ql, kh, kl, vh, vl, gate, mask, ctxh, ctxl);

    dim3 gSq(Dsz/128, Msz/128);      // (8, 64)
    dim3 gF1(DFFsz/128, Msz/128);    // (32, 64)

    // 4-8: O-proj, LN1, FF1, FF2, LN2
    gemm_bf16x3_kernel<<<gSq, 256, GEMM_SMEM>>>(ctxh, ctxl, woh, wol, b_o, tmp, nullptr, nullptr, Dsz, Dsz, 2);
    add_ln_kernel<<<Msz, 256>>>(x, tmp, g1, beta1, x1, x1h, x1l);
    gemm_bf16x3_kernel<<<gF1, 256, GEMM_SMEM>>>(x1h, x1l, w1h, w1l, b1, nullptr, ffh, ffl, DFFsz, Dsz, 5);
    gemm_bf16x3_kernel<<<gSq, 256, GEMM_SMEM>>>(ffh, ffl, w2h, w2l, b2, tmp, nullptr, nullptr, Dsz, DFFsz, 2);
    add_ln_kernel<<<Msz, 256>>>(x1, tmp, g2, beta2, out, nullptr, nullptr);
}

// round 10
// speedup vs baseline: 1.2966x; 1.2096x over previous
#include <cuda_runtime.h>
#include <cuda_bf16.h>
#include <math.h>
#include <cstdint>

// Problem constants
#define Bsz   4
#define Ssz   2048
#define Dsz   1024
#define Hsz   16
#define DKsz  64
#define DFFsz 4096
#define Msz   (Bsz*Ssz)   // 8192 rows

typedef __nv_bfloat16 bf16;

// ---------------- scratch (static device globals; no allocation) ----------------
__device__ float g_tmp [(size_t)Msz*Dsz];
__device__ float g_x1  [(size_t)Msz*Dsz];
__device__ float g_gate[(size_t)Msz*Hsz];

__device__ bf16 g_xh [(size_t)Msz*Dsz],   g_xl [(size_t)Msz*Dsz];
__device__ bf16 g_qh [(size_t)Msz*Dsz];
__device__ bf16 g_kh [(size_t)Msz*Dsz];
__device__ bf16 g_vh [(size_t)Msz*Dsz];
__device__ bf16 g_ctxh[(size_t)Msz*Dsz],  g_ctxl[(size_t)Msz*Dsz];
__device__ bf16 g_x1h[(size_t)Msz*Dsz],   g_x1l[(size_t)Msz*Dsz];
__device__ bf16 g_ffh[(size_t)Msz*DFFsz], g_ffl[(size_t)Msz*DFFsz];
__device__ bf16 g_wqh[(size_t)Dsz*Dsz],   g_wql[(size_t)Dsz*Dsz];
__device__ bf16 g_wkh[(size_t)Dsz*Dsz],   g_wkl[(size_t)Dsz*Dsz];
__device__ bf16 g_wvh[(size_t)Dsz*Dsz],   g_wvl[(size_t)Dsz*Dsz];
__device__ bf16 g_woh[(size_t)Dsz*Dsz],   g_wol[(size_t)Dsz*Dsz];
__device__ bf16 g_w1h[(size_t)Dsz*DFFsz], g_w1l[(size_t)Dsz*DFFsz];
__device__ bf16 g_w2h[(size_t)DFFsz*Dsz], g_w2l[(size_t)DFFsz*Dsz];

// ---------------- small helpers ----------------
__device__ __forceinline__ void cp16(uint32_t dst, const void* src) {
    asm volatile("cp.async.ca.shared.global [%0], [%1], 16;\n" :: "r"(dst), "l"(src));
}
__device__ __forceinline__ void cp_commit() {
    asm volatile("cp.async.commit_group;\n");
}
__device__ __forceinline__ void cp_wait0() {
    asm volatile("cp.async.wait_group 0;\n");
}
__device__ __forceinline__ void cp_wait1() {
    asm volatile("cp.async.wait_group 1;\n");
}
__device__ __forceinline__ void cp_wait2() {
    asm volatile("cp.async.wait_group 2;\n");
}
__device__ __forceinline__ void ldsm4(uint32_t* r, uint32_t addr) {
    asm volatile("ldmatrix.sync.aligned.m8n8.x4.shared.b16 {%0,%1,%2,%3}, [%4];"
                 : "=r"(r[0]), "=r"(r[1]), "=r"(r[2]), "=r"(r[3]) : "r"(addr));
}
__device__ __forceinline__ void ldsm4t(uint32_t& r0, uint32_t& r1,
                                       uint32_t& r2, uint32_t& r3, uint32_t addr) {
    asm volatile("ldmatrix.sync.aligned.m8n8.x4.trans.shared.b16 {%0,%1,%2,%3}, [%4];"
                 : "=r"(r0), "=r"(r1), "=r"(r2), "=r"(r3) : "r"(addr));
}
__device__ __forceinline__ void mma16816(float* ac, const uint32_t* a,
                                         uint32_t b0, uint32_t b1) {
    asm volatile(
        "mma.sync.aligned.m16n8k16.row.col.f32.bf16.bf16.f32 "
        "{%0,%1,%2,%3},{%4,%5,%6,%7},{%8,%9},{%0,%1,%2,%3};"
        : "+f"(ac[0]), "+f"(ac[1]), "+f"(ac[2]), "+f"(ac[3])
        : "r"(a[0]), "r"(a[1]), "r"(a[2]), "r"(a[3]), "r"(b0), "r"(b1));
}
__device__ __forceinline__ void pack_pair(float a, float b, uint32_t& hi, uint32_t& lo) {
    bf16 ha = __float2bfloat16(a), hb = __float2bfloat16(b);
    bf16 la = __float2bfloat16(a - __bfloat162float(ha));
    bf16 lb = __float2bfloat16(b - __bfloat162float(hb));
    __nv_bfloat162 th = __halves2bfloat162(ha, hb);
    __nv_bfloat162 tl = __halves2bfloat162(la, lb);
    hi = *(uint32_t*)&th; lo = *(uint32_t*)&tl;
}
__device__ __forceinline__ uint32_t pack_hi(float a, float b) {
    __nv_bfloat162 th = __halves2bfloat162(__float2bfloat16(a), __float2bfloat16(b));
    return *(uint32_t*)&th;
}

// ---------------- fused split of x + all 6 weights (one launch) ----------------
struct SplitArgs {
    const float* src[7];
    bf16* hi[7];
    bf16* lo[7];
};
__global__ __launch_bounds__(256)
void split_all_kernel(SplitArgs a)
{
    int bid = blockIdx.x;
    int seg, base;
    if      (bid < 8192)  { seg = 0; base = 0; }
    else if (bid < 9216)  { seg = 1; base = 8192; }
    else if (bid < 10240) { seg = 2; base = 9216; }
    else if (bid < 11264) { seg = 3; base = 10240; }
    else if (bid < 12288) { seg = 4; base = 11264; }
    else if (bid < 16384) { seg = 5; base = 12288; }
    else                  { seg = 6; base = 16384; }
    size_t i = (size_t)(bid - base) * 256 + threadIdx.x;
    float4 v = ((const float4*)a.src[seg])[i];
    uint32_t h0, l0, h1, l1;
    pack_pair(v.x, v.y, h0, l0);
    pack_pair(v.z, v.w, h1, l1);
    uint32_t* hp = (uint32_t*)a.hi[seg];
    uint32_t* lp = (uint32_t*)a.lo[seg];
    hp[2*i] = h0; hp[2*i+1] = h1;
    lp[2*i] = l0; lp[2*i+1] = l1;
}

// ---------------- bf16x3 tensor-core GEMM core (4-stage cp.async) ----------
// BM=BN=128, BK=16, 256 threads = 8 warps (2 M x 4 N), warp tile 64x32.
// acc = Ah*Wh + Al*Wh + Ah*Wl.
// mode bits: 1=GELU, 2=write fp32 C, 4=write bf16 Ch/Cl, 8=write bf16 Ch only
#define APAD 24   // 16 + 8 bf16 pad
#define WPAD 136  // 128 + 8 pad
#define NSTG 4
#define SA_B (128*APAD*2)   // 6144 B per A stage buffer
#define SW_B (16*WPAD*2)    // 4352 B per W stage buffer
#define GEMM_SMEM (NSTG*(2*SA_B + 2*SW_B))   // 83968

__device__ __forceinline__
void gemm_core(const bf16* __restrict__ Ah, const bf16* __restrict__ Al,
               const bf16* __restrict__ Wh, const bf16* __restrict__ Wl,
               const float* __restrict__ bias, float* __restrict__ C,
               bf16* __restrict__ Ch, bf16* __restrict__ Cl,
               int N, int K, int mode, int row0, int col0)
{
    extern __shared__ __align__(16) char gdsm[];
    const uint32_t aAh = (uint32_t)__cvta_generic_to_shared(gdsm);
    const uint32_t aAl = aAh + NSTG*SA_B;
    const uint32_t aWh = aAl + NSTG*SA_B;
    const uint32_t aWl = aWh + NSTG*SW_B;

    const int tid = threadIdx.x;

    const char* pAh = (const char*)(Ah + (size_t)(row0 + (tid>>1)) * K + (tid&1)*8);
    const char* pAl = (const char*)(Al + (size_t)(row0 + (tid>>1)) * K + (tid&1)*8);
    const char* pWh = (const char*)(Wh + (size_t)(tid>>4) * N + col0 + (tid&15)*8);
    const char* pWl = (const char*)(Wl + (size_t)(tid>>4) * N + col0 + (tid&15)*8);

    const uint32_t dA = ((tid>>1)*APAD + (tid&1)*8) * 2;
    const uint32_t dW = ((tid>>4)*WPAD + (tid&15)*8) * 2;

    float acc[4][4][4];
    #pragma unroll
    for (int i = 0; i < 4; i++)
        #pragma unroll
        for (int j = 0; j < 4; j++)
            #pragma unroll
            for (int t = 0; t < 4; t++) acc[i][j][t] = 0.0f;

    const int wid = tid >> 5, lane = tid & 31;
    const int wm = wid & 1;       // M offset wm*64
    const int wn = wid >> 1;      // N offset wn*32
    const int lrow = lane & 15, lk = (lane >> 4) * 8;
    const uint32_t offA0 = (uint32_t)(((wm*64 + lrow) * APAD + lk) * 2);
    const uint32_t offB0 = (uint32_t)(((lane & 15) * WPAD + wn*32 + (lane>>4)*8) * 2);

    const int nit = K / 16;

    auto load_stage = [&](int st, int it2) {
        size_t ka = (size_t)it2 * 16 * 2;
        size_t kw = (size_t)it2 * 16 * (size_t)N * 2;
        cp16(aAh + (uint32_t)st*SA_B + dA, pAh + ka);
        cp16(aAl + (uint32_t)st*SA_B + dA, pAl + ka);
        cp16(aWh + (uint32_t)st*SW_B + dW, pWh + kw);
        cp16(aWl + (uint32_t)st*SW_B + dW, pWl + kw);
        cp_commit();
    };

    // prologue: stages 0, 1, 2
    load_stage(0, 0);
    load_stage(1, 1);
    load_stage(2, 2);

    for (int it = 0; it < nit; ++it) {
        int rem = nit - 1 - it;
        if (rem >= 2) cp_wait2();
        else if (rem == 1) cp_wait1();
        else cp_wait0();
        __syncthreads();
        if (it + 3 < nit)
            load_stage((it + 3) & 3, it + 3);
        const uint32_t s = (uint32_t)(it & 3);

        uint32_t afh[4][4], afl[4][4];
        #pragma unroll
        for (int mi = 0; mi < 4; mi++)
            ldsm4(afh[mi], aAh + s*SA_B + offA0 + mi*16*APAD*2);
        #pragma unroll
        for (int mi = 0; mi < 4; mi++)
            ldsm4(afl[mi], aAl + s*SA_B + offA0 + mi*16*APAD*2);

        uint32_t bfr[4][2];
        #pragma unroll
        for (int ng = 0; ng < 2; ng++)
            ldsm4t(bfr[2*ng][0], bfr[2*ng][1], bfr[2*ng+1][0], bfr[2*ng+1][1],
                   aWh + s*SW_B + offB0 + (uint32_t)(ng*16*2));
        #pragma unroll
        for (int mi = 0; mi < 4; mi++)
            #pragma unroll
            for (int ni = 0; ni < 4; ni++) {
                mma16816(acc[mi][ni], afh[mi], bfr[ni][0], bfr[ni][1]);
                mma16816(acc[mi][ni], afl[mi], bfr[ni][0], bfr[ni][1]);
            }
        #pragma unroll
        for (int ng = 0; ng < 2; ng++)
            ldsm4t(bfr[2*ng][0], bfr[2*ng][1], bfr[2*ng+1][0], bfr[2*ng+1][1],
                   aWl + s*SW_B + offB0 + (uint32_t)(ng*16*2));
        #pragma unroll
        for (int mi = 0; mi < 4; mi++)
            #pragma unroll
            for (int ni = 0; ni < 4; ni++)
                mma16816(acc[mi][ni], afh[mi], bfr[ni][0], bfr[ni][1]);
    }

    #pragma unroll
    for (int mi = 0; mi < 4; mi++) {
        #pragma unroll
        for (int ni = 0; ni < 4; ni++) {
            int c = col0 + wn*32 + ni*8 + (lane & 3)*2;
            float bx = bias[c], by = bias[c + 1];
            #pragma unroll
            for (int rh = 0; rh < 2; rh++) {
                size_t r = (size_t)(row0 + wm*64 + mi*16 + (lane >> 2) + rh*8);
                float v0 = acc[mi][ni][2*rh]     + bx;
                float v1 = acc[mi][ni][2*rh + 1] + by;
                if (mode & 1) {
                    v0 = 0.5f * v0 * (1.0f + erff(v0 * 0.70710678118654752f));
                    v1 = 0.5f * v1 * (1.0f + erff(v1 * 0.70710678118654752f));
                }
                if (mode & 2) {
                    float2 o; o.x = v0; o.y = v1;
                    *(float2*)&C[r * N + c] = o;
                }
                if (mode & 4) {
                    uint32_t hp, lp;
                    pack_pair(v0, v1, hp, lp);
                    *(uint32_t*)&Ch[r * N + c] = hp;
                    *(uint32_t*)&Cl[r * N + c] = lp;
                }
                if (mode & 8) {
                    *(uint32_t*)&Ch[r * N + c] = pack_hi(v0, v1);
                }
            }
        }
    }
}

__global__ __launch_bounds__(256)
void gemm_bf16x3_kernel(const bf16* __restrict__ Ah, const bf16* __restrict__ Al,
                        const bf16* __restrict__ Wh, const bf16* __restrict__ Wl,
                        const float* __restrict__ bias, float* __restrict__ C,
                        bf16* __restrict__ Ch, bf16* __restrict__ Cl,
                        int N, int K, int mode)
{
    gemm_core(Ah, Al, Wh, Wl, bias, C, Ch, Cl, N, K, mode,
              blockIdx.y * 128, blockIdx.x * 128);
}

// merged Q/K/V projection: blockIdx.z selects weight/output set; hi-only output
struct QKVArgs {
    const bf16* Wh[3];
    const bf16* Wl[3];
    const float* bias[3];
    bf16* Ch[3];
};
__global__ __launch_bounds__(256)
void qkv_gemm_kernel(const bf16* __restrict__ Ah, const bf16* __restrict__ Al,
                     QKVArgs a)
{
    int z = blockIdx.z;
    gemm_core(Ah, Al, a.Wh[z], a.Wl[z], a.bias[z], nullptr, a.Ch[z], nullptr,
              Dsz, Dsz, 8, blockIdx.y * 128, blockIdx.x * 128);
}

// ---------------- sigmoid gate ----------------------
__global__ __launch_bounds__(256)
void gate_kernel(const float* __restrict__ x, const float* __restrict__ wg,
                 const float* __restrict__ bg, float* __restrict__ gate)
{
    __shared__ float wgs[Dsz][8];
    int hg = blockIdx.y;
    int tid = threadIdx.x;
    for (int idx = tid; idx < Dsz*8; idx += 256)
        wgs[idx >> 3][idx & 7] = wg[(idx >> 3) * Hsz + hg*8 + (idx & 7)];
    __syncthreads();

    int h = tid & 7, r = tid >> 3;
    int m = blockIdx.x * 32 + r;
    const float4* xr = (const float4*)(x + (size_t)m * Dsz);
    float s = 0.0f;
    #pragma unroll 4
    for (int d4 = 0; d4 < Dsz/4; d4++) {
        float4 xv = xr[d4];
        s = fmaf(xv.x, wgs[d4*4 + 0][h], s);
        s = fmaf(xv.y, wgs[d4*4 + 1][h], s);
        s = fmaf(xv.z, wgs[d4*4 + 2][h], s);
        s = fmaf(xv.w, wgs[d4*4 + 3][h], s);
    }
    s += bg[hg*8 + h];
    gate[(size_t)m * Hsz + hg*8 + h] = 1.0f / (1.0f + __expf(-s));
}

// ---------------- tensor-core flash attention (pure bf16 S and PV) -------------
#define FPAD 72
#define KV_STRIDE (64*FPAD)          // elems per [64][72] buffer
#define STAGE_ELEMS (2*KV_STRIDE)    // Kh, Vh
#define FLASH_SMEM (2*STAGE_ELEMS*2 + 2*64*4)   // 37376

__global__ __launch_bounds__(128, 4)
void flash_tc_kernel(const bf16* __restrict__ Qh,
                     const bf16* __restrict__ Kh,
                     const bf16* __restrict__ Vh,
                     const float* __restrict__ gate, const int* __restrict__ mask,
                     bf16* __restrict__ Ch, bf16* __restrict__ Cl)
{
    extern __shared__ __align__(16) char dynsmem[];
    int* smsk = (int*)(dynsmem + (size_t)2*STAGE_ELEMS*2);

    const int tid = threadIdx.x, lane = tid & 31, warp = tid >> 5;
    const int qt = blockIdx.x, h = blockIdx.y, b = blockIdx.z;
    const size_t rowbase = (size_t)b * Ssz;
    const size_t hoff = (size_t)h * DKsz;

    const uint32_t sbase = (uint32_t)__cvta_generic_to_shared(dynsmem);
    const uint32_t mbase = (uint32_t)__cvta_generic_to_shared(smsk);

    // stage Q (hi only) into buffer 0, extract fragments
    {
        int r = tid >> 1;
        size_t gq = (rowbase + qt*64 + r) * Dsz + hoff;
        #pragma unroll
        for (int j = 0; j < 4; j++) {
            int c8 = (tid & 1)*4 + j;
            uint32_t dof = (uint32_t)((r*FPAD + c8*8)*2);
            cp16(sbase + dof, Qh + gq + c8*8);
        }
        cp_commit(); cp_wait0();
    }
    __syncthreads();

    uint32_t qfh[4][4];
    {
        uint32_t arow = (uint32_t)((warp*16 + (lane&15))*FPAD*2);
        #pragma unroll
        for (int ks = 0; ks < 4; ks++) {
            uint32_t acol = (uint32_t)((16*ks + (lane>>4)*8)*2);
            ldsm4(qfh[ks], sbase + arow + acol);
        }
    }
    __syncthreads();

    float oacc[8][4];
    #pragma unroll
    for (int i = 0; i < 8; i++)
        #pragma unroll
        for (int j = 0; j < 4; j++) oacc[i][j] = 0.0f;
    float m0 = -1e30f, m1 = -1e30f, l0 = 0.0f, l1 = 0.0f;

    const int r_ld = tid >> 1;
    const int cbase = (tid & 1)*4;

    // prologue tile 0
    {
        size_t g = (rowbase + r_ld) * Dsz + hoff;
        #pragma unroll
        for (int j = 0; j < 4; j++) {
            int c8 = cbase + j;
            uint32_t dof = (uint32_t)((r_ld*FPAD + c8*8)*2);
            cp16(sbase + dof, Kh + g + c8*8);
            cp16(sbase + KV_STRIDE*2 + dof, Vh + g + c8*8);
        }
        if (tid < 16) cp16(mbase + tid*16, mask + rowbase + tid*4);
        cp_commit();
    }

    const int col0 = 2*(lane & 3);

    for (int kt = 0; kt < Ssz/64; kt++) {
        cp_wait0();
        __syncthreads();
        if (kt + 1 < Ssz/64) {
            int st = (kt + 1) & 1;
            size_t g = (rowbase + (kt+1)*64 + r_ld) * Dsz + hoff;
            uint32_t sb = sbase + (uint32_t)(st*STAGE_ELEMS*2);
            #pragma unroll
            for (int j = 0; j < 4; j++) {
                int c8 = cbase + j;
                uint32_t dof = (uint32_t)((r_ld*FPAD + c8*8)*2);
                cp16(sb + dof, Kh + g + c8*8);
                cp16(sb + KV_STRIDE*2 + dof, Vh + g + c8*8);
            }
            if (tid < 16) cp16(mbase + st*256 + tid*16, mask + rowbase + (kt+1)*64 + tid*4);
            cp_commit();
        }
        const int st = kt & 1;
        const uint32_t kb = sbase + (uint32_t)(st*STAGE_ELEMS*2);

        // ---- S = Q K^T (bf16) ----
        float sc[8][4];
        #pragma unroll
        for (int i = 0; i < 8; i++)
            #pragma unroll
            for (int j = 0; j < 4; j++) sc[i][j] = 0.0f;

        const uint32_t brow = (uint32_t)(((lane&7) + ((lane>>1)&8)) * FPAD * 2);
        const uint32_t bcol = (uint32_t)((lane & 8) * 2);
        #pragma unroll
        for (int ng = 0; ng < 4; ng++) {
            #pragma unroll
            for (int ks = 0; ks < 4; ks++) {
                uint32_t ba = kb + brow + (uint32_t)(16*ng*FPAD*2) + bcol + (uint32_t)(16*ks*2);
                uint32_t bh4[4];
                ldsm4(bh4, ba);
                mma16816(sc[2*ng],   qfh[ks], bh4[0], bh4[1]);
                mma16816(sc[2*ng+1], qfh[ks], bh4[2], bh4[3]);
            }
        }

        // ---- online softmax ----
        const int* mk = smsk + st*64;
        float mx0 = -1e30f, mx1 = -1e30f;
        #pragma unroll
        for (int ni = 0; ni < 8; ni++) {
            int c = 8*ni + col0;
            bool z0 = (mk[c] == 0), z1 = (mk[c+1] == 0);
            sc[ni][0] = z0 ? -1e9f : sc[ni][0]*0.125f;
            sc[ni][1] = z1 ? -1e9f : sc[ni][1]*0.125f;
            sc[ni][2] = z0 ? -1e9f : sc[ni][2]*0.125f;
            sc[ni][3] = z1 ? -1e9f : sc[ni][3]*0.125f;
            mx0 = fmaxf(mx0, fmaxf(sc[ni][0], sc[ni][1]));
            mx1 = fmaxf(mx1, fmaxf(sc[ni][2], sc[ni][3]));
        }
        mx0 = fmaxf(mx0, __shfl_xor_sync(0xffffffffu, mx0, 1));
        mx0 = fmaxf(mx0, __shfl_xor_sync(0xffffffffu, mx0, 2));
        mx1 = fmaxf(mx1, __shfl_xor_sync(0xffffffffu, mx1, 1));
        mx1 = fmaxf(mx1, __shfl_xor_sync(0xffffffffu, mx1, 2));
        float mn0 = fmaxf(m0, mx0), mn1 = fmaxf(m1, mx1);
        float al0 = __expf(m0 - mn0), al1 = __expf(m1 - mn1);
        float rs0 = 0.0f, rs1 = 0.0f;
        #pragma unroll
        for (int ni = 0; ni < 8; ni++) {
            sc[ni][0] = __expf(sc[ni][0] - mn0);
            sc[ni][1] = __expf(sc[ni][1] - mn0);
            sc[ni][2] = __expf(sc[ni][2] - mn1);
            sc[ni][3] = __expf(sc[ni][3] - mn1);
            rs0 += sc[ni][0] + sc[ni][1];
            rs1 += sc[ni][2] + sc[ni][3];
        }
        rs0 += __shfl_xor_sync(0xffffffffu, rs0, 1);
        rs0 += __shfl_xor_sync(0xffffffffu, rs0, 2);
        rs1 += __shfl_xor_sync(0xffffffffu, rs1, 1);
        rs1 += __shfl_xor_sync(0xffffffffu, rs1, 2);
        l0 = l0*al0 + rs0; l1 = l1*al1 + rs1;
        m0 = mn0; m1 = mn1;
        #pragma unroll
        for (int ni = 0; ni < 8; ni++) {
            oacc[ni][0] *= al0; oacc[ni][1] *= al0;
            oacc[ni][2] *= al1; oacc[ni][3] *= al1;
        }

        // ---- O += P V (bf16) ----
        const uint32_t vrow0 = (uint32_t)((lane&15)*FPAD*2);
        const uint32_t vcol0 = (uint32_t)(((lane>>4)*8)*2);
        #pragma unroll
        for (int ki = 0; ki < 4; ki++) {
            uint32_t ph[4];
            ph[0] = pack_hi(sc[2*ki][0],   sc[2*ki][1]);
            ph[1] = pack_hi(sc[2*ki][2],   sc[2*ki][3]);
            ph[2] = pack_hi(sc[2*ki+1][0], sc[2*ki+1][1]);
            ph[3] = pack_hi(sc[2*ki+1][2], sc[2*ki+1][3]);
            uint32_t va0 = kb + KV_STRIDE*2 + vrow0 + (uint32_t)(16*ki*FPAD*2) + vcol0;
            #pragma unroll
            for (int ngd = 0; ngd < 4; ngd++) {
                uint32_t vh4[4];
                ldsm4t(vh4[0], vh4[1], vh4[2], vh4[3], va0 + (uint32_t)(16*ngd*2));
                mma16816(oacc[2*ngd],   ph, vh4[0], vh4[1]);
                mma16816(oacc[2*ngd+1], ph, vh4[2], vh4[3]);
            }
        }
    }

    int q0 = qt*64 + warp*16 + (lane >> 2);
    float f0 = gate[(rowbase + q0)*Hsz + h] / l0;
    float f1 = gate[(rowbase + q0 + 8)*Hsz + h] / l1;
    #pragma unroll
    for (int ni = 0; ni < 8; ni++) {
        size_t o0 = (rowbase + q0) * Dsz + hoff + 8*ni + col0;
        size_t o1 = o0 + (size_t)8 * Dsz;
        uint32_t hp, lp;
        pack_pair(oacc[ni][0]*f0, oacc[ni][1]*f0, hp, lp);
        *(uint32_t*)&Ch[o0] = hp;
        *(uint32_t*)&Cl[o0] = lp;
        pack_pair(oacc[ni][2]*f1, oacc[ni][3]*f1, hp, lp);
        *(uint32_t*)&Ch[o1] = hp;
        *(uint32_t*)&Cl[o1] = lp;
    }
}

// ---------------- fused residual add + LayerNorm (+ optional bf16 split out) ----
__global__ __launch_bounds__(256)
void add_ln_kernel(const float* __restrict__ a, const float* __restrict__ bsrc,
                   const float* __restrict__ g, const float* __restrict__ beta,
                   float* __restrict__ out, bf16* __restrict__ oh, bf16* __restrict__ ol)
{
    int row = blockIdx.x;
    int tid = threadIdx.x;
    __shared__ float buf[Dsz];
    __shared__ float rsum[8], rsq[8];

    size_t base = (size_t)row * Dsz;
    float ls = 0.0f, lq = 0.0f;
    for (int d = tid; d < Dsz; d += 256) {
        float v = a[base + d] + bsrc[base + d];
        buf[d] = v;
        ls += v; lq += v * v;
    }
    int warp = tid >> 5, lane = tid & 31;
    for (int off = 16; off; off >>= 1) {
        ls += __shfl_xor_sync(0xffffffffu, ls, off);
        lq += __shfl_xor_sync(0xffffffffu, lq, off);
    }
    if (lane == 0) { rsum[warp] = ls; rsq[warp] = lq; }
    __syncthreads();
    float ts = 0.0f, tq = 0.0f;
    #pragma unroll
    for (int w = 0; w < 8; w++) { ts += rsum[w]; tq += rsq[w]; }
    float mean = ts * (1.0f / Dsz);
    float var  = tq * (1.0f / Dsz) - mean * mean;
    float rstd = rsqrtf(var + 1e-5f);
    for (int d = tid; d < Dsz; d += 256) {
        float v = (buf[d] - mean) * rstd * g[d] + beta[d];
        out[base + d] = v;
        if (oh) {
            bf16 hv = __float2bfloat16(v);
            oh[base + d] = hv;
            ol[base + d] = __float2bfloat16(v - __bfloat162float(hv));
        }
    }
}

// ---------------- launch ----------------
extern "C" void kernel_launch(void* const* d_in, const int* in_sizes, int n_in,
                              void* d_out, int out_size)
{
    const float* x     = (const float*)d_in[0];
    const float* w_q   = (const float*)d_in[1];
    const float* b_q   = (const float*)d_in[2];
    const float* w_k   = (const float*)d_in[3];
    const float* b_k   = (const float*)d_in[4];
    const float* w_v   = (const float*)d_in[5];
    const float* b_v   = (const float*)d_in[6];
    const float* w_o   = (const float*)d_in[7];
    const float* b_o   = (const float*)d_in[8];
    const float* w_g   = (const float*)d_in[9];
    const float* b_g   = (const float*)d_in[10];
    const float* w1    = (const float*)d_in[11];
    const float* b1    = (const float*)d_in[12];
    const float* w2    = (const float*)d_in[13];
    const float* b2    = (const float*)d_in[14];
    const float* g1    = (const float*)d_in[15];
    const float* beta1 = (const float*)d_in[16];
    const float* g2    = (const float*)d_in[17];
    const float* beta2 = (const float*)d_in[18];
    const int*   mask  = (const int*)  d_in[19];
    float* out = (float*)d_out;

    float *tmp, *x1, *gate;
    cudaGetSymbolAddress((void**)&tmp,  g_tmp);
    cudaGetSymbolAddress((void**)&x1,   g_x1);
    cudaGetSymbolAddress((void**)&gate, g_gate);

    bf16 *xh,*xl,*qh,*kh,*vh,*ctxh,*ctxl,*x1h,*x1l,*ffh,*ffl;
    bf16 *wqh,*wql,*wkh,*wkl,*wvh,*wvl,*woh,*wol,*w1h,*w1l,*w2h,*w2l;
    cudaGetSymbolAddress((void**)&xh,  g_xh);   cudaGetSymbolAddress((void**)&xl,  g_xl);
    cudaGetSymbolAddress((void**)&qh,  g_qh);
    cudaGetSymbolAddress((void**)&kh,  g_kh);
    cudaGetSymbolAddress((void**)&vh,  g_vh);
    cudaGetSymbolAddress((void**)&ctxh,g_ctxh); cudaGetSymbolAddress((void**)&ctxl,g_ctxl);
    cudaGetSymbolAddress((void**)&x1h, g_x1h);  cudaGetSymbolAddress((void**)&x1l, g_x1l);
    cudaGetSymbolAddress((void**)&ffh, g_ffh);  cudaGetSymbolAddress((void**)&ffl, g_ffl);
    cudaGetSymbolAddress((void**)&wqh, g_wqh);  cudaGetSymbolAddress((void**)&wql, g_wql);
    cudaGetSymbolAddress((void**)&wkh, g_wkh);  cudaGetSymbolAddress((void**)&wkl, g_wkl);
    cudaGetSymbolAddress((void**)&wvh, g_wvh);  cudaGetSymbolAddress((void**)&wvl, g_wvl);
    cudaGetSymbolAddress((void**)&woh, g_woh);  cudaGetSymbolAddress((void**)&wol, g_wol);
    cudaGetSymbolAddress((void**)&w1h, g_w1h);  cudaGetSymbolAddress((void**)&w1l, g_w1l);
    cudaGetSymbolAddress((void**)&w2h, g_w2h);  cudaGetSymbolAddress((void**)&w2l, g_w2l);

    cudaFuncSetAttribute(flash_tc_kernel,
                         cudaFuncAttributeMaxDynamicSharedMemorySize, FLASH_SMEM);
    cudaFuncSetAttribute(gemm_bf16x3_kernel,
                         cudaFuncAttributeMaxDynamicSharedMemorySize, GEMM_SMEM);
    cudaFuncSetAttribute(qkv_gemm_kernel,
                         cudaFuncAttributeMaxDynamicSharedMemorySize, GEMM_SMEM);

    // 0: fused split of x + all weights
    SplitArgs sa;
    sa.src[0] = x;   sa.hi[0] = xh;  sa.lo[0] = xl;
    sa.src[1] = w_q; sa.hi[1] = wqh; sa.lo[1] = wql;
    sa.src[2] = w_k; sa.hi[2] = wkh; sa.lo[2] = wkl;
    sa.src[3] = w_v; sa.hi[3] = wvh; sa.lo[3] = wvl;
    sa.src[4] = w_o; sa.hi[4] = woh; sa.lo[4] = wol;
    sa.src[5] = w1;  sa.hi[5] = w1h; sa.lo[5] = w1l;
    sa.src[6] = w2;  sa.hi[6] = w2h; sa.lo[6] = w2l;
    split_all_kernel<<<20480, 256>>>(sa);

    // 1: merged QKV GEMM (hi-only outputs)
    QKVArgs qa;
    qa.Wh[0] = wqh; qa.Wl[0] = wql; qa.bias[0] = b_q; qa.Ch[0] = qh;
    qa.Wh[1] = wkh; qa.Wl[1] = wkl; qa.bias[1] = b_k; qa.Ch[1] = kh;
    qa.Wh[2] = wvh; qa.Wl[2] = wvl; qa.bias[2] = b_v; qa.Ch[2] = vh;
    qkv_gemm_kernel<<<dim3(Dsz/128, Msz/128, 3), 256, GEMM_SMEM>>>(xh, xl, qa);

    // 2: gate
    gate_kernel<<<dim3(Msz/32, 2), 256>>>(x, w_g, b_g, gate);

    // 3: flash attention (pure bf16)
    flash_tc_kernel<<<dim3(Ssz/64, Hsz, Bsz), 128, FLASH_SMEM>>>(
        qh, kh, vh, gate, mask, ctxh, ctxl);

    dim3 gSq(Dsz/128, Msz/128);      // (8, 64)
    dim3 gF1(DFFsz/128, Msz/128);    // (32, 64)

    // 4-8: O-proj, LN1, FF1, FF2, LN2 (all 3-term)
    gemm_bf16x3_kernel<<<gSq, 256, GEMM_SMEM>>>(ctxh, ctxl, woh, wol, b_o, tmp, nullptr, nullptr, Dsz, Dsz, 2);
    add_ln_kernel<<<Msz, 256>>>(x, tmp, g1, beta1, x1, x1h, x1l);
    gemm_bf16x3_kernel<<<gF1, 256, GEMM_SMEM>>>(x1h, x1l, w1h, w1l, b1, nullptr, ffh, ffl, DFFsz, Dsz, 5);
    gemm_bf16x3_kernel<<<gSq, 256, GEMM_SMEM>>>(ffh, ffl, w2h, w2l, b2, tmp, nullptr, nullptr, Dsz, DFFsz, 2);
    add_ln_kernel<<<Msz, 256>>>(x1, tmp, g2, beta2, out, nullptr, nullptr);
}

// round 11
// speedup vs baseline: 1.5406x; 1.1881x over previous
#include <cuda_runtime.h>
#include <cuda_bf16.h>
#include <math.h>
#include <cstdint>

// Problem constants
#define Bsz   4
#define Ssz   2048
#define Dsz   1024
#define Hsz   16
#define DKsz  64
#define DFFsz 4096
#define Msz   (Bsz*Ssz)   // 8192 rows

typedef __nv_bfloat16 bf16;

// ---------------- scratch (static device globals; no allocation) ----------------
__device__ float g_tmp [(size_t)Msz*Dsz];
__device__ float g_x1  [(size_t)Msz*Dsz];
__device__ float g_gate[(size_t)Msz*Hsz];

__device__ bf16 g_xh [(size_t)Msz*Dsz],   g_xl [(size_t)Msz*Dsz];
__device__ bf16 g_qh [(size_t)Msz*Dsz];
__device__ bf16 g_kh [(size_t)Msz*Dsz];
__device__ bf16 g_vh [(size_t)Msz*Dsz];
__device__ bf16 g_ctxh[(size_t)Msz*Dsz];
__device__ bf16 g_x1h[(size_t)Msz*Dsz],   g_x1l[(size_t)Msz*Dsz];
__device__ bf16 g_ffh[(size_t)Msz*DFFsz], g_ffl[(size_t)Msz*DFFsz];
__device__ bf16 g_wqh[(size_t)Dsz*Dsz],   g_wql[(size_t)Dsz*Dsz];
__device__ bf16 g_wkh[(size_t)Dsz*Dsz],   g_wkl[(size_t)Dsz*Dsz];
__device__ bf16 g_wvh[(size_t)Dsz*Dsz],   g_wvl[(size_t)Dsz*Dsz];
__device__ bf16 g_woh[(size_t)Dsz*Dsz],   g_wol[(size_t)Dsz*Dsz];
__device__ bf16 g_w1h[(size_t)Dsz*DFFsz], g_w1l[(size_t)Dsz*DFFsz];
__device__ bf16 g_w2h[(size_t)DFFsz*Dsz], g_w2l[(size_t)DFFsz*Dsz];

// ---------------- small helpers ----------------
__device__ __forceinline__ void cp16(uint32_t dst, const void* src) {
    asm volatile("cp.async.ca.shared.global [%0], [%1], 16;\n" :: "r"(dst), "l"(src));
}
__device__ __forceinline__ void cp_commit() {
    asm volatile("cp.async.commit_group;\n");
}
__device__ __forceinline__ void cp_wait0() {
    asm volatile("cp.async.wait_group 0;\n");
}
__device__ __forceinline__ void cp_wait1() {
    asm volatile("cp.async.wait_group 1;\n");
}
__device__ __forceinline__ void cp_wait2() {
    asm volatile("cp.async.wait_group 2;\n");
}
__device__ __forceinline__ void ldsm4(uint32_t* r, uint32_t addr) {
    asm volatile("ldmatrix.sync.aligned.m8n8.x4.shared.b16 {%0,%1,%2,%3}, [%4];"
                 : "=r"(r[0]), "=r"(r[1]), "=r"(r[2]), "=r"(r[3]) : "r"(addr));
}
__device__ __forceinline__ void ldsm4t(uint32_t& r0, uint32_t& r1,
                                       uint32_t& r2, uint32_t& r3, uint32_t addr) {
    asm volatile("ldmatrix.sync.aligned.m8n8.x4.trans.shared.b16 {%0,%1,%2,%3}, [%4];"
                 : "=r"(r0), "=r"(r1), "=r"(r2), "=r"(r3) : "r"(addr));
}
__device__ __forceinline__ void mma16816(float* ac, const uint32_t* a,
                                         uint32_t b0, uint32_t b1) {
    asm volatile(
        "mma.sync.aligned.m16n8k16.row.col.f32.bf16.bf16.f32 "
        "{%0,%1,%2,%3},{%4,%5,%6,%7},{%8,%9},{%0,%1,%2,%3};"
        : "+f"(ac[0]), "+f"(ac[1]), "+f"(ac[2]), "+f"(ac[3])
        : "r"(a[0]), "r"(a[1]), "r"(a[2]), "r"(a[3]), "r"(b0), "r"(b1));
}
__device__ __forceinline__ void pack_pair(float a, float b, uint32_t& hi, uint32_t& lo) {
    bf16 ha = __float2bfloat16(a), hb = __float2bfloat16(b);
    bf16 la = __float2bfloat16(a - __bfloat162float(ha));
    bf16 lb = __float2bfloat16(b - __bfloat162float(hb));
    __nv_bfloat162 th = __halves2bfloat162(ha, hb);
    __nv_bfloat162 tl = __halves2bfloat162(la, lb);
    hi = *(uint32_t*)&th; lo = *(uint32_t*)&tl;
}
__device__ __forceinline__ uint32_t pack_hi(float a, float b) {
    __nv_bfloat162 th = __halves2bfloat162(__float2bfloat16(a), __float2bfloat16(b));
    return *(uint32_t*)&th;
}

// ---------------- fused split of x + all 6 weights (one launch) ----------------
struct SplitArgs {
    const float* src[7];
    bf16* hi[7];
    bf16* lo[7];
};
__global__ __launch_bounds__(256)
void split_all_kernel(SplitArgs a)
{
    int bid = blockIdx.x;
    int seg, base;
    if      (bid < 8192)  { seg = 0; base = 0; }
    else if (bid < 9216)  { seg = 1; base = 8192; }
    else if (bid < 10240) { seg = 2; base = 9216; }
    else if (bid < 11264) { seg = 3; base = 10240; }
    else if (bid < 12288) { seg = 4; base = 11264; }
    else if (bid < 16384) { seg = 5; base = 12288; }
    else                  { seg = 6; base = 16384; }
    size_t i = (size_t)(bid - base) * 256 + threadIdx.x;
    float4 v = ((const float4*)a.src[seg])[i];
    uint32_t h0, l0, h1, l1;
    pack_pair(v.x, v.y, h0, l0);
    pack_pair(v.z, v.w, h1, l1);
    uint32_t* hp = (uint32_t*)a.hi[seg];
    uint32_t* lp = (uint32_t*)a.lo[seg];
    hp[2*i] = h0; hp[2*i+1] = h1;
    lp[2*i] = l0; lp[2*i+1] = l1;
}

// ---------------- bf16 tensor-core GEMM core (4-stage cp.async) ----------
// BM=BN=128, BK=16, 256 threads = 8 warps (2 M x 4 N), warp tile 64x32.
// TERMS=3: acc = Ah*Wh + Al*Wh + Ah*Wl.  TERMS=1: acc = Ah*Wh.
// mode bits: 1=GELU, 2=write fp32 C, 4=write bf16 Ch/Cl, 8=write bf16 Ch only
#define APAD 24   // 16 + 8 bf16 pad
#define WPAD 136  // 128 + 8 pad
#define NSTG 4
#define SA_B (128*APAD*2)   // 6144 B per A stage buffer
#define SW_B (16*WPAD*2)    // 4352 B per W stage buffer
#define GEMM_SMEM  (NSTG*(2*SA_B + 2*SW_B))   // 83968 (TERMS=3)
#define GEMM_SMEM1 (NSTG*(SA_B + SW_B))       // 41984 (TERMS=1)

template<int TERMS>
__device__ __forceinline__
void gemm_core(const bf16* __restrict__ Ah, const bf16* __restrict__ Al,
               const bf16* __restrict__ Wh, const bf16* __restrict__ Wl,
               const float* __restrict__ bias, float* __restrict__ C,
               bf16* __restrict__ Ch, bf16* __restrict__ Cl,
               int N, int K, int mode, int row0, int col0)
{
    extern __shared__ __align__(16) char gdsm[];
    const uint32_t aAh = (uint32_t)__cvta_generic_to_shared(gdsm);
    const uint32_t aAl = aAh + NSTG*SA_B;                          // TERMS==3 only
    const uint32_t aWh = (TERMS == 3) ? (aAl + NSTG*SA_B) : (aAh + NSTG*SA_B);
    const uint32_t aWl = aWh + NSTG*SW_B;                          // TERMS==3 only

    const int tid = threadIdx.x;

    const char* pAh = (const char*)(Ah + (size_t)(row0 + (tid>>1)) * K + (tid&1)*8);
    const char* pAl = (TERMS == 3) ? (const char*)(Al + (size_t)(row0 + (tid>>1)) * K + (tid&1)*8) : nullptr;
    const char* pWh = (const char*)(Wh + (size_t)(tid>>4) * N + col0 + (tid&15)*8);
    const char* pWl = (TERMS == 3) ? (const char*)(Wl + (size_t)(tid>>4) * N + col0 + (tid&15)*8) : nullptr;

    const uint32_t dA = ((tid>>1)*APAD + (tid&1)*8) * 2;
    const uint32_t dW = ((tid>>4)*WPAD + (tid&15)*8) * 2;

    float acc[4][4][4];
    #pragma unroll
    for (int i = 0; i < 4; i++)
        #pragma unroll
        for (int j = 0; j < 4; j++)
            #pragma unroll
            for (int t = 0; t < 4; t++) acc[i][j][t] = 0.0f;

    const int wid = tid >> 5, lane = tid & 31;
    const int wm = wid & 1;       // M offset wm*64
    const int wn = wid >> 1;      // N offset wn*32
    const int lrow = lane & 15, lk = (lane >> 4) * 8;
    const uint32_t offA0 = (uint32_t)(((wm*64 + lrow) * APAD + lk) * 2);
    const uint32_t offB0 = (uint32_t)(((lane & 15) * WPAD + wn*32 + (lane>>4)*8) * 2);

    const int nit = K / 16;

    auto load_stage = [&](int st, int it2) {
        size_t ka = (size_t)it2 * 16 * 2;
        size_t kw = (size_t)it2 * 16 * (size_t)N * 2;
        cp16(aAh + (uint32_t)st*SA_B + dA, pAh + ka);
        cp16(aWh + (uint32_t)st*SW_B + dW, pWh + kw);
        if (TERMS == 3) {
            cp16(aAl + (uint32_t)st*SA_B + dA, pAl + ka);
            cp16(aWl + (uint32_t)st*SW_B + dW, pWl + kw);
        }
        cp_commit();
    };

    // prologue: stages 0, 1, 2
    load_stage(0, 0);
    load_stage(1, 1);
    load_stage(2, 2);

    for (int it = 0; it < nit; ++it) {
        int rem = nit - 1 - it;
        if (rem >= 2) cp_wait2();
        else if (rem == 1) cp_wait1();
        else cp_wait0();
        __syncthreads();
        if (it + 3 < nit)
            load_stage((it + 3) & 3, it + 3);
        const uint32_t s = (uint32_t)(it & 3);

        uint32_t afh[4][4];
        #pragma unroll
        for (int mi = 0; mi < 4; mi++)
            ldsm4(afh[mi], aAh + s*SA_B + offA0 + mi*16*APAD*2);

        uint32_t bfr[4][2];
        #pragma unroll
        for (int ng = 0; ng < 2; ng++)
            ldsm4t(bfr[2*ng][0], bfr[2*ng][1], bfr[2*ng+1][0], bfr[2*ng+1][1],
                   aWh + s*SW_B + offB0 + (uint32_t)(ng*16*2));

        if (TERMS == 3) {
            uint32_t afl[4][4];
            #pragma unroll
            for (int mi = 0; mi < 4; mi++)
                ldsm4(afl[mi], aAl + s*SA_B + offA0 + mi*16*APAD*2);
            #pragma unroll
            for (int mi = 0; mi < 4; mi++)
                #pragma unroll
                for (int ni = 0; ni < 4; ni++) {
                    mma16816(acc[mi][ni], afh[mi], bfr[ni][0], bfr[ni][1]);
                    mma16816(acc[mi][ni], afl[mi], bfr[ni][0], bfr[ni][1]);
                }
            #pragma unroll
            for (int ng = 0; ng < 2; ng++)
                ldsm4t(bfr[2*ng][0], bfr[2*ng][1], bfr[2*ng+1][0], bfr[2*ng+1][1],
                       aWl + s*SW_B + offB0 + (uint32_t)(ng*16*2));
            #pragma unroll
            for (int mi = 0; mi < 4; mi++)
                #pragma unroll
                for (int ni = 0; ni < 4; ni++)
                    mma16816(acc[mi][ni], afh[mi], bfr[ni][0], bfr[ni][1]);
        } else {
            #pragma unroll
            for (int mi = 0; mi < 4; mi++)
                #pragma unroll
                for (int ni = 0; ni < 4; ni++)
                    mma16816(acc[mi][ni], afh[mi], bfr[ni][0], bfr[ni][1]);
        }
    }

    #pragma unroll
    for (int mi = 0; mi < 4; mi++) {
        #pragma unroll
        for (int ni = 0; ni < 4; ni++) {
            int c = col0 + wn*32 + ni*8 + (lane & 3)*2;
            float bx = bias[c], by = bias[c + 1];
            #pragma unroll
            for (int rh = 0; rh < 2; rh++) {
                size_t r = (size_t)(row0 + wm*64 + mi*16 + (lane >> 2) + rh*8);
                float v0 = acc[mi][ni][2*rh]     + bx;
                float v1 = acc[mi][ni][2*rh + 1] + by;
                if (mode & 1) {
                    v0 = 0.5f * v0 * (1.0f + erff(v0 * 0.70710678118654752f));
                    v1 = 0.5f * v1 * (1.0f + erff(v1 * 0.70710678118654752f));
                }
                if (mode & 2) {
                    float2 o; o.x = v0; o.y = v1;
                    *(float2*)&C[r * N + c] = o;
                }
                if (mode & 4) {
                    uint32_t hp, lp;
                    pack_pair(v0, v1, hp, lp);
                    *(uint32_t*)&Ch[r * N + c] = hp;
                    *(uint32_t*)&Cl[r * N + c] = lp;
                }
                if (mode & 8) {
                    *(uint32_t*)&Ch[r * N + c] = pack_hi(v0, v1);
                }
            }
        }
    }
}

__global__ __launch_bounds__(256)
void gemm_bf16x3_kernel(const bf16* __restrict__ Ah, const bf16* __restrict__ Al,
                        const bf16* __restrict__ Wh, const bf16* __restrict__ Wl,
                        const float* __restrict__ bias, float* __restrict__ C,
                        bf16* __restrict__ Ch, bf16* __restrict__ Cl,
                        int N, int K, int mode)
{
    gemm_core<3>(Ah, Al, Wh, Wl, bias, C, Ch, Cl, N, K, mode,
                 blockIdx.y * 128, blockIdx.x * 128);
}

// single-term GEMM (bf16 x bf16, hi only)
__global__ __launch_bounds__(256)
void gemm_bf16x1_kernel(const bf16* __restrict__ Ah,
                        const bf16* __restrict__ Wh,
                        const float* __restrict__ bias, float* __restrict__ C,
                        bf16* __restrict__ Ch,
                        int N, int K, int mode)
{
    gemm_core<1>(Ah, nullptr, Wh, nullptr, bias, C, Ch, nullptr, N, K, mode,
                 blockIdx.y * 128, blockIdx.x * 128);
}

// merged Q/K/V projection: blockIdx.z selects weight/output set; 1-term, hi-only out
struct QKVArgs {
    const bf16* Wh[3];
    const float* bias[3];
    bf16* Ch[3];
};
__global__ __launch_bounds__(256)
void qkv_gemm_kernel(const bf16* __restrict__ Ah, QKVArgs a)
{
    int z = blockIdx.z;
    gemm_core<1>(Ah, nullptr, a.Wh[z], nullptr, a.bias[z], nullptr, a.Ch[z], nullptr,
                 Dsz, Dsz, 8, blockIdx.y * 128, blockIdx.x * 128);
}

// ---------------- sigmoid gate ----------------------
__global__ __launch_bounds__(256)
void gate_kernel(const float* __restrict__ x, const float* __restrict__ wg,
                 const float* __restrict__ bg, float* __restrict__ gate)
{
    __shared__ float wgs[Dsz][8];
    int hg = blockIdx.y;
    int tid = threadIdx.x;
    for (int idx = tid; idx < Dsz*8; idx += 256)
        wgs[idx >> 3][idx & 7] = wg[(idx >> 3) * Hsz + hg*8 + (idx & 7)];
    __syncthreads();

    int h = tid & 7, r = tid >> 3;
    int m = blockIdx.x * 32 + r;
    const float4* xr = (const float4*)(x + (size_t)m * Dsz);
    float s = 0.0f;
    #pragma unroll 4
    for (int d4 = 0; d4 < Dsz/4; d4++) {
        float4 xv = xr[d4];
        s = fmaf(xv.x, wgs[d4*4 + 0][h], s);
        s = fmaf(xv.y, wgs[d4*4 + 1][h], s);
        s = fmaf(xv.z, wgs[d4*4 + 2][h], s);
        s = fmaf(xv.w, wgs[d4*4 + 3][h], s);
    }
    s += bg[hg*8 + h];
    gate[(size_t)m * Hsz + hg*8 + h] = 1.0f / (1.0f + __expf(-s));
}

// ---------------- tensor-core flash attention (pure bf16 S and PV) -------------
#define FPAD 72
#define KV_STRIDE (64*FPAD)          // elems per [64][72] buffer
#define STAGE_ELEMS (2*KV_STRIDE)    // Kh, Vh
#define FLASH_SMEM (2*STAGE_ELEMS*2 + 2*64*4)   // 37376

__global__ __launch_bounds__(128, 4)
void flash_tc_kernel(const bf16* __restrict__ Qh,
                     const bf16* __restrict__ Kh,
                     const bf16* __restrict__ Vh,
                     const float* __restrict__ gate, const int* __restrict__ mask,
                     bf16* __restrict__ Ch)
{
    extern __shared__ __align__(16) char dynsmem[];
    int* smsk = (int*)(dynsmem + (size_t)2*STAGE_ELEMS*2);

    const int tid = threadIdx.x, lane = tid & 31, warp = tid >> 5;
    const int qt = blockIdx.x, h = blockIdx.y, b = blockIdx.z;
    const size_t rowbase = (size_t)b * Ssz;
    const size_t hoff = (size_t)h * DKsz;

    const uint32_t sbase = (uint32_t)__cvta_generic_to_shared(dynsmem);
    const uint32_t mbase = (uint32_t)__cvta_generic_to_shared(smsk);

    // stage Q (hi only) into buffer 0, extract fragments
    {
        int r = tid >> 1;
        size_t gq = (rowbase + qt*64 + r) * Dsz + hoff;
        #pragma unroll
        for (int j = 0; j < 4; j++) {
            int c8 = (tid & 1)*4 + j;
            uint32_t dof = (uint32_t)((r*FPAD + c8*8)*2);
            cp16(sbase + dof, Qh + gq + c8*8);
        }
        cp_commit(); cp_wait0();
    }
    __syncthreads();

    uint32_t qfh[4][4];
    {
        uint32_t arow = (uint32_t)((warp*16 + (lane&15))*FPAD*2);
        #pragma unroll
        for (int ks = 0; ks < 4; ks++) {
            uint32_t acol = (uint32_t)((16*ks + (lane>>4)*8)*2);
            ldsm4(qfh[ks], sbase + arow + acol);
        }
    }
    __syncthreads();

    float oacc[8][4];
    #pragma unroll
    for (int i = 0; i < 8; i++)
        #pragma unroll
        for (int j = 0; j < 4; j++) oacc[i][j] = 0.0f;
    float m0 = -1e30f, m1 = -1e30f, l0 = 0.0f, l1 = 0.0f;

    const int r_ld = tid >> 1;
    const int cbase = (tid & 1)*4;

    // prologue tile 0
    {
        size_t g = (rowbase + r_ld) * Dsz + hoff;
        #pragma unroll
        for (int j = 0; j < 4; j++) {
            int c8 = cbase + j;
            uint32_t dof = (uint32_t)((r_ld*FPAD + c8*8)*2);
            cp16(sbase + dof, Kh + g + c8*8);
            cp16(sbase + KV_STRIDE*2 + dof, Vh + g + c8*8);
        }
        if (tid < 16) cp16(mbase + tid*16, mask + rowbase + tid*4);
        cp_commit();
    }

    const int col0 = 2*(lane & 3);

    for (int kt = 0; kt < Ssz/64; kt++) {
        cp_wait0();
        __syncthreads();
        if (kt + 1 < Ssz/64) {
            int st = (kt + 1) & 1;
            size_t g = (rowbase + (kt+1)*64 + r_ld) * Dsz + hoff;
            uint32_t sb = sbase + (uint32_t)(st*STAGE_ELEMS*2);
            #pragma unroll
            for (int j = 0; j < 4; j++) {
                int c8 = cbase + j;
                uint32_t dof = (uint32_t)((r_ld*FPAD + c8*8)*2);
                cp16(sb + dof, Kh + g + c8*8);
                cp16(sb + KV_STRIDE*2 + dof, Vh + g + c8*8);
            }
            if (tid < 16) cp16(mbase + st*256 + tid*16, mask + rowbase + (kt+1)*64 + tid*4);
            cp_commit();
        }
        const int st = kt & 1;
        const uint32_t kb = sbase + (uint32_t)(st*STAGE_ELEMS*2);

        // ---- S = Q K^T (bf16) ----
        float sc[8][4];
        #pragma unroll
        for (int i = 0; i < 8; i++)
            #pragma unroll
            for (int j = 0; j < 4; j++) sc[i][j] = 0.0f;

        const uint32_t brow = (uint32_t)(((lane&7) + ((lane>>1)&8)) * FPAD * 2);
        const uint32_t bcol = (uint32_t)((lane & 8) * 2);
        #pragma unroll
        for (int ng = 0; ng < 4; ng++) {
            #pragma unroll
            for (int ks = 0; ks < 4; ks++) {
                uint32_t ba = kb + brow + (uint32_t)(16*ng*FPAD*2) + bcol + (uint32_t)(16*ks*2);
                uint32_t bh4[4];
                ldsm4(bh4, ba);
                mma16816(sc[2*ng],   qfh[ks], bh4[0], bh4[1]);
                mma16816(sc[2*ng+1], qfh[ks], bh4[2], bh4[3]);
            }
        }

        // ---- online softmax ----
        const int* mk = smsk + st*64;
        float mx0 = -1e30f, mx1 = -1e30f;
        #pragma unroll
        for (int ni = 0; ni < 8; ni++) {
            int c = 8*ni + col0;
            bool z0 = (mk[c] == 0), z1 = (mk[c+1] == 0);
            sc[ni][0] = z0 ? -1e9f : sc[ni][0]*0.125f;
            sc[ni][1] = z1 ? -1e9f : sc[ni][1]*0.125f;
            sc[ni][2] = z0 ? -1e9f : sc[ni][2]*0.125f;
            sc[ni][3] = z1 ? -1e9f : sc[ni][3]*0.125f;
            mx0 = fmaxf(mx0, fmaxf(sc[ni][0], sc[ni][1]));
            mx1 = fmaxf(mx1, fmaxf(sc[ni][2], sc[ni][3]));
        }
        mx0 = fmaxf(mx0, __shfl_xor_sync(0xffffffffu, mx0, 1));
        mx0 = fmaxf(mx0, __shfl_xor_sync(0xffffffffu, mx0, 2));
        mx1 = fmaxf(mx1, __shfl_xor_sync(0xffffffffu, mx1, 1));
        mx1 = fmaxf(mx1, __shfl_xor_sync(0xffffffffu, mx1, 2));
        float mn0 = fmaxf(m0, mx0), mn1 = fmaxf(m1, mx1);
        float al0 = __expf(m0 - mn0), al1 = __expf(m1 - mn1);
        float rs0 = 0.0f, rs1 = 0.0f;
        #pragma unroll
        for (int ni = 0; ni < 8; ni++) {
            sc[ni][0] = __expf(sc[ni][0] - mn0);
            sc[ni][1] = __expf(sc[ni][1] - mn0);
            sc[ni][2] = __expf(sc[ni][2] - mn1);
            sc[ni][3] = __expf(sc[ni][3] - mn1);
            rs0 += sc[ni][0] + sc[ni][1];
            rs1 += sc[ni][2] + sc[ni][3];
        }
        rs0 += __shfl_xor_sync(0xffffffffu, rs0, 1);
        rs0 += __shfl_xor_sync(0xffffffffu, rs0, 2);
        rs1 += __shfl_xor_sync(0xffffffffu, rs1, 1);
        rs1 += __shfl_xor_sync(0xffffffffu, rs1, 2);
        l0 = l0*al0 + rs0; l1 = l1*al1 + rs1;
        m0 = mn0; m1 = mn1;
        #pragma unroll
        for (int ni = 0; ni < 8; ni++) {
            oacc[ni][0] *= al0; oacc[ni][1] *= al0;
            oacc[ni][2] *= al1; oacc[ni][3] *= al1;
        }

        // ---- O += P V (bf16) ----
        const uint32_t vrow0 = (uint32_t)((lane&15)*FPAD*2);
        const uint32_t vcol0 = (uint32_t)(((lane>>4)*8)*2);
        #pragma unroll
        for (int ki = 0; ki < 4; ki++) {
            uint32_t ph[4];
            ph[0] = pack_hi(sc[2*ki][0],   sc[2*ki][1]);
            ph[1] = pack_hi(sc[2*ki][2],   sc[2*ki][3]);
            ph[2] = pack_hi(sc[2*ki+1][0], sc[2*ki+1][1]);
            ph[3] = pack_hi(sc[2*ki+1][2], sc[2*ki+1][3]);
            uint32_t va0 = kb + KV_STRIDE*2 + vrow0 + (uint32_t)(16*ki*FPAD*2) + vcol0;
            #pragma unroll
            for (int ngd = 0; ngd < 4; ngd++) {
                uint32_t vh4[4];
                ldsm4t(vh4[0], vh4[1], vh4[2], vh4[3], va0 + (uint32_t)(16*ngd*2));
                mma16816(oacc[2*ngd],   ph, vh4[0], vh4[1]);
                mma16816(oacc[2*ngd+1], ph, vh4[2], vh4[3]);
            }
        }
    }

    int q0 = qt*64 + warp*16 + (lane >> 2);
    float f0 = gate[(rowbase + q0)*Hsz + h] / l0;
    float f1 = gate[(rowbase + q0 + 8)*Hsz + h] / l1;
    #pragma unroll
    for (int ni = 0; ni < 8; ni++) {
        size_t o0 = (rowbase + q0) * Dsz + hoff + 8*ni + col0;
        size_t o1 = o0 + (size_t)8 * Dsz;
        *(uint32_t*)&Ch[o0] = pack_hi(oacc[ni][0]*f0, oacc[ni][1]*f0);
        *(uint32_t*)&Ch[o1] = pack_hi(oacc[ni][2]*f1, oacc[ni][3]*f1);
    }
}

// ---------------- fused residual add + LayerNorm (+ optional bf16 split out) ----
__global__ __launch_bounds__(256)
void add_ln_kernel(const float* __restrict__ a, const float* __restrict__ bsrc,
                   const float* __restrict__ g, const float* __restrict__ beta,
                   float* __restrict__ out, bf16* __restrict__ oh, bf16* __restrict__ ol)
{
    int row = blockIdx.x;
    int tid = threadIdx.x;
    __shared__ float buf[Dsz];
    __shared__ float rsum[8], rsq[8];

    size_t base = (size_t)row * Dsz;
    float ls = 0.0f, lq = 0.0f;
    for (int d = tid; d < Dsz; d += 256) {
        float v = a[base + d] + bsrc[base + d];
        buf[d] = v;
        ls += v; lq += v * v;
    }
    int warp = tid >> 5, lane = tid & 31;
    for (int off = 16; off; off >>= 1) {
        ls += __shfl_xor_sync(0xffffffffu, ls, off);
        lq += __shfl_xor_sync(0xffffffffu, lq, off);
    }
    if (lane == 0) { rsum[warp] = ls; rsq[warp] = lq; }
    __syncthreads();
    float ts = 0.0f, tq = 0.0f;
    #pragma unroll
    for (int w = 0; w < 8; w++) { ts += rsum[w]; tq += rsq[w]; }
    float mean = ts * (1.0f / Dsz);
    float var  = tq * (1.0f / Dsz) - mean * mean;
    float rstd = rsqrtf(var + 1e-5f);
    for (int d = tid; d < Dsz; d += 256) {
        float v = (buf[d] - mean) * rstd * g[d] + beta[d];
        out[base + d] = v;
        if (oh) {
            bf16 hv = __float2bfloat16(v);
            oh[base + d] = hv;
            ol[base + d] = __float2bfloat16(v - __bfloat162float(hv));
        }
    }
}

// ---------------- launch ----------------
extern "C" void kernel_launch(void* const* d_in, const int* in_sizes, int n_in,
                              void* d_out, int out_size)
{
    const float* x     = (const float*)d_in[0];
    const float* w_q   = (const float*)d_in[1];
    const float* b_q   = (const float*)d_in[2];
    const float* w_k   = (const float*)d_in[3];
    const float* b_k   = (const float*)d_in[4];
    const float* w_v   = (const float*)d_in[5];
    const float* b_v   = (const float*)d_in[6];
    const float* w_o   = (const float*)d_in[7];
    const float* b_o   = (const float*)d_in[8];
    const float* w_g   = (const float*)d_in[9];
    const float* b_g   = (const float*)d_in[10];
    const float* w1    = (const float*)d_in[11];
    const float* b1    = (const float*)d_in[12];
    const float* w2    = (const float*)d_in[13];
    const float* b2    = (const float*)d_in[14];
    const float* g1    = (const float*)d_in[15];
    const float* beta1 = (const float*)d_in[16];
    const float* g2    = (const float*)d_in[17];
    const float* beta2 = (const float*)d_in[18];
    const int*   mask  = (const int*)  d_in[19];
    float* out = (float*)d_out;

    float *tmp, *x1, *gate;
    cudaGetSymbolAddress((void**)&tmp,  g_tmp);
    cudaGetSymbolAddress((void**)&x1,   g_x1);
    cudaGetSymbolAddress((void**)&gate, g_gate);

    bf16 *xh,*xl,*qh,*kh,*vh,*ctxh,*x1h,*x1l,*ffh,*ffl;
    bf16 *wqh,*wql,*wkh,*wkl,*wvh,*wvl,*woh,*wol,*w1h,*w1l,*w2h,*w2l;
    cudaGetSymbolAddress((void**)&xh,  g_xh);   cudaGetSymbolAddress((void**)&xl,  g_xl);
    cudaGetSymbolAddress((void**)&qh,  g_qh);
    cudaGetSymbolAddress((void**)&kh,  g_kh);
    cudaGetSymbolAddress((void**)&vh,  g_vh);
    cudaGetSymbolAddress((void**)&ctxh,g_ctxh);
    cudaGetSymbolAddress((void**)&x1h, g_x1h);  cudaGetSymbolAddress((void**)&x1l, g_x1l);
    cudaGetSymbolAddress((void**)&ffh, g_ffh);  cudaGetSymbolAddress((void**)&ffl, g_ffl);
    cudaGetSymbolAddress((void**)&wqh, g_wqh);  cudaGetSymbolAddress((void**)&wql, g_wql);
    cudaGetSymbolAddress((void**)&wkh, g_wkh);  cudaGetSymbolAddress((void**)&wkl, g_wkl);
    cudaGetSymbolAddress((void**)&wvh, g_wvh);  cudaGetSymbolAddress((void**)&wvl, g_wvl);
    cudaGetSymbolAddress((void**)&woh, g_woh);  cudaGetSymbolAddress((void**)&wol, g_wol);
    cudaGetSymbolAddress((void**)&w1h, g_w1h);  cudaGetSymbolAddress((void**)&w1l, g_w1l);
    cudaGetSymbolAddress((void**)&w2h, g_w2h);  cudaGetSymbolAddress((void**)&w2l, g_w2l);

    cudaFuncSetAttribute(flash_tc_kernel,
                         cudaFuncAttributeMaxDynamicSharedMemorySize, FLASH_SMEM);
    cudaFuncSetAttribute(gemm_bf16x3_kernel,
                         cudaFuncAttributeMaxDynamicSharedMemorySize, GEMM_SMEM);
    cudaFuncSetAttribute(gemm_bf16x1_kernel,
                         cudaFuncAttributeMaxDynamicSharedMemorySize, GEMM_SMEM1);
    cudaFuncSetAttribute(qkv_gemm_kernel,
                         cudaFuncAttributeMaxDynamicSharedMemorySize, GEMM_SMEM1);

    // 0: fused split of x + all weights
    SplitArgs sa;
    sa.src[0] = x;   sa.hi[0] = xh;  sa.lo[0] = xl;
    sa.src[1] = w_q; sa.hi[1] = wqh; sa.lo[1] = wql;
    sa.src[2] = w_k; sa.hi[2] = wkh; sa.lo[2] = wkl;
    sa.src[3] = w_v; sa.hi[3] = wvh; sa.lo[3] = wvl;
    sa.src[4] = w_o; sa.hi[4] = woh; sa.lo[4] = wol;
    sa.src[5] = w1;  sa.hi[5] = w1h; sa.lo[5] = w1l;
    sa.src[6] = w2;  sa.hi[6] = w2h; sa.lo[6] = w2l;
    split_all_kernel<<<20480, 256>>>(sa);

    // 1: merged QKV GEMM (1-term, hi-only outputs)
    QKVArgs qa;
    qa.Wh[0] = wqh; qa.bias[0] = b_q; qa.Ch[0] = qh;
    qa.Wh[1] = wkh; qa.bias[1] = b_k; qa.Ch[1] = kh;
    qa.Wh[2] = wvh; qa.bias[2] = b_v; qa.Ch[2] = vh;
    qkv_gemm_kernel<<<dim3(Dsz/128, Msz/128, 3), 256, GEMM_SMEM1>>>(xh, qa);

    // 2: gate
    gate_kernel<<<dim3(Msz/32, 2), 256>>>(x, w_g, b_g, gate);

    // 3: flash attention (pure bf16, hi-only ctx)
    flash_tc_kernel<<<dim3(Ssz/64, Hsz, Bsz), 128, FLASH_SMEM>>>(
        qh, kh, vh, gate, mask, ctxh);

    dim3 gSq(Dsz/128, Msz/128);      // (8, 64)
    dim3 gF1(DFFsz/128, Msz/128);    // (32, 64)

    // 4: O-proj (1-term)
    gemm_bf16x1_kernel<<<gSq, 256, GEMM_SMEM1>>>(ctxh, woh, b_o, tmp, nullptr, Dsz, Dsz, 2);
    // 5: LN1
    add_ln_kernel<<<Msz, 256>>>(x, tmp, g1, beta1, x1, x1h, x1l);
    // 6: FF1 (3-term, GELU)
    gemm_bf16x3_kernel<<<gF1, 256, GEMM_SMEM>>>(x1h, x1l, w1h, w1l, b1, nullptr, ffh, ffl, DFFsz, Dsz, 5);
    // 7: FF2 (3-term)
    gemm_bf16x3_kernel<<<gSq, 256, GEMM_SMEM>>>(ffh, ffl, w2h, w2l, b2, tmp, nullptr, nullptr, Dsz, DFFsz, 2);
    // 8: LN2
    add_ln_kernel<<<Msz, 256>>>(x1, tmp, g2, beta2, out, nullptr, nullptr);
}

// round 12
// speedup vs baseline: 1.5941x; 1.0347x over previous
#include <cuda_runtime.h>
#include <cuda_bf16.h>
#include <math.h>
#include <cstdint>

// Problem constants
#define Bsz   4
#define Ssz   2048
#define Dsz   1024
#define Hsz   16
#define DKsz  64
#define DFFsz 4096
#define Msz   (Bsz*Ssz)   // 8192 rows

typedef __nv_bfloat16 bf16;

// ---------------- scratch (static device globals; no allocation) ----------------
__device__ float g_tmp [(size_t)Msz*Dsz];
__device__ float g_x1  [(size_t)Msz*Dsz];
__device__ float g_gate[(size_t)Msz*Hsz];

__device__ bf16 g_xh [(size_t)Msz*Dsz],   g_xl [(size_t)Msz*Dsz];
__device__ bf16 g_qh [(size_t)Msz*Dsz];
__device__ bf16 g_kh [(size_t)Msz*Dsz];
__device__ bf16 g_vh [(size_t)Msz*Dsz];
__device__ bf16 g_ctxh[(size_t)Msz*Dsz];
__device__ bf16 g_x1h[(size_t)Msz*Dsz],   g_x1l[(size_t)Msz*Dsz];
__device__ bf16 g_ffh[(size_t)Msz*DFFsz], g_ffl[(size_t)Msz*DFFsz];
__device__ bf16 g_wqh[(size_t)Dsz*Dsz],   g_wql[(size_t)Dsz*Dsz];
__device__ bf16 g_wkh[(size_t)Dsz*Dsz],   g_wkl[(size_t)Dsz*Dsz];
__device__ bf16 g_wvh[(size_t)Dsz*Dsz],   g_wvl[(size_t)Dsz*Dsz];
__device__ bf16 g_woh[(size_t)Dsz*Dsz],   g_wol[(size_t)Dsz*Dsz];
__device__ bf16 g_w1h[(size_t)Dsz*DFFsz], g_w1l[(size_t)Dsz*DFFsz];
__device__ bf16 g_w2h[(size_t)DFFsz*Dsz], g_w2l[(size_t)DFFsz*Dsz];

// ---------------- small helpers ----------------
__device__ __forceinline__ void cp16(uint32_t dst, const void* src) {
    asm volatile("cp.async.ca.shared.global [%0], [%1], 16;\n" :: "r"(dst), "l"(src));
}
__device__ __forceinline__ void cp_commit() {
    asm volatile("cp.async.commit_group;\n");
}
__device__ __forceinline__ void cp_wait0() {
    asm volatile("cp.async.wait_group 0;\n");
}
__device__ __forceinline__ void cp_wait1() {
    asm volatile("cp.async.wait_group 1;\n");
}
__device__ __forceinline__ void cp_wait2() {
    asm volatile("cp.async.wait_group 2;\n");
}
__device__ __forceinline__ void ldsm4(uint32_t* r, uint32_t addr) {
    asm volatile("ldmatrix.sync.aligned.m8n8.x4.shared.b16 {%0,%1,%2,%3}, [%4];"
                 : "=r"(r[0]), "=r"(r[1]), "=r"(r[2]), "=r"(r[3]) : "r"(addr));
}
__device__ __forceinline__ void ldsm4t(uint32_t& r0, uint32_t& r1,
                                       uint32_t& r2, uint32_t& r3, uint32_t addr) {
    asm volatile("ldmatrix.sync.aligned.m8n8.x4.trans.shared.b16 {%0,%1,%2,%3}, [%4];"
                 : "=r"(r0), "=r"(r1), "=r"(r2), "=r"(r3) : "r"(addr));
}
__device__ __forceinline__ void mma16816(float* ac, const uint32_t* a,
                                         uint32_t b0, uint32_t b1) {
    asm volatile(
        "mma.sync.aligned.m16n8k16.row.col.f32.bf16.bf16.f32 "
        "{%0,%1,%2,%3},{%4,%5,%6,%7},{%8,%9},{%0,%1,%2,%3};"
        : "+f"(ac[0]), "+f"(ac[1]), "+f"(ac[2]), "+f"(ac[3])
        : "r"(a[0]), "r"(a[1]), "r"(a[2]), "r"(a[3]), "r"(b0), "r"(b1));
}
__device__ __forceinline__ void pack_pair(float a, float b, uint32_t& hi, uint32_t& lo) {
    bf16 ha = __float2bfloat16(a), hb = __float2bfloat16(b);
    bf16 la = __float2bfloat16(a - __bfloat162float(ha));
    bf16 lb = __float2bfloat16(b - __bfloat162float(hb));
    __nv_bfloat162 th = __halves2bfloat162(ha, hb);
    __nv_bfloat162 tl = __halves2bfloat162(la, lb);
    hi = *(uint32_t*)&th; lo = *(uint32_t*)&tl;
}
__device__ __forceinline__ uint32_t pack_hi(float a, float b) {
    __nv_bfloat162 th = __halves2bfloat162(__float2bfloat16(a), __float2bfloat16(b));
    return *(uint32_t*)&th;
}

// ---------------- splits (x separate from weights, for profiling order) --------
__global__ __launch_bounds__(256)
void split_x_kernel(const float* __restrict__ in, bf16* __restrict__ hi,
                    bf16* __restrict__ lo)
{
    size_t i = (size_t)blockIdx.x * 256 + threadIdx.x;
    float4 v = ((const float4*)in)[i];
    uint32_t h0, l0, h1, l1;
    pack_pair(v.x, v.y, h0, l0);
    pack_pair(v.z, v.w, h1, l1);
    ((uint32_t*)hi)[2*i] = h0; ((uint32_t*)hi)[2*i+1] = h1;
    ((uint32_t*)lo)[2*i] = l0; ((uint32_t*)lo)[2*i+1] = l1;
}

struct SplitWArgs {
    const float* src[6];
    bf16* hi[6];
    bf16* lo[6];
};
__global__ __launch_bounds__(256)
void split_w_kernel(SplitWArgs a)
{
    int bid = blockIdx.x;
    int seg, base;
    if      (bid < 1024)  { seg = 0; base = 0; }
    else if (bid < 2048)  { seg = 1; base = 1024; }
    else if (bid < 3072)  { seg = 2; base = 2048; }
    else if (bid < 4096)  { seg = 3; base = 3072; }
    else if (bid < 8192)  { seg = 4; base = 4096; }
    else                  { seg = 5; base = 8192; }
    size_t i = (size_t)(bid - base) * 256 + threadIdx.x;
    float4 v = ((const float4*)a.src[seg])[i];
    uint32_t h0, l0, h1, l1;
    pack_pair(v.x, v.y, h0, l0);
    pack_pair(v.z, v.w, h1, l1);
    uint32_t* hp = (uint32_t*)a.hi[seg];
    uint32_t* lp = (uint32_t*)a.lo[seg];
    hp[2*i] = h0; hp[2*i+1] = h1;
    lp[2*i] = l0; lp[2*i+1] = l1;
}

// ---------------- bf16 tensor-core GEMM core (4-stage cp.async) ----------
// BM=BN=128, BK=16, 256 threads = 8 warps (2 M x 4 N), warp tile 64x32.
// TERMS=3: acc = Ah*Wh + Al*Wh + Ah*Wl.  TERMS=1: acc = Ah*Wh.
// mode bits: 1=GELU, 2=write fp32 C, 4=write bf16 Ch/Cl, 8=write bf16 Ch only
#define APAD 24   // 16 + 8 bf16 pad
#define WPAD 136  // 128 + 8 pad
#define NSTG 4
#define SA_B (128*APAD*2)   // 6144 B per A stage buffer
#define SW_B (16*WPAD*2)    // 4352 B per W stage buffer
#define GEMM_SMEM  (NSTG*(2*SA_B + 2*SW_B))   // 83968 (TERMS=3)
#define GEMM_SMEM1 (NSTG*(SA_B + SW_B))       // 41984 (TERMS=1)

template<int TERMS>
__device__ __forceinline__
void gemm_core(const bf16* __restrict__ Ah, const bf16* __restrict__ Al,
               const bf16* __restrict__ Wh, const bf16* __restrict__ Wl,
               const float* __restrict__ bias, float* __restrict__ C,
               bf16* __restrict__ Ch, bf16* __restrict__ Cl,
               int N, int K, int mode, int row0, int col0)
{
    extern __shared__ __align__(16) char gdsm[];
    const uint32_t aAh = (uint32_t)__cvta_generic_to_shared(gdsm);
    const uint32_t aAl = aAh + NSTG*SA_B;
    const uint32_t aWh = (TERMS == 3) ? (aAl + NSTG*SA_B) : (aAh + NSTG*SA_B);
    const uint32_t aWl = aWh + NSTG*SW_B;

    const int tid = threadIdx.x;

    const char* pAh = (const char*)(Ah + (size_t)(row0 + (tid>>1)) * K + (tid&1)*8);
    const char* pAl = (TERMS == 3) ? (const char*)(Al + (size_t)(row0 + (tid>>1)) * K + (tid&1)*8) : nullptr;
    const char* pWh = (const char*)(Wh + (size_t)(tid>>4) * N + col0 + (tid&15)*8);
    const char* pWl = (TERMS == 3) ? (const char*)(Wl + (size_t)(tid>>4) * N + col0 + (tid&15)*8) : nullptr;

    const uint32_t dA = ((tid>>1)*APAD + (tid&1)*8) * 2;
    const uint32_t dW = ((tid>>4)*WPAD + (tid&15)*8) * 2;

    float acc[4][4][4];
    #pragma unroll
    for (int i = 0; i < 4; i++)
        #pragma unroll
        for (int j = 0; j < 4; j++)
            #pragma unroll
            for (int t = 0; t < 4; t++) acc[i][j][t] = 0.0f;

    const int wid = tid >> 5, lane = tid & 31;
    const int wm = wid & 1;       // M offset wm*64
    const int wn = wid >> 1;      // N offset wn*32
    const int lrow = lane & 15, lk = (lane >> 4) * 8;
    const uint32_t offA0 = (uint32_t)(((wm*64 + lrow) * APAD + lk) * 2);
    const uint32_t offB0 = (uint32_t)(((lane & 15) * WPAD + wn*32 + (lane>>4)*8) * 2);

    const int nit = K / 16;

    auto load_stage = [&](int st, int it2) {
        size_t ka = (size_t)it2 * 16 * 2;
        size_t kw = (size_t)it2 * 16 * (size_t)N * 2;
        cp16(aAh + (uint32_t)st*SA_B + dA, pAh + ka);
        cp16(aWh + (uint32_t)st*SW_B + dW, pWh + kw);
        if (TERMS == 3) {
            cp16(aAl + (uint32_t)st*SA_B + dA, pAl + ka);
            cp16(aWl + (uint32_t)st*SW_B + dW, pWl + kw);
        }
        cp_commit();
    };

    load_stage(0, 0);
    load_stage(1, 1);
    load_stage(2, 2);

    for (int it = 0; it < nit; ++it) {
        int rem = nit - 1 - it;
        if (rem >= 2) cp_wait2();
        else if (rem == 1) cp_wait1();
        else cp_wait0();
        __syncthreads();
        if (it + 3 < nit)
            load_stage((it + 3) & 3, it + 3);
        const uint32_t s = (uint32_t)(it & 3);

        uint32_t afh[4][4];
        #pragma unroll
        for (int mi = 0; mi < 4; mi++)
            ldsm4(afh[mi], aAh + s*SA_B + offA0 + mi*16*APAD*2);

        uint32_t bfr[4][2];
        #pragma unroll
        for (int ng = 0; ng < 2; ng++)
            ldsm4t(bfr[2*ng][0], bfr[2*ng][1], bfr[2*ng+1][0], bfr[2*ng+1][1],
                   aWh + s*SW_B + offB0 + (uint32_t)(ng*16*2));

        if (TERMS == 3) {
            uint32_t afl[4][4];
            #pragma unroll
            for (int mi = 0; mi < 4; mi++)
                ldsm4(afl[mi], aAl + s*SA_B + offA0 + mi*16*APAD*2);
            #pragma unroll
            for (int mi = 0; mi < 4; mi++)
                #pragma unroll
                for (int ni = 0; ni < 4; ni++) {
                    mma16816(acc[mi][ni], afh[mi], bfr[ni][0], bfr[ni][1]);
                    mma16816(acc[mi][ni], afl[mi], bfr[ni][0], bfr[ni][1]);
                }
            #pragma unroll
            for (int ng = 0; ng < 2; ng++)
                ldsm4t(bfr[2*ng][0], bfr[2*ng][1], bfr[2*ng+1][0], bfr[2*ng+1][1],
                       aWl + s*SW_B + offB0 + (uint32_t)(ng*16*2));
            #pragma unroll
            for (int mi = 0; mi < 4; mi++)
                #pragma unroll
                for (int ni = 0; ni < 4; ni++)
                    mma16816(acc[mi][ni], afh[mi], bfr[ni][0], bfr[ni][1]);
        } else {
            #pragma unroll
            for (int mi = 0; mi < 4; mi++)
                #pragma unroll
                for (int ni = 0; ni < 4; ni++)
                    mma16816(acc[mi][ni], afh[mi], bfr[ni][0], bfr[ni][1]);
        }
    }

    #pragma unroll
    for (int mi = 0; mi < 4; mi++) {
        #pragma unroll
        for (int ni = 0; ni < 4; ni++) {
            int c = col0 + wn*32 + ni*8 + (lane & 3)*2;
            float bx = bias[c], by = bias[c + 1];
            #pragma unroll
            for (int rh = 0; rh < 2; rh++) {
                size_t r = (size_t)(row0 + wm*64 + mi*16 + (lane >> 2) + rh*8);
                float v0 = acc[mi][ni][2*rh]     + bx;
                float v1 = acc[mi][ni][2*rh + 1] + by;
                if (mode & 1) {
                    v0 = 0.5f * v0 * (1.0f + erff(v0 * 0.70710678118654752f));
                    v1 = 0.5f * v1 * (1.0f + erff(v1 * 0.70710678118654752f));
                }
                if (mode & 2) {
                    float2 o; o.x = v0; o.y = v1;
                    *(float2*)&C[r * N + c] = o;
                }
                if (mode & 4) {
                    uint32_t hp, lp;
                    pack_pair(v0, v1, hp, lp);
                    *(uint32_t*)&Ch[r * N + c] = hp;
                    *(uint32_t*)&Cl[r * N + c] = lp;
                }
                if (mode & 8) {
                    *(uint32_t*)&Ch[r * N + c] = pack_hi(v0, v1);
                }
            }
        }
    }
}

__global__ __launch_bounds__(256)
void gemm_bf16x3_kernel(const bf16* __restrict__ Ah, const bf16* __restrict__ Al,
                        const bf16* __restrict__ Wh, const bf16* __restrict__ Wl,
                        const float* __restrict__ bias, float* __restrict__ C,
                        bf16* __restrict__ Ch, bf16* __restrict__ Cl,
                        int N, int K, int mode)
{
    gemm_core<3>(Ah, Al, Wh, Wl, bias, C, Ch, Cl, N, K, mode,
                 blockIdx.y * 128, blockIdx.x * 128);
}

__global__ __launch_bounds__(256)
void gemm_bf16x1_kernel(const bf16* __restrict__ Ah,
                        const bf16* __restrict__ Wh,
                        const float* __restrict__ bias, float* __restrict__ C,
                        bf16* __restrict__ Ch,
                        int N, int K, int mode)
{
    gemm_core<1>(Ah, nullptr, Wh, nullptr, bias, C, Ch, nullptr, N, K, mode,
                 blockIdx.y * 128, blockIdx.x * 128);
}

// merged Q/K/V projection: blockIdx.z selects weight/output set; 1-term, hi-only out
struct QKVArgs {
    const bf16* Wh[3];
    const float* bias[3];
    bf16* Ch[3];
};
__global__ __launch_bounds__(256)
void qkv_gemm_kernel(const bf16* __restrict__ Ah, QKVArgs a)
{
    int z = blockIdx.z;
    gemm_core<1>(Ah, nullptr, a.Wh[z], nullptr, a.bias[z], nullptr, a.Ch[z], nullptr,
                 Dsz, Dsz, 8, blockIdx.y * 128, blockIdx.x * 128);
}

// ---------------- sigmoid gate ----------------------
__global__ __launch_bounds__(256)
void gate_kernel(const float* __restrict__ x, const float* __restrict__ wg,
                 const float* __restrict__ bg, float* __restrict__ gate)
{
    __shared__ float wgs[Dsz][8];
    int hg = blockIdx.y;
    int tid = threadIdx.x;
    for (int idx = tid; idx < Dsz*8; idx += 256)
        wgs[idx >> 3][idx & 7] = wg[(idx >> 3) * Hsz + hg*8 + (idx & 7)];
    __syncthreads();

    int h = tid & 7, r = tid >> 3;
    int m = blockIdx.x * 32 + r;
    const float4* xr = (const float4*)(x + (size_t)m * Dsz);
    float s = 0.0f;
    #pragma unroll 4
    for (int d4 = 0; d4 < Dsz/4; d4++) {
        float4 xv = xr[d4];
        s = fmaf(xv.x, wgs[d4*4 + 0][h], s);
        s = fmaf(xv.y, wgs[d4*4 + 1][h], s);
        s = fmaf(xv.z, wgs[d4*4 + 2][h], s);
        s = fmaf(xv.w, wgs[d4*4 + 3][h], s);
    }
    s += bg[hg*8 + h];
    gate[(size_t)m * Hsz + hg*8 + h] = 1.0f / (1.0f + __expf(-s));
}

// ---------------- tensor-core flash attention (bf16, 128-q tile, 8 warps) ------
#define FPAD 72
#define KV_STRIDE (64*FPAD)            // elems per [64][72] K or V buffer
#define Q_STRIDE  (128*FPAD)           // Q region [128][72]
#define KV_STAGE  (2*KV_STRIDE)        // K + V per stage
#define FLASH_SMEM (Q_STRIDE*2 + 2*KV_STAGE*2 + 2*64*4)   // 18432+36864+512 = 55808

__global__ __launch_bounds__(256, 2)
void flash_tc_kernel(const bf16* __restrict__ Qh,
                     const bf16* __restrict__ Kh,
                     const bf16* __restrict__ Vh,
                     const float* __restrict__ gate, const int* __restrict__ mask,
                     bf16* __restrict__ Ch)
{
    extern __shared__ __align__(16) char dynsmem[];
    const uint32_t qbase = (uint32_t)__cvta_generic_to_shared(dynsmem);
    const uint32_t kvbase = qbase + Q_STRIDE*2;
    const uint32_t mbase = kvbase + 2*KV_STAGE*2;
    int* smsk = (int*)(dynsmem + (size_t)Q_STRIDE*2 + (size_t)2*KV_STAGE*2);

    const int tid = threadIdx.x, lane = tid & 31, warp = tid >> 5;
    const int qt = blockIdx.x, h = blockIdx.y, b = blockIdx.z;
    const size_t rowbase = (size_t)b * Ssz;
    const size_t hoff = (size_t)h * DKsz;

    // stage Q (128 rows x 64 cols)
    {
        int r = tid >> 1;
        size_t gq = (rowbase + qt*128 + r) * Dsz + hoff;
        #pragma unroll
        for (int j = 0; j < 4; j++) {
            int c8 = (tid & 1)*4 + j;
            uint32_t dof = (uint32_t)((r*FPAD + c8*8)*2);
            cp16(qbase + dof, Qh + gq + c8*8);
        }
        cp_commit(); cp_wait0();
    }
    __syncthreads();

    uint32_t qfh[4][4];
    {
        uint32_t arow = (uint32_t)((warp*16 + (lane&15))*FPAD*2);
        #pragma unroll
        for (int ks = 0; ks < 4; ks++) {
            uint32_t acol = (uint32_t)((16*ks + (lane>>4)*8)*2);
            ldsm4(qfh[ks], qbase + arow + acol);
        }
    }
    __syncthreads();

    float oacc[8][4];
    #pragma unroll
    for (int i = 0; i < 8; i++)
        #pragma unroll
        for (int j = 0; j < 4; j++) oacc[i][j] = 0.0f;
    float m0 = -1e30f, m1 = -1e30f, l0 = 0.0f, l1 = 0.0f;

    // K/V loader: 256 threads, 2 cp16 each per K and V buffer
    const int r_ld = tid >> 2;           // 0..63
    const int cbase = (tid & 3)*2;       // 0,2,4,6

    {
        size_t g = (rowbase + r_ld) * Dsz + hoff;
        #pragma unroll
        for (int j = 0; j < 2; j++) {
            int c8 = cbase + j;
            uint32_t dof = (uint32_t)((r_ld*FPAD + c8*8)*2);
            cp16(kvbase + dof, Kh + g + c8*8);
            cp16(kvbase + KV_STRIDE*2 + dof, Vh + g + c8*8);
        }
        if (tid < 16) cp16(mbase + tid*16, mask + rowbase + tid*4);
        cp_commit();
    }

    const int col0 = 2*(lane & 3);

    for (int kt = 0; kt < Ssz/64; kt++) {
        cp_wait0();
        __syncthreads();
        if (kt + 1 < Ssz/64) {
            int st = (kt + 1) & 1;
            size_t g = (rowbase + (kt+1)*64 + r_ld) * Dsz + hoff;
            uint32_t sb = kvbase + (uint32_t)(st*KV_STAGE*2);
            #pragma unroll
            for (int j = 0; j < 2; j++) {
                int c8 = cbase + j;
                uint32_t dof = (uint32_t)((r_ld*FPAD + c8*8)*2);
                cp16(sb + dof, Kh + g + c8*8);
                cp16(sb + KV_STRIDE*2 + dof, Vh + g + c8*8);
            }
            if (tid < 16) cp16(mbase + st*256 + tid*16, mask + rowbase + (kt+1)*64 + tid*4);
            cp_commit();
        }
        const int st = kt & 1;
        const uint32_t kb = kvbase + (uint32_t)(st*KV_STAGE*2);

        // ---- S = Q K^T ----
        float sc[8][4];
        #pragma unroll
        for (int i = 0; i < 8; i++)
            #pragma unroll
            for (int j = 0; j < 4; j++) sc[i][j] = 0.0f;

        const uint32_t brow = (uint32_t)(((lane&7) + ((lane>>1)&8)) * FPAD * 2);
        const uint32_t bcol = (uint32_t)((lane & 8) * 2);
        #pragma unroll
        for (int ng = 0; ng < 4; ng++) {
            #pragma unroll
            for (int ks = 0; ks < 4; ks++) {
                uint32_t ba = kb + brow + (uint32_t)(16*ng*FPAD*2) + bcol + (uint32_t)(16*ks*2);
                uint32_t bh4[4];
                ldsm4(bh4, ba);
                mma16816(sc[2*ng],   qfh[ks], bh4[0], bh4[1]);
                mma16816(sc[2*ng+1], qfh[ks], bh4[2], bh4[3]);
            }
        }

        // ---- online softmax ----
        const int* mk = smsk + st*64;
        float mx0 = -1e30f, mx1 = -1e30f;
        #pragma unroll
        for (int ni = 0; ni < 8; ni++) {
            int c = 8*ni + col0;
            bool z0 = (mk[c] == 0), z1 = (mk[c+1] == 0);
            sc[ni][0] = z0 ? -1e9f : sc[ni][0]*0.125f;
            sc[ni][1] = z1 ? -1e9f : sc[ni][1]*0.125f;
            sc[ni][2] = z0 ? -1e9f : sc[ni][2]*0.125f;
            sc[ni][3] = z1 ? -1e9f : sc[ni][3]*0.125f;
            mx0 = fmaxf(mx0, fmaxf(sc[ni][0], sc[ni][1]));
            mx1 = fmaxf(mx1, fmaxf(sc[ni][2], sc[ni][3]));
        }
        mx0 = fmaxf(mx0, __shfl_xor_sync(0xffffffffu, mx0, 1));
        mx0 = fmaxf(mx0, __shfl_xor_sync(0xffffffffu, mx0, 2));
        mx1 = fmaxf(mx1, __shfl_xor_sync(0xffffffffu, mx1, 1));
        mx1 = fmaxf(mx1, __shfl_xor_sync(0xffffffffu, mx1, 2));
        float mn0 = fmaxf(m0, mx0), mn1 = fmaxf(m1, mx1);
        float al0 = __expf(m0 - mn0), al1 = __expf(m1 - mn1);
        float rs0 = 0.0f, rs1 = 0.0f;
        #pragma unroll
        for (int ni = 0; ni < 8; ni++) {
            sc[ni][0] = __expf(sc[ni][0] - mn0);
            sc[ni][1] = __expf(sc[ni][1] - mn0);
            sc[ni][2] = __expf(sc[ni][2] - mn1);
            sc[ni][3] = __expf(sc[ni][3] - mn1);
            rs0 += sc[ni][0] + sc[ni][1];
            rs1 += sc[ni][2] + sc[ni][3];
        }
        rs0 += __shfl_xor_sync(0xffffffffu, rs0, 1);
        rs0 += __shfl_xor_sync(0xffffffffu, rs0, 2);
        rs1 += __shfl_xor_sync(0xffffffffu, rs1, 1);
        rs1 += __shfl_xor_sync(0xffffffffu, rs1, 2);
        l0 = l0*al0 + rs0; l1 = l1*al1 + rs1;
        m0 = mn0; m1 = mn1;
        #pragma unroll
        for (int ni = 0; ni < 8; ni++) {
            oacc[ni][0] *= al0; oacc[ni][1] *= al0;
            oacc[ni][2] *= al1; oacc[ni][3] *= al1;
        }

        // ---- O += P V ----
        const uint32_t vrow0 = (uint32_t)((lane&15)*FPAD*2);
        const uint32_t vcol0 = (uint32_t)(((lane>>4)*8)*2);
        #pragma unroll
        for (int ki = 0; ki < 4; ki++) {
            uint32_t ph[4];
            ph[0] = pack_hi(sc[2*ki][0],   sc[2*ki][1]);
            ph[1] = pack_hi(sc[2*ki][2],   sc[2*ki][3]);
            ph[2] = pack_hi(sc[2*ki+1][0], sc[2*ki+1][1]);
            ph[3] = pack_hi(sc[2*ki+1][2], sc[2*ki+1][3]);
            uint32_t va0 = kb + KV_STRIDE*2 + vrow0 + (uint32_t)(16*ki*FPAD*2) + vcol0;
            #pragma unroll
            for (int ngd = 0; ngd < 4; ngd++) {
                uint32_t vh4[4];
                ldsm4t(vh4[0], vh4[1], vh4[2], vh4[3], va0 + (uint32_t)(16*ngd*2));
                mma16816(oacc[2*ngd],   ph, vh4[0], vh4[1]);
                mma16816(oacc[2*ngd+1], ph, vh4[2], vh4[3]);
            }
        }
    }

    int q0 = qt*128 + warp*16 + (lane >> 2);
    float f0 = gate[(rowbase + q0)*Hsz + h] / l0;
    float f1 = gate[(rowbase + q0 + 8)*Hsz + h] / l1;
    #pragma unroll
    for (int ni = 0; ni < 8; ni++) {
        size_t o0 = (rowbase + q0) * Dsz + hoff + 8*ni + col0;
        size_t o1 = o0 + (size_t)8 * Dsz;
        *(uint32_t*)&Ch[o0] = pack_hi(oacc[ni][0]*f0, oacc[ni][1]*f0);
        *(uint32_t*)&Ch[o1] = pack_hi(oacc[ni][2]*f1, oacc[ni][3]*f1);
    }
}

// ---------------- fused residual add + LayerNorm (+ optional bf16 split out) ----
__global__ __launch_bounds__(256)
void add_ln_kernel(const float* __restrict__ a, const float* __restrict__ bsrc,
                   const float* __restrict__ g, const float* __restrict__ beta,
                   float* __restrict__ out, bf16* __restrict__ oh, bf16* __restrict__ ol)
{
    int row = blockIdx.x;
    int tid = threadIdx.x;
    __shared__ float buf[Dsz];
    __shared__ float rsum[8], rsq[8];

    size_t base = (size_t)row * Dsz;
    float ls = 0.0f, lq = 0.0f;
    for (int d = tid; d < Dsz; d += 256) {
        float v = a[base + d] + bsrc[base + d];
        buf[d] = v;
        ls += v; lq += v * v;
    }
    int warp = tid >> 5, lane = tid & 31;
    for (int off = 16; off; off >>= 1) {
        ls += __shfl_xor_sync(0xffffffffu, ls, off);
        lq += __shfl_xor_sync(0xffffffffu, lq, off);
    }
    if (lane == 0) { rsum[warp] = ls; rsq[warp] = lq; }
    __syncthreads();
    float ts = 0.0f, tq = 0.0f;
    #pragma unroll
    for (int w = 0; w < 8; w++) { ts += rsum[w]; tq += rsq[w]; }
    float mean = ts * (1.0f / Dsz);
    float var  = tq * (1.0f / Dsz) - mean * mean;
    float rstd = rsqrtf(var + 1e-5f);
    for (int d = tid; d < Dsz; d += 256) {
        float v = (buf[d] - mean) * rstd * g[d] + beta[d];
        out[base + d] = v;
        if (oh) {
            bf16 hv = __float2bfloat16(v);
            oh[base + d] = hv;
            ol[base + d] = __float2bfloat16(v - __bfloat162float(hv));
        }
    }
}

// ---------------- launch ----------------
extern "C" void kernel_launch(void* const* d_in, const int* in_sizes, int n_in,
                              void* d_out, int out_size)
{
    const float* x     = (const float*)d_in[0];
    const float* w_q   = (const float*)d_in[1];
    const float* b_q   = (const float*)d_in[2];
    const float* w_k   = (const float*)d_in[3];
    const float* b_k   = (const float*)d_in[4];
    const float* w_v   = (const float*)d_in[5];
    const float* b_v   = (const float*)d_in[6];
    const float* w_o   = (const float*)d_in[7];
    const float* b_o   = (const float*)d_in[8];
    const float* w_g   = (const float*)d_in[9];
    const float* b_g   = (const float*)d_in[10];
    const float* w1    = (const float*)d_in[11];
    const float* b1    = (const float*)d_in[12];
    const float* w2    = (const float*)d_in[13];
    const float* b2    = (const float*)d_in[14];
    const float* g1    = (const float*)d_in[15];
    const float* beta1 = (const float*)d_in[16];
    const float* g2    = (const float*)d_in[17];
    const float* beta2 = (const float*)d_in[18];
    const int*   mask  = (const int*)  d_in[19];
    float* out = (float*)d_out;

    float *tmp, *x1, *gate;
    cudaGetSymbolAddress((void**)&tmp,  g_tmp);
    cudaGetSymbolAddress((void**)&x1,   g_x1);
    cudaGetSymbolAddress((void**)&gate, g_gate);

    bf16 *xh,*xl,*qh,*kh,*vh,*ctxh,*x1h,*x1l,*ffh,*ffl;
    bf16 *wqh,*wql,*wkh,*wkl,*wvh,*wvl,*woh,*wol,*w1h,*w1l,*w2h,*w2l;
    cudaGetSymbolAddress((void**)&xh,  g_xh);   cudaGetSymbolAddress((void**)&xl,  g_xl);
    cudaGetSymbolAddress((void**)&qh,  g_qh);
    cudaGetSymbolAddress((void**)&kh,  g_kh);
    cudaGetSymbolAddress((void**)&vh,  g_vh);
    cudaGetSymbolAddress((void**)&ctxh,g_ctxh);
    cudaGetSymbolAddress((void**)&x1h, g_x1h);  cudaGetSymbolAddress((void**)&x1l, g_x1l);
    cudaGetSymbolAddress((void**)&ffh, g_ffh);  cudaGetSymbolAddress((void**)&ffl, g_ffl);
    cudaGetSymbolAddress((void**)&wqh, g_wqh);  cudaGetSymbolAddress((void**)&wql, g_wql);
    cudaGetSymbolAddress((void**)&wkh, g_wkh);  cudaGetSymbolAddress((void**)&wkl, g_wkl);
    cudaGetSymbolAddress((void**)&wvh, g_wvh);  cudaGetSymbolAddress((void**)&wvl, g_wvl);
    cudaGetSymbolAddress((void**)&woh, g_woh);  cudaGetSymbolAddress((void**)&wol, g_wol);
    cudaGetSymbolAddress((void**)&w1h, g_w1h);  cudaGetSymbolAddress((void**)&w1l, g_w1l);
    cudaGetSymbolAddress((void**)&w2h, g_w2h);  cudaGetSymbolAddress((void**)&w2l, g_w2l);

    cudaFuncSetAttribute(flash_tc_kernel,
                         cudaFuncAttributeMaxDynamicSharedMemorySize, FLASH_SMEM);
    cudaFuncSetAttribute(gemm_bf16x3_kernel,
                         cudaFuncAttributeMaxDynamicSharedMemorySize, GEMM_SMEM);
    cudaFuncSetAttribute(gemm_bf16x1_kernel,
                         cudaFuncAttributeMaxDynamicSharedMemorySize, GEMM_SMEM1);
    cudaFuncSetAttribute(qkv_gemm_kernel,
                         cudaFuncAttributeMaxDynamicSharedMemorySize, GEMM_SMEM1);

    // 0: split x
    split_x_kernel<<<Msz*Dsz/(4*256), 256>>>(x, xh, xl);

    // 1: split weights
    SplitWArgs sw;
    sw.src[0] = w_q; sw.hi[0] = wqh; sw.lo[0] = wql;
    sw.src[1] = w_k; sw.hi[1] = wkh; sw.lo[1] = wkl;
    sw.src[2] = w_v; sw.hi[2] = wvh; sw.lo[2] = wvl;
    sw.src[3] = w_o; sw.hi[3] = woh; sw.lo[3] = wol;
    sw.src[4] = w1;  sw.hi[4] = w1h; sw.lo[4] = w1l;
    sw.src[5] = w2;  sw.hi[5] = w2h; sw.lo[5] = w2l;
    split_w_kernel<<<12288, 256>>>(sw);

    // 2: gate
    gate_kernel<<<dim3(Msz/32, 2), 256>>>(x, w_g, b_g, gate);

    // 3: merged QKV GEMM (1-term) <- profiled slot (process launch 5)
    QKVArgs qa;
    qa.Wh[0] = wqh; qa.bias[0] = b_q; qa.Ch[0] = qh;
    qa.Wh[1] = wkh; qa.bias[1] = b_k; qa.Ch[1] = kh;
    qa.Wh[2] = wvh; qa.bias[2] = b_v; qa.Ch[2] = vh;
    qkv_gemm_kernel<<<dim3(Dsz/128, Msz/128, 3), 256, GEMM_SMEM1>>>(xh, qa);

    // 4: flash attention (bf16, 128-q tile)
    flash_tc_kernel<<<dim3(Ssz/128, Hsz, Bsz), 256, FLASH_SMEM>>>(
        qh, kh, vh, gate, mask, ctxh);

    dim3 gSq(Dsz/128, Msz/128);      // (8, 64)
    dim3 gF1(DFFsz/128, Msz/128);    // (32, 64)

    // 5: O-proj (1-term)
    gemm_bf16x1_kernel<<<gSq, 256, GEMM_SMEM1>>>(ctxh, woh, b_o, tmp, nullptr, Dsz, Dsz, 2);
    // 6: LN1
    add_ln_kernel<<<Msz, 256>>>(x, tmp, g1, beta1, x1, x1h, x1l);
    // 7: FF1 (3-term, GELU)
    gemm_bf16x3_kernel<<<gF1, 256, GEMM_SMEM>>>(x1h, x1l, w1h, w1l, b1, nullptr, ffh, ffl, DFFsz, Dsz, 5);
    // 8: FF2 (3-term)
    gemm_bf16x3_kernel<<<gSq, 256, GEMM_SMEM>>>(ffh, ffl, w2h, w2l, b2, tmp, nullptr, nullptr, Dsz, DFFsz, 2);
    // 9: LN2
    add_ln_kernel<<<Msz, 256>>>(x1, tmp, g2, beta2, out, nullptr, nullptr);
}

// round 13
// speedup vs baseline: 1.7615x; 1.1050x over previous
#include <cuda_runtime.h>
#include <cuda_bf16.h>
#include <math.h>
#include <cstdint>

// Problem constants
#define Bsz   4
#define Ssz   2048
#define Dsz   1024
#define Hsz   16
#define DKsz  64
#define DFFsz 4096
#define Msz   (Bsz*Ssz)   // 8192 rows

typedef __nv_bfloat16 bf16;

// ---------------- scratch (static device globals; no allocation) ----------------
__device__ float g_tmp [(size_t)Msz*Dsz];
__device__ float g_x1  [(size_t)Msz*Dsz];
__device__ float g_gate[(size_t)Msz*Hsz];

__device__ bf16 g_xh [(size_t)Msz*Dsz],   g_xl [(size_t)Msz*Dsz];
__device__ bf16 g_qh [(size_t)Msz*Dsz];
__device__ bf16 g_kh [(size_t)Msz*Dsz];
__device__ bf16 g_vh [(size_t)Msz*Dsz];
__device__ bf16 g_ctxh[(size_t)Msz*Dsz];
__device__ bf16 g_x1h[(size_t)Msz*Dsz],   g_x1l[(size_t)Msz*Dsz];
__device__ bf16 g_ffh[(size_t)Msz*DFFsz], g_ffl[(size_t)Msz*DFFsz];
__device__ bf16 g_wqh[(size_t)Dsz*Dsz],   g_wql[(size_t)Dsz*Dsz];
__device__ bf16 g_wkh[(size_t)Dsz*Dsz],   g_wkl[(size_t)Dsz*Dsz];
__device__ bf16 g_wvh[(size_t)Dsz*Dsz],   g_wvl[(size_t)Dsz*Dsz];
__device__ bf16 g_woh[(size_t)Dsz*Dsz],   g_wol[(size_t)Dsz*Dsz];
__device__ bf16 g_w1h[(size_t)Dsz*DFFsz], g_w1l[(size_t)Dsz*DFFsz];
__device__ bf16 g_w2h[(size_t)DFFsz*Dsz], g_w2l[(size_t)DFFsz*Dsz];

// ---------------- small helpers ----------------
__device__ __forceinline__ void cp16(uint32_t dst, const void* src) {
    asm volatile("cp.async.ca.shared.global [%0], [%1], 16;\n" :: "r"(dst), "l"(src));
}
__device__ __forceinline__ void cp_commit() {
    asm volatile("cp.async.commit_group;\n");
}
__device__ __forceinline__ void cp_wait0() {
    asm volatile("cp.async.wait_group 0;\n");
}
__device__ __forceinline__ void cp_wait1() {
    asm volatile("cp.async.wait_group 1;\n");
}
__device__ __forceinline__ void cp_wait2() {
    asm volatile("cp.async.wait_group 2;\n");
}
__device__ __forceinline__ void ldsm4(uint32_t* r, uint32_t addr) {
    asm volatile("ldmatrix.sync.aligned.m8n8.x4.shared.b16 {%0,%1,%2,%3}, [%4];"
                 : "=r"(r[0]), "=r"(r[1]), "=r"(r[2]), "=r"(r[3]) : "r"(addr));
}
__device__ __forceinline__ void ldsm4t(uint32_t& r0, uint32_t& r1,
                                       uint32_t& r2, uint32_t& r3, uint32_t addr) {
    asm volatile("ldmatrix.sync.aligned.m8n8.x4.trans.shared.b16 {%0,%1,%2,%3}, [%4];"
                 : "=r"(r0), "=r"(r1), "=r"(r2), "=r"(r3) : "r"(addr));
}
__device__ __forceinline__ void mma16816(float* ac, const uint32_t* a,
                                         uint32_t b0, uint32_t b1) {
    asm volatile(
        "mma.sync.aligned.m16n8k16.row.col.f32.bf16.bf16.f32 "
        "{%0,%1,%2,%3},{%4,%5,%6,%7},{%8,%9},{%0,%1,%2,%3};"
        : "+f"(ac[0]), "+f"(ac[1]), "+f"(ac[2]), "+f"(ac[3])
        : "r"(a[0]), "r"(a[1]), "r"(a[2]), "r"(a[3]), "r"(b0), "r"(b1));
}
__device__ __forceinline__ void pack_pair(float a, float b, uint32_t& hi, uint32_t& lo) {
    bf16 ha = __float2bfloat16(a), hb = __float2bfloat16(b);
    bf16 la = __float2bfloat16(a - __bfloat162float(ha));
    bf16 lb = __float2bfloat16(b - __bfloat162float(hb));
    __nv_bfloat162 th = __halves2bfloat162(ha, hb);
    __nv_bfloat162 tl = __halves2bfloat162(la, lb);
    hi = *(uint32_t*)&th; lo = *(uint32_t*)&tl;
}
__device__ __forceinline__ uint32_t pack_hi(float a, float b) {
    __nv_bfloat162 th = __halves2bfloat162(__float2bfloat16(a), __float2bfloat16(b));
    return *(uint32_t*)&th;
}

// ---------------- splits ----------------
__global__ __launch_bounds__(256)
void split_x_kernel(const float* __restrict__ in, bf16* __restrict__ hi,
                    bf16* __restrict__ lo)
{
    size_t i = (size_t)blockIdx.x * 256 + threadIdx.x;
    float4 v = ((const float4*)in)[i];
    uint32_t h0, l0, h1, l1;
    pack_pair(v.x, v.y, h0, l0);
    pack_pair(v.z, v.w, h1, l1);
    ((uint32_t*)hi)[2*i] = h0; ((uint32_t*)hi)[2*i+1] = h1;
    ((uint32_t*)lo)[2*i] = l0; ((uint32_t*)lo)[2*i+1] = l1;
}

struct SplitWArgs {
    const float* src[6];
    bf16* hi[6];
    bf16* lo[6];
};
__global__ __launch_bounds__(256)
void split_w_kernel(SplitWArgs a)
{
    int bid = blockIdx.x;
    int seg, base;
    if      (bid < 1024)  { seg = 0; base = 0; }
    else if (bid < 2048)  { seg = 1; base = 1024; }
    else if (bid < 3072)  { seg = 2; base = 2048; }
    else if (bid < 4096)  { seg = 3; base = 3072; }
    else if (bid < 8192)  { seg = 4; base = 4096; }
    else                  { seg = 5; base = 8192; }
    size_t i = (size_t)(bid - base) * 256 + threadIdx.x;
    float4 v = ((const float4*)a.src[seg])[i];
    uint32_t h0, l0, h1, l1;
    pack_pair(v.x, v.y, h0, l0);
    pack_pair(v.z, v.w, h1, l1);
    uint32_t* hp = (uint32_t*)a.hi[seg];
    uint32_t* lp = (uint32_t*)a.lo[seg];
    hp[2*i] = h0; hp[2*i+1] = h1;
    lp[2*i] = l0; lp[2*i+1] = l1;
}

// ---------------- bf16 tensor-core GEMM core (4-stage cp.async) ----------
// BM=128, BN=256, BK=16, 256 threads = 8 warps (2 M x 4 N), warp tile 64x64.
// TERMS=3: acc = Ah*Wh + Al*Wh + Ah*Wl.  TERMS=1: acc = Ah*Wh.
// mode bits: 1=GELU, 2=write fp32 C, 4=write bf16 Ch/Cl, 8=write bf16 Ch only
#define APAD 24   // 16 + 8 bf16 pad
#define WPAD 264  // 256 + 8 pad (528B stride; 528 mod 128 = 16 -> conflict-free)
#define NSTG 4
#define SA_B (128*APAD*2)   // 6144 B per A stage buffer
#define SW_B (16*WPAD*2)    // 8448 B per W stage buffer
#define GEMM_SMEM  (NSTG*(2*SA_B + 2*SW_B))   // 116736 (TERMS=3)
#define GEMM_SMEM1 (NSTG*(SA_B + SW_B))       // 58368  (TERMS=1)

template<int TERMS>
__device__ __forceinline__
void gemm_core(const bf16* __restrict__ Ah, const bf16* __restrict__ Al,
               const bf16* __restrict__ Wh, const bf16* __restrict__ Wl,
               const float* __restrict__ bias, float* __restrict__ C,
               bf16* __restrict__ Ch, bf16* __restrict__ Cl,
               int N, int K, int mode, int row0, int col0)
{
    extern __shared__ __align__(16) char gdsm[];
    const uint32_t aAh = (uint32_t)__cvta_generic_to_shared(gdsm);
    const uint32_t aAl = aAh + NSTG*SA_B;
    const uint32_t aWh = (TERMS == 3) ? (aAl + NSTG*SA_B) : (aAh + NSTG*SA_B);
    const uint32_t aWl = aWh + NSTG*SW_B;

    const int tid = threadIdx.x;

    // A: 128 rows x 16 cols; 256 chunks of 8 elems; 1 per thread
    const char* pAh = (const char*)(Ah + (size_t)(row0 + (tid>>1)) * K + (tid&1)*8);
    const char* pAl = (TERMS == 3) ? (const char*)(Al + (size_t)(row0 + (tid>>1)) * K + (tid&1)*8) : nullptr;
    // W: 16 rows x 256 cols; 512 chunks; 2 per thread (rows tid>>5 and tid>>5+8)
    const char* pWh = (const char*)(Wh + (size_t)(tid>>5) * N + col0 + (tid&31)*8);
    const char* pWl = (TERMS == 3) ? (const char*)(Wl + (size_t)(tid>>5) * N + col0 + (tid&31)*8) : nullptr;

    const uint32_t dA = ((tid>>1)*APAD + (tid&1)*8) * 2;
    const uint32_t dW = ((tid>>5)*WPAD + (tid&31)*8) * 2;
    const uint32_t dW2 = (uint32_t)(8*WPAD*2);   // +8 k-rows in smem
    const size_t  gW2 = (size_t)8 * N * 2;       // +8 k-rows in gmem

    float acc[4][8][4];
    #pragma unroll
    for (int i = 0; i < 4; i++)
        #pragma unroll
        for (int j = 0; j < 8; j++)
            #pragma unroll
            for (int t = 0; t < 4; t++) acc[i][j][t] = 0.0f;

    const int wid = tid >> 5, lane = tid & 31;
    const int wm = wid & 1;       // M offset wm*64
    const int wn = wid >> 1;      // N offset wn*64
    const int lrow = lane & 15, lk = (lane >> 4) * 8;
    const uint32_t offA0 = (uint32_t)(((wm*64 + lrow) * APAD + lk) * 2);
    const uint32_t offB0 = (uint32_t)(((lane & 15) * WPAD + wn*64 + (lane>>4)*8) * 2);

    const int nit = K / 16;

    auto load_stage = [&](int st, int it2) {
        size_t ka = (size_t)it2 * 16 * 2;
        size_t kw = (size_t)it2 * 16 * (size_t)N * 2;
        cp16(aAh + (uint32_t)st*SA_B + dA, pAh + ka);
        cp16(aWh + (uint32_t)st*SW_B + dW, pWh + kw);
        cp16(aWh + (uint32_t)st*SW_B + dW + dW2, pWh + kw + gW2);
        if (TERMS == 3) {
            cp16(aAl + (uint32_t)st*SA_B + dA, pAl + ka);
            cp16(aWl + (uint32_t)st*SW_B + dW, pWl + kw);
            cp16(aWl + (uint32_t)st*SW_B + dW + dW2, pWl + kw + gW2);
        }
        cp_commit();
    };

    load_stage(0, 0);
    load_stage(1, 1);
    load_stage(2, 2);

    for (int it = 0; it < nit; ++it) {
        int rem = nit - 1 - it;
        if (rem >= 2) cp_wait2();
        else if (rem == 1) cp_wait1();
        else cp_wait0();
        __syncthreads();
        if (it + 3 < nit)
            load_stage((it + 3) & 3, it + 3);
        const uint32_t s = (uint32_t)(it & 3);

        uint32_t afh[4][4];
        #pragma unroll
        for (int mi = 0; mi < 4; mi++)
            ldsm4(afh[mi], aAh + s*SA_B + offA0 + mi*16*APAD*2);

        uint32_t bfr[8][2];
        #pragma unroll
        for (int ng = 0; ng < 4; ng++)
            ldsm4t(bfr[2*ng][0], bfr[2*ng][1], bfr[2*ng+1][0], bfr[2*ng+1][1],
                   aWh + s*SW_B + offB0 + (uint32_t)(ng*16*2));

        if (TERMS == 3) {
            uint32_t afl[4][4];
            #pragma unroll
            for (int mi = 0; mi < 4; mi++)
                ldsm4(afl[mi], aAl + s*SA_B + offA0 + mi*16*APAD*2);
            #pragma unroll
            for (int mi = 0; mi < 4; mi++)
                #pragma unroll
                for (int ni = 0; ni < 8; ni++) {
                    mma16816(acc[mi][ni], afh[mi], bfr[ni][0], bfr[ni][1]);
                    mma16816(acc[mi][ni], afl[mi], bfr[ni][0], bfr[ni][1]);
                }
            #pragma unroll
            for (int ng = 0; ng < 4; ng++)
                ldsm4t(bfr[2*ng][0], bfr[2*ng][1], bfr[2*ng+1][0], bfr[2*ng+1][1],
                       aWl + s*SW_B + offB0 + (uint32_t)(ng*16*2));
            #pragma unroll
            for (int mi = 0; mi < 4; mi++)
                #pragma unroll
                for (int ni = 0; ni < 8; ni++)
                    mma16816(acc[mi][ni], afh[mi], bfr[ni][0], bfr[ni][1]);
        } else {
            #pragma unroll
            for (int mi = 0; mi < 4; mi++)
                #pragma unroll
                for (int ni = 0; ni < 8; ni++)
                    mma16816(acc[mi][ni], afh[mi], bfr[ni][0], bfr[ni][1]);
        }
    }

    #pragma unroll
    for (int mi = 0; mi < 4; mi++) {
        #pragma unroll
        for (int ni = 0; ni < 8; ni++) {
            int c = col0 + wn*64 + ni*8 + (lane & 3)*2;
            float bx = bias[c], by = bias[c + 1];
            #pragma unroll
            for (int rh = 0; rh < 2; rh++) {
                size_t r = (size_t)(row0 + wm*64 + mi*16 + (lane >> 2) + rh*8);
                float v0 = acc[mi][ni][2*rh]     + bx;
                float v1 = acc[mi][ni][2*rh + 1] + by;
                if (mode & 1) {
                    v0 = 0.5f * v0 * (1.0f + erff(v0 * 0.70710678118654752f));
                    v1 = 0.5f * v1 * (1.0f + erff(v1 * 0.70710678118654752f));
                }
                if (mode & 2) {
                    float2 o; o.x = v0; o.y = v1;
                    *(float2*)&C[r * N + c] = o;
                }
                if (mode & 4) {
                    uint32_t hp, lp;
                    pack_pair(v0, v1, hp, lp);
                    *(uint32_t*)&Ch[r * N + c] = hp;
                    *(uint32_t*)&Cl[r * N + c] = lp;
                }
                if (mode & 8) {
                    *(uint32_t*)&Ch[r * N + c] = pack_hi(v0, v1);
                }
            }
        }
    }
}

__global__ __launch_bounds__(256, 1)
void gemm_bf16x3_kernel(const bf16* __restrict__ Ah, const bf16* __restrict__ Al,
                        const bf16* __restrict__ Wh, const bf16* __restrict__ Wl,
                        const float* __restrict__ bias, float* __restrict__ C,
                        bf16* __restrict__ Ch, bf16* __restrict__ Cl,
                        int N, int K, int mode)
{
    gemm_core<3>(Ah, Al, Wh, Wl, bias, C, Ch, Cl, N, K, mode,
                 blockIdx.y * 128, blockIdx.x * 256);
}

__global__ __launch_bounds__(256, 1)
void gemm_bf16x1_kernel(const bf16* __restrict__ Ah,
                        const bf16* __restrict__ Wh,
                        const float* __restrict__ bias, float* __restrict__ C,
                        bf16* __restrict__ Ch,
                        int N, int K, int mode)
{
    gemm_core<1>(Ah, nullptr, Wh, nullptr, bias, C, Ch, nullptr, N, K, mode,
                 blockIdx.y * 128, blockIdx.x * 256);
}

// merged Q/K/V projection: blockIdx.z selects weight/output set; 1-term, hi-only out
struct QKVArgs {
    const bf16* Wh[3];
    const float* bias[3];
    bf16* Ch[3];
};
__global__ __launch_bounds__(256, 1)
void qkv_gemm_kernel(const bf16* __restrict__ Ah, QKVArgs a)
{
    int z = blockIdx.z;
    gemm_core<1>(Ah, nullptr, a.Wh[z], nullptr, a.bias[z], nullptr, a.Ch[z], nullptr,
                 Dsz, Dsz, 8, blockIdx.y * 128, blockIdx.x * 256);
}

// ---------------- sigmoid gate ----------------------
__global__ __launch_bounds__(256)
void gate_kernel(const float* __restrict__ x, const float* __restrict__ wg,
                 const float* __restrict__ bg, float* __restrict__ gate)
{
    __shared__ float wgs[Dsz][8];
    int hg = blockIdx.y;
    int tid = threadIdx.x;
    for (int idx = tid; idx < Dsz*8; idx += 256)
        wgs[idx >> 3][idx & 7] = wg[(idx >> 3) * Hsz + hg*8 + (idx & 7)];
    __syncthreads();

    int h = tid & 7, r = tid >> 3;
    int m = blockIdx.x * 32 + r;
    const float4* xr = (const float4*)(x + (size_t)m * Dsz);
    float s = 0.0f;
    #pragma unroll 4
    for (int d4 = 0; d4 < Dsz/4; d4++) {
        float4 xv = xr[d4];
        s = fmaf(xv.x, wgs[d4*4 + 0][h], s);
        s = fmaf(xv.y, wgs[d4*4 + 1][h], s);
        s = fmaf(xv.z, wgs[d4*4 + 2][h], s);
        s = fmaf(xv.w, wgs[d4*4 + 3][h], s);
    }
    s += bg[hg*8 + h];
    gate[(size_t)m * Hsz + hg*8 + h] = 1.0f / (1.0f + __expf(-s));
}

// ---------------- tensor-core flash attention (bf16, 128-q tile, 8 warps) ------
#define FPAD 72
#define KV_STRIDE (64*FPAD)
#define Q_STRIDE  (128*FPAD)
#define KV_STAGE  (2*KV_STRIDE)
#define FLASH_SMEM (Q_STRIDE*2 + 2*KV_STAGE*2 + 2*64*4)

__global__ __launch_bounds__(256, 2)
void flash_tc_kernel(const bf16* __restrict__ Qh,
                     const bf16* __restrict__ Kh,
                     const bf16* __restrict__ Vh,
                     const float* __restrict__ gate, const int* __restrict__ mask,
                     bf16* __restrict__ Ch)
{
    extern __shared__ __align__(16) char dynsmem[];
    const uint32_t qbase = (uint32_t)__cvta_generic_to_shared(dynsmem);
    const uint32_t kvbase = qbase + Q_STRIDE*2;
    const uint32_t mbase = kvbase + 2*KV_STAGE*2;
    int* smsk = (int*)(dynsmem + (size_t)Q_STRIDE*2 + (size_t)2*KV_STAGE*2);

    const int tid = threadIdx.x, lane = tid & 31, warp = tid >> 5;
    const int qt = blockIdx.x, h = blockIdx.y, b = blockIdx.z;
    const size_t rowbase = (size_t)b * Ssz;
    const size_t hoff = (size_t)h * DKsz;

    {
        int r = tid >> 1;
        size_t gq = (rowbase + qt*128 + r) * Dsz + hoff;
        #pragma unroll
        for (int j = 0; j < 4; j++) {
            int c8 = (tid & 1)*4 + j;
            uint32_t dof = (uint32_t)((r*FPAD + c8*8)*2);
            cp16(qbase + dof, Qh + gq + c8*8);
        }
        cp_commit(); cp_wait0();
    }
    __syncthreads();

    uint32_t qfh[4][4];
    {
        uint32_t arow = (uint32_t)((warp*16 + (lane&15))*FPAD*2);
        #pragma unroll
        for (int ks = 0; ks < 4; ks++) {
            uint32_t acol = (uint32_t)((16*ks + (lane>>4)*8)*2);
            ldsm4(qfh[ks], qbase + arow + acol);
        }
    }
    __syncthreads();

    float oacc[8][4];
    #pragma unroll
    for (int i = 0; i < 8; i++)
        #pragma unroll
        for (int j = 0; j < 4; j++) oacc[i][j] = 0.0f;
    float m0 = -1e30f, m1 = -1e30f, l0 = 0.0f, l1 = 0.0f;

    const int r_ld = tid >> 2;
    const int cbase = (tid & 3)*2;

    {
        size_t g = (rowbase + r_ld) * Dsz + hoff;
        #pragma unroll
        for (int j = 0; j < 2; j++) {
            int c8 = cbase + j;
            uint32_t dof = (uint32_t)((r_ld*FPAD + c8*8)*2);
            cp16(kvbase + dof, Kh + g + c8*8);
            cp16(kvbase + KV_STRIDE*2 + dof, Vh + g + c8*8);
        }
        if (tid < 16) cp16(mbase + tid*16, mask + rowbase + tid*4);
        cp_commit();
    }

    const int col0 = 2*(lane & 3);

    for (int kt = 0; kt < Ssz/64; kt++) {
        cp_wait0();
        __syncthreads();
        if (kt + 1 < Ssz/64) {
            int st = (kt + 1) & 1;
            size_t g = (rowbase + (kt+1)*64 + r_ld) * Dsz + hoff;
            uint32_t sb = kvbase + (uint32_t)(st*KV_STAGE*2);
            #pragma unroll
            for (int j = 0; j < 2; j++) {
                int c8 = cbase + j;
                uint32_t dof = (uint32_t)((r_ld*FPAD + c8*8)*2);
                cp16(sb + dof, Kh + g + c8*8);
                cp16(sb + KV_STRIDE*2 + dof, Vh + g + c8*8);
            }
            if (tid < 16) cp16(mbase + st*256 + tid*16, mask + rowbase + (kt+1)*64 + tid*4);
            cp_commit();
        }
        const int st = kt & 1;
        const uint32_t kb = kvbase + (uint32_t)(st*KV_STAGE*2);

        float sc[8][4];
        #pragma unroll
        for (int i = 0; i < 8; i++)
            #pragma unroll
            for (int j = 0; j < 4; j++) sc[i][j] = 0.0f;

        const uint32_t brow = (uint32_t)(((lane&7) + ((lane>>1)&8)) * FPAD * 2);
        const uint32_t bcol = (uint32_t)((lane & 8) * 2);
        #pragma unroll
        for (int ng = 0; ng < 4; ng++) {
            #pragma unroll
            for (int ks = 0; ks < 4; ks++) {
                uint32_t ba = kb + brow + (uint32_t)(16*ng*FPAD*2) + bcol + (uint32_t)(16*ks*2);
                uint32_t bh4[4];
                ldsm4(bh4, ba);
                mma16816(sc[2*ng],   qfh[ks], bh4[0], bh4[1]);
                mma16816(sc[2*ng+1], qfh[ks], bh4[2], bh4[3]);
            }
        }

        const int* mk = smsk + st*64;
        float mx0 = -1e30f, mx1 = -1e30f;
        #pragma unroll
        for (int ni = 0; ni < 8; ni++) {
            int c = 8*ni + col0;
            bool z0 = (mk[c] == 0), z1 = (mk[c+1] == 0);
            sc[ni][0] = z0 ? -1e9f : sc[ni][0]*0.125f;
            sc[ni][1] = z1 ? -1e9f : sc[ni][1]*0.125f;
            sc[ni][2] = z0 ? -1e9f : sc[ni][2]*0.125f;
            sc[ni][3] = z1 ? -1e9f : sc[ni][3]*0.125f;
            mx0 = fmaxf(mx0, fmaxf(sc[ni][0], sc[ni][1]));
            mx1 = fmaxf(mx1, fmaxf(sc[ni][2], sc[ni][3]));
        }
        mx0 = fmaxf(mx0, __shfl_xor_sync(0xffffffffu, mx0, 1));
        mx0 = fmaxf(mx0, __shfl_xor_sync(0xffffffffu, mx0, 2));
        mx1 = fmaxf(mx1, __shfl_xor_sync(0xffffffffu, mx1, 1));
        mx1 = fmaxf(mx1, __shfl_xor_sync(0xffffffffu, mx1, 2));
        float mn0 = fmaxf(m0, mx0), mn1 = fmaxf(m1, mx1);
        float al0 = __expf(m0 - mn0), al1 = __expf(m1 - mn1);
        float rs0 = 0.0f, rs1 = 0.0f;
        #pragma unroll
        for (int ni = 0; ni < 8; ni++) {
            sc[ni][0] = __expf(sc[ni][0] - mn0);
            sc[ni][1] = __expf(sc[ni][1] - mn0);
            sc[ni][2] = __expf(sc[ni][2] - mn1);
            sc[ni][3] = __expf(sc[ni][3] - mn1);
            rs0 += sc[ni][0] + sc[ni][1];
            rs1 += sc[ni][2] + sc[ni][3];
        }
        rs0 += __shfl_xor_sync(0xffffffffu, rs0, 1);
        rs0 += __shfl_xor_sync(0xffffffffu, rs0, 2);
        rs1 += __shfl_xor_sync(0xffffffffu, rs1, 1);
        rs1 += __shfl_xor_sync(0xffffffffu, rs1, 2);
        l0 = l0*al0 + rs0; l1 = l1*al1 + rs1;
        m0 = mn0; m1 = mn1;
        #pragma unroll
        for (int ni = 0; ni < 8; ni++) {
            oacc[ni][0] *= al0; oacc[ni][1] *= al0;
            oacc[ni][2] *= al1; oacc[ni][3] *= al1;
        }

        const uint32_t vrow0 = (uint32_t)((lane&15)*FPAD*2);
        const uint32_t vcol0 = (uint32_t)(((lane>>4)*8)*2);
        #pragma unroll
        for (int ki = 0; ki < 4; ki++) {
            uint32_t ph[4];
            ph[0] = pack_hi(sc[2*ki][0],   sc[2*ki][1]);
            ph[1] = pack_hi(sc[2*ki][2],   sc[2*ki][3]);
            ph[2] = pack_hi(sc[2*ki+1][0], sc[2*ki+1][1]);
            ph[3] = pack_hi(sc[2*ki+1][2], sc[2*ki+1][3]);
            uint32_t va0 = kb + KV_STRIDE*2 + vrow0 + (uint32_t)(16*ki*FPAD*2) + vcol0;
            #pragma unroll
            for (int ngd = 0; ngd < 4; ngd++) {
                uint32_t vh4[4];
                ldsm4t(vh4[0], vh4[1], vh4[2], vh4[3], va0 + (uint32_t)(16*ngd*2));
                mma16816(oacc[2*ngd],   ph, vh4[0], vh4[1]);
                mma16816(oacc[2*ngd+1], ph, vh4[2], vh4[3]);
            }
        }
    }

    int q0 = qt*128 + warp*16 + (lane >> 2);
    float f0 = gate[(rowbase + q0)*Hsz + h] / l0;
    float f1 = gate[(rowbase + q0 + 8)*Hsz + h] / l1;
    #pragma unroll
    for (int ni = 0; ni < 8; ni++) {
        size_t o0 = (rowbase + q0) * Dsz + hoff + 8*ni + col0;
        size_t o1 = o0 + (size_t)8 * Dsz;
        *(uint32_t*)&Ch[o0] = pack_hi(oacc[ni][0]*f0, oacc[ni][1]*f0);
        *(uint32_t*)&Ch[o1] = pack_hi(oacc[ni][2]*f1, oacc[ni][3]*f1);
    }
}

// ---------------- fused residual add + LayerNorm (+ optional bf16 split out) ----
__global__ __launch_bounds__(256)
void add_ln_kernel(const float* __restrict__ a, const float* __restrict__ bsrc,
                   const float* __restrict__ g, const float* __restrict__ beta,
                   float* __restrict__ out, bf16* __restrict__ oh, bf16* __restrict__ ol)
{
    int row = blockIdx.x;
    int tid = threadIdx.x;
    __shared__ float buf[Dsz];
    __shared__ float rsum[8], rsq[8];

    size_t base = (size_t)row * Dsz;
    float ls = 0.0f, lq = 0.0f;
    for (int d = tid; d < Dsz; d += 256) {
        float v = a[base + d] + bsrc[base + d];
        buf[d] = v;
        ls += v; lq += v * v;
    }
    int warp = tid >> 5, lane = tid & 31;
    for (int off = 16; off; off >>= 1) {
        ls += __shfl_xor_sync(0xffffffffu, ls, off);
        lq += __shfl_xor_sync(0xffffffffu, lq, off);
    }
    if (lane == 0) { rsum[warp] = ls; rsq[warp] = lq; }
    __syncthreads();
    float ts = 0.0f, tq = 0.0f;
    #pragma unroll
    for (int w = 0; w < 8; w++) { ts += rsum[w]; tq += rsq[w]; }
    float mean = ts * (1.0f / Dsz);
    float var  = tq * (1.0f / Dsz) - mean * mean;
    float rstd = rsqrtf(var + 1e-5f);
    for (int d = tid; d < Dsz; d += 256) {
        float v = (buf[d] - mean) * rstd * g[d] + beta[d];
        out[base + d] = v;
        if (oh) {
            bf16 hv = __float2bfloat16(v);
            oh[base + d] = hv;
            ol[base + d] = __float2bfloat16(v - __bfloat162float(hv));
        }
    }
}

// ---------------- launch ----------------
extern "C" void kernel_launch(void* const* d_in, const int* in_sizes, int n_in,
                              void* d_out, int out_size)
{
    const float* x     = (const float*)d_in[0];
    const float* w_q   = (const float*)d_in[1];
    const float* b_q   = (const float*)d_in[2];
    const float* w_k   = (const float*)d_in[3];
    const float* b_k   = (const float*)d_in[4];
    const float* w_v   = (const float*)d_in[5];
    const float* b_v   = (const float*)d_in[6];
    const float* w_o   = (const float*)d_in[7];
    const float* b_o   = (const float*)d_in[8];
    const float* w_g   = (const float*)d_in[9];
    const float* b_g   = (const float*)d_in[10];
    const float* w1    = (const float*)d_in[11];
    const float* b1    = (const float*)d_in[12];
    const float* w2    = (const float*)d_in[13];
    const float* b2    = (const float*)d_in[14];
    const float* g1    = (const float*)d_in[15];
    const float* beta1 = (const float*)d_in[16];
    const float* g2    = (const float*)d_in[17];
    const float* beta2 = (const float*)d_in[18];
    const int*   mask  = (const int*)  d_in[19];
    float* out = (float*)d_out;

    float *tmp, *x1, *gate;
    cudaGetSymbolAddress((void**)&tmp,  g_tmp);
    cudaGetSymbolAddress((void**)&x1,   g_x1);
    cudaGetSymbolAddress((void**)&gate, g_gate);

    bf16 *xh,*xl,*qh,*kh,*vh,*ctxh,*x1h,*x1l,*ffh,*ffl;
    bf16 *wqh,*wql,*wkh,*wkl,*wvh,*wvl,*woh,*wol,*w1h,*w1l,*w2h,*w2l;
    cudaGetSymbolAddress((void**)&xh,  g_xh);   cudaGetSymbolAddress((void**)&xl,  g_xl);
    cudaGetSymbolAddress((void**)&qh,  g_qh);
    cudaGetSymbolAddress((void**)&kh,  g_kh);
    cudaGetSymbolAddress((void**)&vh,  g_vh);
    cudaGetSymbolAddress((void**)&ctxh,g_ctxh);
    cudaGetSymbolAddress((void**)&x1h, g_x1h);  cudaGetSymbolAddress((void**)&x1l, g_x1l);
    cudaGetSymbolAddress((void**)&ffh, g_ffh);  cudaGetSymbolAddress((void**)&ffl, g_ffl);
    cudaGetSymbolAddress((void**)&wqh, g_wqh);  cudaGetSymbolAddress((void**)&wql, g_wql);
    cudaGetSymbolAddress((void**)&wkh, g_wkh);  cudaGetSymbolAddress((void**)&wkl, g_wkl);
    cudaGetSymbolAddress((void**)&wvh, g_wvh);  cudaGetSymbolAddress((void**)&wvl, g_wvl);
    cudaGetSymbolAddress((void**)&woh, g_woh);  cudaGetSymbolAddress((void**)&wol, g_wol);
    cudaGetSymbolAddress((void**)&w1h, g_w1h);  cudaGetSymbolAddress((void**)&w1l, g_w1l);
    cudaGetSymbolAddress((void**)&w2h, g_w2h);  cudaGetSymbolAddress((void**)&w2l, g_w2l);

    cudaFuncSetAttribute(flash_tc_kernel,
                         cudaFuncAttributeMaxDynamicSharedMemorySize, FLASH_SMEM);
    cudaFuncSetAttribute(gemm_bf16x3_kernel,
                         cudaFuncAttributeMaxDynamicSharedMemorySize, GEMM_SMEM);
    cudaFuncSetAttribute(gemm_bf16x1_kernel,
                         cudaFuncAttributeMaxDynamicSharedMemorySize, GEMM_SMEM1);
    cudaFuncSetAttribute(qkv_gemm_kernel,
                         cudaFuncAttributeMaxDynamicSharedMemorySize, GEMM_SMEM1);

    // 0: split x
    split_x_kernel<<<Msz*Dsz/(4*256), 256>>>(x, xh, xl);

    // 1: split weights
    SplitWArgs sw;
    sw.src[0] = w_q; sw.hi[0] = wqh; sw.lo[0] = wql;
    sw.src[1] = w_k; sw.hi[1] = wkh; sw.lo[1] = wkl;
    sw.src[2] = w_v; sw.hi[2] = wvh; sw.lo[2] = wvl;
    sw.src[3] = w_o; sw.hi[3] = woh; sw.lo[3] = wol;
    sw.src[4] = w1;  sw.hi[4] = w1h; sw.lo[4] = w1l;
    sw.src[5] = w2;  sw.hi[5] = w2h; sw.lo[5] = w2l;
    split_w_kernel<<<12288, 256>>>(sw);

    // 2: gate
    gate_kernel<<<dim3(Msz/32, 2), 256>>>(x, w_g, b_g, gate);

    // 3: merged QKV GEMM (1-term) <- profiled slot
    QKVArgs qa;
    qa.Wh[0] = wqh; qa.bias[0] = b_q; qa.Ch[0] = qh;
    qa.Wh[1] = wkh; qa.bias[1] = b_k; qa.Ch[1] = kh;
    qa.Wh[2] = wvh; qa.bias[2] = b_v; qa.Ch[2] = vh;
    qkv_gemm_kernel<<<dim3(Dsz/256, Msz/128, 3), 256, GEMM_SMEM1>>>(xh, qa);

    // 4: flash attention
    flash_tc_kernel<<<dim3(Ssz/128, Hsz, Bsz), 256, FLASH_SMEM>>>(
        qh, kh, vh, gate, mask, ctxh);

    dim3 gSq(Dsz/256, Msz/128);      // (4, 64)
    dim3 gF1(DFFsz/256, Msz/128);    // (16, 64)

    // 5: O-proj (1-term)
    gemm_bf16x1_kernel<<<gSq, 256, GEMM_SMEM1>>>(ctxh, woh, b_o, tmp, nullptr, Dsz, Dsz, 2);
    // 6: LN1
    add_ln_kernel<<<Msz, 256>>>(x, tmp, g1, beta1, x1, x1h, x1l);
    // 7: FF1 (3-term, GELU)
    gemm_bf16x3_kernel<<<gF1, 256, GEMM_SMEM>>>(x1h, x1l, w1h, w1l, b1, nullptr, ffh, ffl, DFFsz, Dsz, 5);
    // 8: FF2 (3-term)
    gemm_bf16x3_kernel<<<gSq, 256, GEMM_SMEM>>>(ffh, ffl, w2h, w2l, b2, tmp, nullptr, nullptr, Dsz, DFFsz, 2);
    // 9: LN2
    add_ln_kernel<<<Msz, 256>>>(x1, tmp, g2, beta2, out, nullptr, nullptr);
}

// round 14
// speedup vs baseline: 1.7906x; 1.0165x over previous
#include <cuda_runtime.h>
#include <cuda_bf16.h>
#include <math.h>
#include <cstdint>

// Problem constants
#define Bsz   4
#define Ssz   2048
#define Dsz   1024
#define Hsz   16
#define DKsz  64
#define DFFsz 4096
#define Msz   (Bsz*Ssz)   // 8192 rows

typedef __nv_bfloat16 bf16;

// ---------------- scratch (static device globals; no allocation) ----------------
__device__ float g_tmp [(size_t)Msz*Dsz];
__device__ float g_x1  [(size_t)Msz*Dsz];
__device__ float g_gate[(size_t)Msz*Hsz];

__device__ bf16 g_xh [(size_t)Msz*Dsz],   g_xl [(size_t)Msz*Dsz];
__device__ bf16 g_qh [(size_t)Msz*Dsz];
__device__ bf16 g_kh [(size_t)Msz*Dsz];
__device__ bf16 g_vh [(size_t)Msz*Dsz];
__device__ bf16 g_ctxh[(size_t)Msz*Dsz];
__device__ bf16 g_x1h[(size_t)Msz*Dsz],   g_x1l[(size_t)Msz*Dsz];
__device__ bf16 g_ffh[(size_t)Msz*DFFsz], g_ffl[(size_t)Msz*DFFsz];
__device__ bf16 g_wqh[(size_t)Dsz*Dsz],   g_wql[(size_t)Dsz*Dsz];
__device__ bf16 g_wkh[(size_t)Dsz*Dsz],   g_wkl[(size_t)Dsz*Dsz];
__device__ bf16 g_wvh[(size_t)Dsz*Dsz],   g_wvl[(size_t)Dsz*Dsz];
__device__ bf16 g_woh[(size_t)Dsz*Dsz],   g_wol[(size_t)Dsz*Dsz];
__device__ bf16 g_w1h[(size_t)Dsz*DFFsz], g_w1l[(size_t)Dsz*DFFsz];
__device__ bf16 g_w2h[(size_t)DFFsz*Dsz], g_w2l[(size_t)DFFsz*Dsz];

// ---------------- small helpers ----------------
__device__ __forceinline__ void cp16(uint32_t dst, const void* src) {
    asm volatile("cp.async.ca.shared.global [%0], [%1], 16;\n" :: "r"(dst), "l"(src));
}
__device__ __forceinline__ void cp_commit() {
    asm volatile("cp.async.commit_group;\n");
}
__device__ __forceinline__ void cp_wait0() {
    asm volatile("cp.async.wait_group 0;\n");
}
__device__ __forceinline__ void cp_wait1() {
    asm volatile("cp.async.wait_group 1;\n");
}
__device__ __forceinline__ void cp_wait2() {
    asm volatile("cp.async.wait_group 2;\n");
}
__device__ __forceinline__ void ldsm4(uint32_t* r, uint32_t addr) {
    asm volatile("ldmatrix.sync.aligned.m8n8.x4.shared.b16 {%0,%1,%2,%3}, [%4];"
                 : "=r"(r[0]), "=r"(r[1]), "=r"(r[2]), "=r"(r[3]) : "r"(addr));
}
__device__ __forceinline__ void ldsm4t(uint32_t& r0, uint32_t& r1,
                                       uint32_t& r2, uint32_t& r3, uint32_t addr) {
    asm volatile("ldmatrix.sync.aligned.m8n8.x4.trans.shared.b16 {%0,%1,%2,%3}, [%4];"
                 : "=r"(r0), "=r"(r1), "=r"(r2), "=r"(r3) : "r"(addr));
}
__device__ __forceinline__ void mma16816(float* ac, const uint32_t* a,
                                         uint32_t b0, uint32_t b1) {
    asm volatile(
        "mma.sync.aligned.m16n8k16.row.col.f32.bf16.bf16.f32 "
        "{%0,%1,%2,%3},{%4,%5,%6,%7},{%8,%9},{%0,%1,%2,%3};"
        : "+f"(ac[0]), "+f"(ac[1]), "+f"(ac[2]), "+f"(ac[3])
        : "r"(a[0]), "r"(a[1]), "r"(a[2]), "r"(a[3]), "r"(b0), "r"(b1));
}
__device__ __forceinline__ void pack_pair(float a, float b, uint32_t& hi, uint32_t& lo) {
    bf16 ha = __float2bfloat16(a), hb = __float2bfloat16(b);
    bf16 la = __float2bfloat16(a - __bfloat162float(ha));
    bf16 lb = __float2bfloat16(b - __bfloat162float(hb));
    __nv_bfloat162 th = __halves2bfloat162(ha, hb);
    __nv_bfloat162 tl = __halves2bfloat162(la, lb);
    hi = *(uint32_t*)&th; lo = *(uint32_t*)&tl;
}
__device__ __forceinline__ uint32_t pack_hi(float a, float b) {
    __nv_bfloat162 th = __halves2bfloat162(__float2bfloat16(a), __float2bfloat16(b));
    return *(uint32_t*)&th;
}

// ---------------- splits ----------------
__global__ __launch_bounds__(256)
void split_x_kernel(const float* __restrict__ in, bf16* __restrict__ hi,
                    bf16* __restrict__ lo)
{
    size_t i = (size_t)blockIdx.x * 256 + threadIdx.x;
    float4 v = ((const float4*)in)[i];
    uint32_t h0, l0, h1, l1;
    pack_pair(v.x, v.y, h0, l0);
    pack_pair(v.z, v.w, h1, l1);
    ((uint32_t*)hi)[2*i] = h0; ((uint32_t*)hi)[2*i+1] = h1;
    ((uint32_t*)lo)[2*i] = l0; ((uint32_t*)lo)[2*i+1] = l1;
}

struct SplitWArgs {
    const float* src[6];
    bf16* hi[6];
    bf16* lo[6];
};
__global__ __launch_bounds__(256)
void split_w_kernel(SplitWArgs a)
{
    int bid = blockIdx.x;
    int seg, base;
    if      (bid < 1024)  { seg = 0; base = 0; }
    else if (bid < 2048)  { seg = 1; base = 1024; }
    else if (bid < 3072)  { seg = 2; base = 2048; }
    else if (bid < 4096)  { seg = 3; base = 3072; }
    else if (bid < 8192)  { seg = 4; base = 4096; }
    else                  { seg = 5; base = 8192; }
    size_t i = (size_t)(bid - base) * 256 + threadIdx.x;
    float4 v = ((const float4*)a.src[seg])[i];
    uint32_t h0, l0, h1, l1;
    pack_pair(v.x, v.y, h0, l0);
    pack_pair(v.z, v.w, h1, l1);
    uint32_t* hp = (uint32_t*)a.hi[seg];
    uint32_t* lp = (uint32_t*)a.lo[seg];
    hp[2*i] = h0; hp[2*i+1] = h1;
    lp[2*i] = l0; lp[2*i+1] = l1;
}

// ---------------- bf16 tensor-core GEMM core (4-stage cp.async) ----------
// BM=128, BN in {128, 256}, BK=16, 256 threads = 8 warps (2 M x 4 N).
// Warp tile 64 x (BN/4).  TERMS=3: acc = Ah*Wh + Al*Wh + Ah*Wl.  TERMS=1: Ah*Wh.
// mode bits: 1=GELU, 2=write fp32 C, 4=write bf16 Ch/Cl, 8=write bf16 Ch only
#define APAD 24
#define NSTG 4
#define SA_B (128*APAD*2)   // 6144 B per A stage buffer

template<int BN> struct GeoT {};
template<> struct GeoT<128> {
    static const int WPAD = 136;   // 272B stride; mod128 = 16
    static const int NI = 4;       // n8-subtiles per warp
    static const int WCHUNK = 1;   // cp16 per thread per W buffer
};
template<> struct GeoT<256> {
    static const int WPAD = 264;   // 528B stride; mod128 = 16
    static const int NI = 8;
    static const int WCHUNK = 2;
};

#define SWB(BN)  (16*GeoT<BN>::WPAD*2)
#define GSMEM(TERMS,BN) (NSTG*((TERMS==3?2:1)*(SA_B + SWB(BN))))

template<int TERMS, int BN>
__device__ __forceinline__
void gemm_core(const bf16* __restrict__ Ah, const bf16* __restrict__ Al,
               const bf16* __restrict__ Wh, const bf16* __restrict__ Wl,
               const float* __restrict__ bias, float* __restrict__ C,
               bf16* __restrict__ Ch, bf16* __restrict__ Cl,
               int N, int K, int mode, int row0, int col0)
{
    const int WPAD = GeoT<BN>::WPAD;
    const int NI   = GeoT<BN>::NI;
    const int SW_B = 16*WPAD*2;

    extern __shared__ __align__(16) char gdsm[];
    const uint32_t aAh = (uint32_t)__cvta_generic_to_shared(gdsm);
    const uint32_t aAl = aAh + NSTG*SA_B;
    const uint32_t aWh = (TERMS == 3) ? (aAl + NSTG*SA_B) : (aAh + NSTG*SA_B);
    const uint32_t aWl = aWh + (uint32_t)(NSTG*SW_B);

    const int tid = threadIdx.x;

    const char* pAh = (const char*)(Ah + (size_t)(row0 + (tid>>1)) * K + (tid&1)*8);
    const char* pAl = (TERMS == 3) ? (const char*)(Al + (size_t)(row0 + (tid>>1)) * K + (tid&1)*8) : nullptr;

    // W loader geometry
    const int wsh = (BN == 256) ? 5 : 4;     // threads per k-row group shift
    const int wmsk = (BN == 256) ? 31 : 15;
    const char* pWh = (const char*)(Wh + (size_t)(tid>>wsh) * N + col0 + (tid&wmsk)*8);
    const char* pWl = (TERMS == 3) ? (const char*)(Wl + (size_t)(tid>>wsh) * N + col0 + (tid&wmsk)*8) : nullptr;

    const uint32_t dA = ((tid>>1)*APAD + (tid&1)*8) * 2;
    const uint32_t dW = (uint32_t)(((tid>>wsh)*WPAD + (tid&wmsk)*8) * 2);
    const uint32_t dW2 = (uint32_t)(8*WPAD*2);
    const size_t  gW2 = (size_t)8 * N * 2;

    float acc[4][GeoT<BN>::NI][4];
    #pragma unroll
    for (int i = 0; i < 4; i++)
        #pragma unroll
        for (int j = 0; j < NI; j++)
            #pragma unroll
            for (int t = 0; t < 4; t++) acc[i][j][t] = 0.0f;

    const int wid = tid >> 5, lane = tid & 31;
    const int wm = wid & 1;       // M offset wm*64
    const int wn = wid >> 1;      // N offset wn*(BN/4)
    const int wnw = BN / 4;       // warp N width
    const int lrow = lane & 15, lk = (lane >> 4) * 8;
    const uint32_t offA0 = (uint32_t)(((wm*64 + lrow) * APAD + lk) * 2);
    const uint32_t offB0 = (uint32_t)(((lane & 15) * WPAD + wn*wnw + (lane>>4)*8) * 2);

    const int nit = K / 16;

    auto load_stage = [&](int st, int it2) {
        size_t ka = (size_t)it2 * 16 * 2;
        size_t kw = (size_t)it2 * 16 * (size_t)N * 2;
        cp16(aAh + (uint32_t)st*SA_B + dA, pAh + ka);
        cp16(aWh + (uint32_t)(st*SW_B) + dW, pWh + kw);
        if (BN == 256)
            cp16(aWh + (uint32_t)(st*SW_B) + dW + dW2, pWh + kw + gW2);
        if (TERMS == 3) {
            cp16(aAl + (uint32_t)st*SA_B + dA, pAl + ka);
            cp16(aWl + (uint32_t)(st*SW_B) + dW, pWl + kw);
            if (BN == 256)
                cp16(aWl + (uint32_t)(st*SW_B) + dW + dW2, pWl + kw + gW2);
        }
        cp_commit();
    };

    load_stage(0, 0);
    load_stage(1, 1);
    load_stage(2, 2);

    for (int it = 0; it < nit; ++it) {
        int rem = nit - 1 - it;
        if (rem >= 2) cp_wait2();
        else if (rem == 1) cp_wait1();
        else cp_wait0();
        __syncthreads();
        if (it + 3 < nit)
            load_stage((it + 3) & 3, it + 3);
        const uint32_t s = (uint32_t)(it & 3);

        uint32_t afh[4][4];
        #pragma unroll
        for (int mi = 0; mi < 4; mi++)
            ldsm4(afh[mi], aAh + s*SA_B + offA0 + mi*16*APAD*2);

        uint32_t bfr[GeoT<BN>::NI][2];
        #pragma unroll
        for (int ng = 0; ng < NI/2; ng++)
            ldsm4t(bfr[2*ng][0], bfr[2*ng][1], bfr[2*ng+1][0], bfr[2*ng+1][1],
                   aWh + (uint32_t)(s*SW_B) + offB0 + (uint32_t)(ng*16*2));

        if (TERMS == 3) {
            uint32_t afl[4][4];
            #pragma unroll
            for (int mi = 0; mi < 4; mi++)
                ldsm4(afl[mi], aAl + s*SA_B + offA0 + mi*16*APAD*2);
            #pragma unroll
            for (int mi = 0; mi < 4; mi++)
                #pragma unroll
                for (int ni = 0; ni < NI; ni++) {
                    mma16816(acc[mi][ni], afh[mi], bfr[ni][0], bfr[ni][1]);
                    mma16816(acc[mi][ni], afl[mi], bfr[ni][0], bfr[ni][1]);
                }
            #pragma unroll
            for (int ng = 0; ng < NI/2; ng++)
                ldsm4t(bfr[2*ng][0], bfr[2*ng][1], bfr[2*ng+1][0], bfr[2*ng+1][1],
                       aWl + (uint32_t)(s*SW_B) + offB0 + (uint32_t)(ng*16*2));
            #pragma unroll
            for (int mi = 0; mi < 4; mi++)
                #pragma unroll
                for (int ni = 0; ni < NI; ni++)
                    mma16816(acc[mi][ni], afh[mi], bfr[ni][0], bfr[ni][1]);
        } else {
            #pragma unroll
            for (int mi = 0; mi < 4; mi++)
                #pragma unroll
                for (int ni = 0; ni < NI; ni++)
                    mma16816(acc[mi][ni], afh[mi], bfr[ni][0], bfr[ni][1]);
        }
    }

    #pragma unroll
    for (int mi = 0; mi < 4; mi++) {
        #pragma unroll
        for (int ni = 0; ni < NI; ni++) {
            int c = col0 + wn*wnw + ni*8 + (lane & 3)*2;
            float bx = bias[c], by = bias[c + 1];
            #pragma unroll
            for (int rh = 0; rh < 2; rh++) {
                size_t r = (size_t)(row0 + wm*64 + mi*16 + (lane >> 2) + rh*8);
                float v0 = acc[mi][ni][2*rh]     + bx;
                float v1 = acc[mi][ni][2*rh + 1] + by;
                if (mode & 1) {
                    v0 = 0.5f * v0 * (1.0f + erff(v0 * 0.70710678118654752f));
                    v1 = 0.5f * v1 * (1.0f + erff(v1 * 0.70710678118654752f));
                }
                if (mode & 2) {
                    float2 o; o.x = v0; o.y = v1;
                    *(float2*)&C[r * N + c] = o;
                }
                if (mode & 4) {
                    uint32_t hp, lp;
                    pack_pair(v0, v1, hp, lp);
                    *(uint32_t*)&Ch[r * N + c] = hp;
                    *(uint32_t*)&Cl[r * N + c] = lp;
                }
                if (mode & 8) {
                    *(uint32_t*)&Ch[r * N + c] = pack_hi(v0, v1);
                }
            }
        }
    }
}

// 3-term: BN=256 (85 B/MMA)
__global__ __launch_bounds__(256, 1)
void gemm_bf16x3_kernel(const bf16* __restrict__ Ah, const bf16* __restrict__ Al,
                        const bf16* __restrict__ Wh, const bf16* __restrict__ Wl,
                        const float* __restrict__ bias, float* __restrict__ C,
                        bf16* __restrict__ Ch, bf16* __restrict__ Cl,
                        int N, int K, int mode)
{
    gemm_core<3, 256>(Ah, Al, Wh, Wl, bias, C, Ch, Cl, N, K, mode,
                      blockIdx.y * 128, blockIdx.x * 256);
}

// 1-term: BN=128 (R12 geometry, 2 CTAs/SM)
__global__ __launch_bounds__(256)
void gemm_bf16x1_kernel(const bf16* __restrict__ Ah,
                        const bf16* __restrict__ Wh,
                        const float* __restrict__ bias, float* __restrict__ C,
                        bf16* __restrict__ Ch,
                        int N, int K, int mode)
{
    gemm_core<1, 128>(Ah, nullptr, Wh, nullptr, bias, C, Ch, nullptr, N, K, mode,
                      blockIdx.y * 128, blockIdx.x * 128);
}

struct QKVArgs {
    const bf16* Wh[3];
    const float* bias[3];
    bf16* Ch[3];
};
__global__ __launch_bounds__(256)
void qkv_gemm_kernel(const bf16* __restrict__ Ah, QKVArgs a)
{
    int z = blockIdx.z;
    gemm_core<1, 128>(Ah, nullptr, a.Wh[z], nullptr, a.bias[z], nullptr, a.Ch[z], nullptr,
                      Dsz, Dsz, 8, blockIdx.y * 128, blockIdx.x * 128);
}

// ---------------- sigmoid gate ----------------------
__global__ __launch_bounds__(256)
void gate_kernel(const float* __restrict__ x, const float* __restrict__ wg,
                 const float* __restrict__ bg, float* __restrict__ gate)
{
    __shared__ float wgs[Dsz][8];
    int hg = blockIdx.y;
    int tid = threadIdx.x;
    for (int idx = tid; idx < Dsz*8; idx += 256)
        wgs[idx >> 3][idx & 7] = wg[(idx >> 3) * Hsz + hg*8 + (idx & 7)];
    __syncthreads();

    int h = tid & 7, r = tid >> 3;
    int m = blockIdx.x * 32 + r;
    const float4* xr = (const float4*)(x + (size_t)m * Dsz);
    float s = 0.0f;
    #pragma unroll 4
    for (int d4 = 0; d4 < Dsz/4; d4++) {
        float4 xv = xr[d4];
        s = fmaf(xv.x, wgs[d4*4 + 0][h], s);
        s = fmaf(xv.y, wgs[d4*4 + 1][h], s);
        s = fmaf(xv.z, wgs[d4*4 + 2][h], s);
        s = fmaf(xv.w, wgs[d4*4 + 3][h], s);
    }
    s += bg[hg*8 + h];
    gate[(size_t)m * Hsz + hg*8 + h] = 1.0f / (1.0f + __expf(-s));
}

// ---------------- tensor-core flash attention (bf16, 128-q tile, 8 warps) ------
#define FPAD 72
#define KV_STRIDE (64*FPAD)
#define Q_STRIDE  (128*FPAD)
#define KV_STAGE  (2*KV_STRIDE)
#define FLASH_SMEM (Q_STRIDE*2 + 2*KV_STAGE*2 + 2*64*4)

__global__ __launch_bounds__(256, 2)
void flash_tc_kernel(const bf16* __restrict__ Qh,
                     const bf16* __restrict__ Kh,
                     const bf16* __restrict__ Vh,
                     const float* __restrict__ gate, const int* __restrict__ mask,
                     bf16* __restrict__ Ch)
{
    extern __shared__ __align__(16) char dynsmem[];
    const uint32_t qbase = (uint32_t)__cvta_generic_to_shared(dynsmem);
    const uint32_t kvbase = qbase + Q_STRIDE*2;
    const uint32_t mbase = kvbase + 2*KV_STAGE*2;
    int* smsk = (int*)(dynsmem + (size_t)Q_STRIDE*2 + (size_t)2*KV_STAGE*2);

    const int tid = threadIdx.x, lane = tid & 31, warp = tid >> 5;
    const int qt = blockIdx.x, h = blockIdx.y, b = blockIdx.z;
    const size_t rowbase = (size_t)b * Ssz;
    const size_t hoff = (size_t)h * DKsz;

    {
        int r = tid >> 1;
        size_t gq = (rowbase + qt*128 + r) * Dsz + hoff;
        #pragma unroll
        for (int j = 0; j < 4; j++) {
            int c8 = (tid & 1)*4 + j;
            uint32_t dof = (uint32_t)((r*FPAD + c8*8)*2);
            cp16(qbase + dof, Qh + gq + c8*8);
        }
        cp_commit(); cp_wait0();
    }
    __syncthreads();

    uint32_t qfh[4][4];
    {
        uint32_t arow = (uint32_t)((warp*16 + (lane&15))*FPAD*2);
        #pragma unroll
        for (int ks = 0; ks < 4; ks++) {
            uint32_t acol = (uint32_t)((16*ks + (lane>>4)*8)*2);
            ldsm4(qfh[ks], qbase + arow + acol);
        }
    }
    __syncthreads();

    float oacc[8][4];
    #pragma unroll
    for (int i = 0; i < 8; i++)
        #pragma unroll
        for (int j = 0; j < 4; j++) oacc[i][j] = 0.0f;
    float m0 = -1e30f, m1 = -1e30f, l0 = 0.0f, l1 = 0.0f;

    const int r_ld = tid >> 2;
    const int cbase = (tid & 3)*2;

    {
        size_t g = (rowbase + r_ld) * Dsz + hoff;
        #pragma unroll
        for (int j = 0; j < 2; j++) {
            int c8 = cbase + j;
            uint32_t dof = (uint32_t)((r_ld*FPAD + c8*8)*2);
            cp16(kvbase + dof, Kh + g + c8*8);
            cp16(kvbase + KV_STRIDE*2 + dof, Vh + g + c8*8);
        }
        if (tid < 16) cp16(mbase + tid*16, mask + rowbase + tid*4);
        cp_commit();
    }

    const int col0 = 2*(lane & 3);

    for (int kt = 0; kt < Ssz/64; kt++) {
        cp_wait0();
        __syncthreads();
        if (kt + 1 < Ssz/64) {
            int st = (kt + 1) & 1;
            size_t g = (rowbase + (kt+1)*64 + r_ld) * Dsz + hoff;
            uint32_t sb = kvbase + (uint32_t)(st*KV_STAGE*2);
            #pragma unroll
            for (int j = 0; j < 2; j++) {
                int c8 = cbase + j;
                uint32_t dof = (uint32_t)((r_ld*FPAD + c8*8)*2);
                cp16(sb + dof, Kh + g + c8*8);
                cp16(sb + KV_STRIDE*2 + dof, Vh + g + c8*8);
            }
            if (tid < 16) cp16(mbase + st*256 + tid*16, mask + rowbase + (kt+1)*64 + tid*4);
            cp_commit();
        }
        const int st = kt & 1;
        const uint32_t kb = kvbase + (uint32_t)(st*KV_STAGE*2);

        float sc[8][4];
        #pragma unroll
        for (int i = 0; i < 8; i++)
            #pragma unroll
            for (int j = 0; j < 4; j++) sc[i][j] = 0.0f;

        const uint32_t brow = (uint32_t)(((lane&7) + ((lane>>1)&8)) * FPAD * 2);
        const uint32_t bcol = (uint32_t)((lane & 8) * 2);
        #pragma unroll
        for (int ng = 0; ng < 4; ng++) {
            #pragma unroll
            for (int ks = 0; ks < 4; ks++) {
                uint32_t ba = kb + brow + (uint32_t)(16*ng*FPAD*2) + bcol + (uint32_t)(16*ks*2);
                uint32_t bh4[4];
                ldsm4(bh4, ba);
                mma16816(sc[2*ng],   qfh[ks], bh4[0], bh4[1]);
                mma16816(sc[2*ng+1], qfh[ks], bh4[2], bh4[3]);
            }
        }

        const int* mk = smsk + st*64;
        float mx0 = -1e30f, mx1 = -1e30f;
        #pragma unroll
        for (int ni = 0; ni < 8; ni++) {
            int c = 8*ni + col0;
            bool z0 = (mk[c] == 0), z1 = (mk[c+1] == 0);
            sc[ni][0] = z0 ? -1e9f : sc[ni][0]*0.125f;
            sc[ni][1] = z1 ? -1e9f : sc[ni][1]*0.125f;
            sc[ni][2] = z0 ? -1e9f : sc[ni][2]*0.125f;
            sc[ni][3] = z1 ? -1e9f : sc[ni][3]*0.125f;
            mx0 = fmaxf(mx0, fmaxf(sc[ni][0], sc[ni][1]));
            mx1 = fmaxf(mx1, fmaxf(sc[ni][2], sc[ni][3]));
        }
        mx0 = fmaxf(mx0, __shfl_xor_sync(0xffffffffu, mx0, 1));
        mx0 = fmaxf(mx0, __shfl_xor_sync(0xffffffffu, mx0, 2));
        mx1 = fmaxf(mx1, __shfl_xor_sync(0xffffffffu, mx1, 1));
        mx1 = fmaxf(mx1, __shfl_xor_sync(0xffffffffu, mx1, 2));
        float mn0 = fmaxf(m0, mx0), mn1 = fmaxf(m1, mx1);
        float al0 = __expf(m0 - mn0), al1 = __expf(m1 - mn1);
        float rs0 = 0.0f, rs1 = 0.0f;
        #pragma unroll
        for (int ni = 0; ni < 8; ni++) {
            sc[ni][0] = __expf(sc[ni][0] - mn0);
            sc[ni][1] = __expf(sc[ni][1] - mn0);
            sc[ni][2] = __expf(sc[ni][2] - mn1);
            sc[ni][3] = __expf(sc[ni][3] - mn1);
            rs0 += sc[ni][0] + sc[ni][1];
            rs1 += sc[ni][2] + sc[ni][3];
        }
        rs0 += __shfl_xor_sync(0xffffffffu, rs0, 1);
        rs0 += __shfl_xor_sync(0xffffffffu, rs0, 2);
        rs1 += __shfl_xor_sync(0xffffffffu, rs1, 1);
        rs1 += __shfl_xor_sync(0xffffffffu, rs1, 2);
        l0 = l0*al0 + rs0; l1 = l1*al1 + rs1;
        m0 = mn0; m1 = mn1;
        #pragma unroll
        for (int ni = 0; ni < 8; ni++) {
            oacc[ni][0] *= al0; oacc[ni][1] *= al0;
            oacc[ni][2] *= al1; oacc[ni][3] *= al1;
        }

        const uint32_t vrow0 = (uint32_t)((lane&15)*FPAD*2);
        const uint32_t vcol0 = (uint32_t)(((lane>>4)*8)*2);
        #pragma unroll
        for (int ki = 0; ki < 4; ki++) {
            uint32_t ph[4];
            ph[0] = pack_hi(sc[2*ki][0],   sc[2*ki][1]);
            ph[1] = pack_hi(sc[2*ki][2],   sc[2*ki][3]);
            ph[2] = pack_hi(sc[2*ki+1][0], sc[2*ki+1][1]);
            ph[3] = pack_hi(sc[2*ki+1][2], sc[2*ki+1][3]);
            uint32_t va0 = kb + KV_STRIDE*2 + vrow0 + (uint32_t)(16*ki*FPAD*2) + vcol0;
            #pragma unroll
            for (int ngd = 0; ngd < 4; ngd++) {
                uint32_t vh4[4];
                ldsm4t(vh4[0], vh4[1], vh4[2], vh4[3], va0 + (uint32_t)(16*ngd*2));
                mma16816(oacc[2*ngd],   ph, vh4[0], vh4[1]);
                mma16816(oacc[2*ngd+1], ph, vh4[2], vh4[3]);
            }
        }
    }

    int q0 = qt*128 + warp*16 + (lane >> 2);
    float f0 = gate[(rowbase + q0)*Hsz + h] / l0;
    float f1 = gate[(rowbase + q0 + 8)*Hsz + h] / l1;
    #pragma unroll
    for (int ni = 0; ni < 8; ni++) {
        size_t o0 = (rowbase + q0) * Dsz + hoff + 8*ni + col0;
        size_t o1 = o0 + (size_t)8 * Dsz;
        *(uint32_t*)&Ch[o0] = pack_hi(oacc[ni][0]*f0, oacc[ni][1]*f0);
        *(uint32_t*)&Ch[o1] = pack_hi(oacc[ni][2]*f1, oacc[ni][3]*f1);
    }
}

// ---------------- fused residual add + LayerNorm (+ optional bf16 split out) ----
__global__ __launch_bounds__(256)
void add_ln_kernel(const float* __restrict__ a, const float* __restrict__ bsrc,
                   const float* __restrict__ g, const float* __restrict__ beta,
                   float* __restrict__ out, bf16* __restrict__ oh, bf16* __restrict__ ol)
{
    int row = blockIdx.x;
    int tid = threadIdx.x;
    __shared__ float buf[Dsz];
    __shared__ float rsum[8], rsq[8];

    size_t base = (size_t)row * Dsz;
    float ls = 0.0f, lq = 0.0f;
    for (int d = tid; d < Dsz; d += 256) {
        float v = a[base + d] + bsrc[base + d];
        buf[d] = v;
        ls += v; lq += v * v;
    }
    int warp = tid >> 5, lane = tid & 31;
    for (int off = 16; off; off >>= 1) {
        ls += __shfl_xor_sync(0xffffffffu, ls, off);
        lq += __shfl_xor_sync(0xffffffffu, lq, off);
    }
    if (lane == 0) { rsum[warp] = ls; rsq[warp] = lq; }
    __syncthreads();
    float ts = 0.0f, tq = 0.0f;
    #pragma unroll
    for (int w = 0; w < 8; w++) { ts += rsum[w]; tq += rsq[w]; }
    float mean = ts * (1.0f / Dsz);
    float var  = tq * (1.0f / Dsz) - mean * mean;
    float rstd = rsqrtf(var + 1e-5f);
    for (int d = tid; d < Dsz; d += 256) {
        float v = (buf[d] - mean) * rstd * g[d] + beta[d];
        out[base + d] = v;
        if (oh) {
            bf16 hv = __float2bfloat16(v);
            oh[base + d] = hv;
            ol[base + d] = __float2bfloat16(v - __bfloat162float(hv));
        }
    }
}

// ---------------- launch ----------------
extern "C" void kernel_launch(void* const* d_in, const int* in_sizes, int n_in,
                              void* d_out, int out_size)
{
    const float* x     = (const float*)d_in[0];
    const float* w_q   = (const float*)d_in[1];
    const float* b_q   = (const float*)d_in[2];
    const float* w_k   = (const float*)d_in[3];
    const float* b_k   = (const float*)d_in[4];
    const float* w_v   = (const float*)d_in[5];
    const float* b_v   = (const float*)d_in[6];
    const float* w_o   = (const float*)d_in[7];
    const float* b_o   = (const float*)d_in[8];
    const float* w_g   = (const float*)d_in[9];
    const float* b_g   = (const float*)d_in[10];
    const float* w1    = (const float*)d_in[11];
    const float* b1    = (const float*)d_in[12];
    const float* w2    = (const float*)d_in[13];
    const float* b2    = (const float*)d_in[14];
    const float* g1    = (const float*)d_in[15];
    const float* beta1 = (const float*)d_in[16];
    const float* g2    = (const float*)d_in[17];
    const float* beta2 = (const float*)d_in[18];
    const int*   mask  = (const int*)  d_in[19];
    float* out = (float*)d_out;

    float *tmp, *x1, *gate;
    cudaGetSymbolAddress((void**)&tmp,  g_tmp);
    cudaGetSymbolAddress((void**)&x1,   g_x1);
    cudaGetSymbolAddress((void**)&gate, g_gate);

    bf16 *xh,*xl,*qh,*kh,*vh,*ctxh,*x1h,*x1l,*ffh,*ffl;
    bf16 *wqh,*wql,*wkh,*wkl,*wvh,*wvl,*woh,*wol,*w1h,*w1l,*w2h,*w2l;
    cudaGetSymbolAddress((void**)&xh,  g_xh);   cudaGetSymbolAddress((void**)&xl,  g_xl);
    cudaGetSymbolAddress((void**)&qh,  g_qh);
    cudaGetSymbolAddress((void**)&kh,  g_kh);
    cudaGetSymbolAddress((void**)&vh,  g_vh);
    cudaGetSymbolAddress((void**)&ctxh,g_ctxh);
    cudaGetSymbolAddress((void**)&x1h, g_x1h);  cudaGetSymbolAddress((void**)&x1l, g_x1l);
    cudaGetSymbolAddress((void**)&ffh, g_ffh);  cudaGetSymbolAddress((void**)&ffl, g_ffl);
    cudaGetSymbolAddress((void**)&wqh, g_wqh);  cudaGetSymbolAddress((void**)&wql, g_wql);
    cudaGetSymbolAddress((void**)&wkh, g_wkh);  cudaGetSymbolAddress((void**)&wkl, g_wkl);
    cudaGetSymbolAddress((void**)&wvh, g_wvh);  cudaGetSymbolAddress((void**)&wvl, g_wvl);
    cudaGetSymbolAddress((void**)&woh, g_woh);  cudaGetSymbolAddress((void**)&wol, g_wol);
    cudaGetSymbolAddress((void**)&w1h, g_w1h);  cudaGetSymbolAddress((void**)&w1l, g_w1l);
    cudaGetSymbolAddress((void**)&w2h, g_w2h);  cudaGetSymbolAddress((void**)&w2l, g_w2l);

    cudaFuncSetAttribute(flash_tc_kernel,
                         cudaFuncAttributeMaxDynamicSharedMemorySize, FLASH_SMEM);
    cudaFuncSetAttribute(gemm_bf16x3_kernel,
                         cudaFuncAttributeMaxDynamicSharedMemorySize, GSMEM(3,256));
    cudaFuncSetAttribute(gemm_bf16x1_kernel,
                         cudaFuncAttributeMaxDynamicSharedMemorySize, GSMEM(1,128));
    cudaFuncSetAttribute(qkv_gemm_kernel,
                         cudaFuncAttributeMaxDynamicSharedMemorySize, GSMEM(1,128));

    // 0: split x
    split_x_kernel<<<Msz*Dsz/(4*256), 256>>>(x, xh, xl);

    // 1: split weights
    SplitWArgs sw;
    sw.src[0] = w_q; sw.hi[0] = wqh; sw.lo[0] = wql;
    sw.src[1] = w_k; sw.hi[1] = wkh; sw.lo[1] = wkl;
    sw.src[2] = w_v; sw.hi[2] = wvh; sw.lo[2] = wvl;
    sw.src[3] = w_o; sw.hi[3] = woh; sw.lo[3] = wol;
    sw.src[4] = w1;  sw.hi[4] = w1h; sw.lo[4] = w1l;
    sw.src[5] = w2;  sw.hi[5] = w2h; sw.lo[5] = w2l;
    split_w_kernel<<<12288, 256>>>(sw);

    // 2: gate
    gate_kernel<<<dim3(Msz/32, 2), 256>>>(x, w_g, b_g, gate);

    // 3: merged QKV GEMM (1-term, BN=128) <- profiled slot
    QKVArgs qa;
    qa.Wh[0] = wqh; qa.bias[0] = b_q; qa.Ch[0] = qh;
    qa.Wh[1] = wkh; qa.bias[1] = b_k; qa.Ch[1] = kh;
    qa.Wh[2] = wvh; qa.bias[2] = b_v; qa.Ch[2] = vh;
    qkv_gemm_kernel<<<dim3(Dsz/128, Msz/128, 3), 256, GSMEM(1,128)>>>(xh, qa);

    // 4: flash attention
    flash_tc_kernel<<<dim3(Ssz/128, Hsz, Bsz), 256, FLASH_SMEM>>>(
        qh, kh, vh, gate, mask, ctxh);

    // 5: O-proj (1-term, BN=128)
    gemm_bf16x1_kernel<<<dim3(Dsz/128, Msz/128), 256, GSMEM(1,128)>>>(
        ctxh, woh, b_o, tmp, nullptr, Dsz, Dsz, 2);
    // 6: LN1
    add_ln_kernel<<<Msz, 256>>>(x, tmp, g1, beta1, x1, x1h, x1l);
    // 7: FF1 (3-term, BN=256, GELU)
    gemm_bf16x3_kernel<<<dim3(DFFsz/256, Msz/128), 256, GSMEM(3,256)>>>(
        x1h, x1l, w1h, w1l, b1, nullptr, ffh, ffl, DFFsz, Dsz, 5);
    // 8: FF2 (3-term, BN=256)
    gemm_bf16x3_kernel<<<dim3(Dsz/256, Msz/128), 256, GSMEM(3,256)>>>(
        ffh, ffl, w2h, w2l, b2, tmp, nullptr, nullptr, Dsz, DFFsz, 2);
    // 9: LN2
    add_ln_kernel<<<Msz, 256>>>(x1, tmp, g2, beta2, out, nullptr, nullptr);
}

// round 15
// speedup vs baseline: 2.1523x; 1.2020x over previous
#include <cuda_runtime.h>
#include <cuda_bf16.h>
#include <math.h>
#include <cstdint>

// Problem constants
#define Bsz   4
#define Ssz   2048
#define Dsz   1024
#define Hsz   16
#define DKsz  64
#define DFFsz 4096
#define Msz   (Bsz*Ssz)   // 8192 rows

typedef __nv_bfloat16 bf16;

// ---------------- scratch (static device globals; no allocation) ----------------
__device__ float g_tmp [(size_t)Msz*Dsz];
__device__ float g_x1  [(size_t)Msz*Dsz];
__device__ float g_gate[(size_t)Msz*Hsz];

__device__ bf16 g_xh [(size_t)Msz*Dsz],   g_xl [(size_t)Msz*Dsz];
__device__ bf16 g_qh [(size_t)Msz*Dsz];
__device__ bf16 g_kh [(size_t)Msz*Dsz];
__device__ bf16 g_vh [(size_t)Msz*Dsz];
__device__ bf16 g_ctxh[(size_t)Msz*Dsz];
__device__ bf16 g_x1h[(size_t)Msz*Dsz],   g_x1l[(size_t)Msz*Dsz];
__device__ bf16 g_ffh[(size_t)Msz*DFFsz], g_ffl[(size_t)Msz*DFFsz];
__device__ bf16 g_wqh[(size_t)Dsz*Dsz];
__device__ bf16 g_wkh[(size_t)Dsz*Dsz];
__device__ bf16 g_wvh[(size_t)Dsz*Dsz];
__device__ bf16 g_woh[(size_t)Dsz*Dsz];
__device__ bf16 g_w1h[(size_t)Dsz*DFFsz], g_w1l[(size_t)Dsz*DFFsz];
__device__ bf16 g_w2h[(size_t)DFFsz*Dsz];

// ---------------- small helpers ----------------
__device__ __forceinline__ void cp16(uint32_t dst, const void* src) {
    asm volatile("cp.async.ca.shared.global [%0], [%1], 16;\n" :: "r"(dst), "l"(src));
}
__device__ __forceinline__ void cp_commit() {
    asm volatile("cp.async.commit_group;\n");
}
__device__ __forceinline__ void cp_wait0() {
    asm volatile("cp.async.wait_group 0;\n");
}
__device__ __forceinline__ void cp_wait1() {
    asm volatile("cp.async.wait_group 1;\n");
}
__device__ __forceinline__ void cp_wait2() {
    asm volatile("cp.async.wait_group 2;\n");
}
__device__ __forceinline__ void ldsm4(uint32_t* r, uint32_t addr) {
    asm volatile("ldmatrix.sync.aligned.m8n8.x4.shared.b16 {%0,%1,%2,%3}, [%4];"
                 : "=r"(r[0]), "=r"(r[1]), "=r"(r[2]), "=r"(r[3]) : "r"(addr));
}
__device__ __forceinline__ void ldsm4t(uint32_t& r0, uint32_t& r1,
                                       uint32_t& r2, uint32_t& r3, uint32_t addr) {
    asm volatile("ldmatrix.sync.aligned.m8n8.x4.trans.shared.b16 {%0,%1,%2,%3}, [%4];"
                 : "=r"(r0), "=r"(r1), "=r"(r2), "=r"(r3) : "r"(addr));
}
__device__ __forceinline__ void mma16816(float* ac, const uint32_t* a,
                                         uint32_t b0, uint32_t b1) {
    asm volatile(
        "mma.sync.aligned.m16n8k16.row.col.f32.bf16.bf16.f32 "
        "{%0,%1,%2,%3},{%4,%5,%6,%7},{%8,%9},{%0,%1,%2,%3};"
        : "+f"(ac[0]), "+f"(ac[1]), "+f"(ac[2]), "+f"(ac[3])
        : "r"(a[0]), "r"(a[1]), "r"(a[2]), "r"(a[3]), "r"(b0), "r"(b1));
}
__device__ __forceinline__ void pack_pair(float a, float b, uint32_t& hi, uint32_t& lo) {
    bf16 ha = __float2bfloat16(a), hb = __float2bfloat16(b);
    bf16 la = __float2bfloat16(a - __bfloat162float(ha));
    bf16 lb = __float2bfloat16(b - __bfloat162float(hb));
    __nv_bfloat162 th = __halves2bfloat162(ha, hb);
    __nv_bfloat162 tl = __halves2bfloat162(la, lb);
    hi = *(uint32_t*)&th; lo = *(uint32_t*)&tl;
}
__device__ __forceinline__ uint32_t pack_hi(float a, float b) {
    __nv_bfloat162 th = __halves2bfloat162(__float2bfloat16(a), __float2bfloat16(b));
    return *(uint32_t*)&th;
}

// ---------------- splits (2 float4 per thread) ----------------
__global__ __launch_bounds__(256)
void split_x_kernel(const float* __restrict__ in, bf16* __restrict__ hi,
                    bf16* __restrict__ lo)
{
    size_t base = (size_t)blockIdx.x * 512 + threadIdx.x;
    #pragma unroll
    for (int k = 0; k < 2; k++) {
        size_t i = base + k * 256;
        float4 v = ((const float4*)in)[i];
        uint32_t h0, l0, h1, l1;
        pack_pair(v.x, v.y, h0, l0);
        pack_pair(v.z, v.w, h1, l1);
        ((uint32_t*)hi)[2*i] = h0; ((uint32_t*)hi)[2*i+1] = h1;
        ((uint32_t*)lo)[2*i] = l0; ((uint32_t*)lo)[2*i+1] = l1;
    }
}

// weights: hi-only for wq/wk/wv/wo/w2 (lo unused); hi+lo for w1
struct SplitWArgs {
    const float* src[6];
    bf16* hi[6];
    bf16* lo[6];      // nullptr -> hi only
};
__global__ __launch_bounds__(256)
void split_w_kernel(SplitWArgs a)
{
    int bid = blockIdx.x;
    int seg, base;
    if      (bid < 512)   { seg = 0; base = 0; }
    else if (bid < 1024)  { seg = 1; base = 512; }
    else if (bid < 1536)  { seg = 2; base = 1024; }
    else if (bid < 2048)  { seg = 3; base = 1536; }
    else if (bid < 4096)  { seg = 4; base = 2048; }
    else                  { seg = 5; base = 4096; }
    const float* src = a.src[seg];
    bf16* hi = a.hi[seg];
    bf16* lo = a.lo[seg];
    size_t b0 = (size_t)(bid - base) * 512 + threadIdx.x;
    #pragma unroll
    for (int k = 0; k < 2; k++) {
        size_t i = b0 + k * 256;
        float4 v = ((const float4*)src)[i];
        uint32_t h0, l0, h1, l1;
        pack_pair(v.x, v.y, h0, l0);
        pack_pair(v.z, v.w, h1, l1);
        ((uint32_t*)hi)[2*i] = h0; ((uint32_t*)hi)[2*i+1] = h1;
        if (lo) {
            ((uint32_t*)lo)[2*i] = l0; ((uint32_t*)lo)[2*i+1] = l1;
        }
    }
}

// ---------------- 1-term bf16 GEMM (proven R12/R14 path: BN=128, 4-stage) ------
#define APAD 24
#define NSTG 4
#define SA_B (128*APAD*2)   // 6144
#define WPAD1 136
#define SW_B1 (16*WPAD1*2)  // 4352
#define GSMEM1 (NSTG*(SA_B + SW_B1))  // 41984

__device__ __forceinline__
void gemm1_core(const bf16* __restrict__ Ah,
                const bf16* __restrict__ Wh,
                const float* __restrict__ bias, float* __restrict__ C,
                bf16* __restrict__ Ch,
                int N, int K, int mode, int row0, int col0)
{
    extern __shared__ __align__(16) char gdsm[];
    const uint32_t aAh = (uint32_t)__cvta_generic_to_shared(gdsm);
    const uint32_t aWh = aAh + NSTG*SA_B;

    const int tid = threadIdx.x;

    const char* pAh = (const char*)(Ah + (size_t)(row0 + (tid>>1)) * K + (tid&1)*8);
    const char* pWh = (const char*)(Wh + (size_t)(tid>>4) * N + col0 + (tid&15)*8);

    const uint32_t dA = ((tid>>1)*APAD + (tid&1)*8) * 2;
    const uint32_t dW = (uint32_t)(((tid>>4)*WPAD1 + (tid&15)*8) * 2);

    float acc[4][4][4];
    #pragma unroll
    for (int i = 0; i < 4; i++)
        #pragma unroll
        for (int j = 0; j < 4; j++)
            #pragma unroll
            for (int t = 0; t < 4; t++) acc[i][j][t] = 0.0f;

    const int wid = tid >> 5, lane = tid & 31;
    const int wm = wid & 1;
    const int wn = wid >> 1;
    const int lrow = lane & 15, lk = (lane >> 4) * 8;
    const uint32_t offA0 = (uint32_t)(((wm*64 + lrow) * APAD + lk) * 2);
    const uint32_t offB0 = (uint32_t)(((lane & 15) * WPAD1 + wn*32 + (lane>>4)*8) * 2);

    const int nit = K / 16;

    auto load_stage = [&](int st, int it2) {
        size_t ka = (size_t)it2 * 16 * 2;
        size_t kw = (size_t)it2 * 16 * (size_t)N * 2;
        cp16(aAh + (uint32_t)st*SA_B + dA, pAh + ka);
        cp16(aWh + (uint32_t)(st*SW_B1) + dW, pWh + kw);
        cp_commit();
    };

    load_stage(0, 0);
    load_stage(1, 1);
    load_stage(2, 2);

    for (int it = 0; it < nit; ++it) {
        int rem = nit - 1 - it;
        if (rem >= 2) cp_wait2();
        else if (rem == 1) cp_wait1();
        else cp_wait0();
        __syncthreads();
        if (it + 3 < nit)
            load_stage((it + 3) & 3, it + 3);
        const uint32_t s = (uint32_t)(it & 3);

        uint32_t afh[4][4];
        #pragma unroll
        for (int mi = 0; mi < 4; mi++)
            ldsm4(afh[mi], aAh + s*SA_B + offA0 + mi*16*APAD*2);

        uint32_t bfr[4][2];
        #pragma unroll
        for (int ng = 0; ng < 2; ng++)
            ldsm4t(bfr[2*ng][0], bfr[2*ng][1], bfr[2*ng+1][0], bfr[2*ng+1][1],
                   aWh + (uint32_t)(s*SW_B1) + offB0 + (uint32_t)(ng*16*2));

        #pragma unroll
        for (int mi = 0; mi < 4; mi++)
            #pragma unroll
            for (int ni = 0; ni < 4; ni++)
                mma16816(acc[mi][ni], afh[mi], bfr[ni][0], bfr[ni][1]);
    }

    #pragma unroll
    for (int mi = 0; mi < 4; mi++) {
        #pragma unroll
        for (int ni = 0; ni < 4; ni++) {
            int c = col0 + wn*32 + ni*8 + (lane & 3)*2;
            float bx = bias[c], by = bias[c + 1];
            #pragma unroll
            for (int rh = 0; rh < 2; rh++) {
                size_t r = (size_t)(row0 + wm*64 + mi*16 + (lane >> 2) + rh*8);
                float v0 = acc[mi][ni][2*rh]     + bx;
                float v1 = acc[mi][ni][2*rh + 1] + by;
                if (mode & 2) {
                    float2 o; o.x = v0; o.y = v1;
                    *(float2*)&C[r * N + c] = o;
                }
                if (mode & 8) {
                    *(uint32_t*)&Ch[r * N + c] = pack_hi(v0, v1);
                }
            }
        }
    }
}

__global__ __launch_bounds__(256)
void gemm_bf16x1_kernel(const bf16* __restrict__ Ah,
                        const bf16* __restrict__ Wh,
                        const float* __restrict__ bias, float* __restrict__ C,
                        bf16* __restrict__ Ch,
                        int N, int K, int mode)
{
    gemm1_core(Ah, Wh, bias, C, Ch, N, K, mode,
               blockIdx.y * 128, blockIdx.x * 128);
}

struct QKVArgs {
    const bf16* Wh[3];
    const float* bias[3];
    bf16* Ch[3];
};
__global__ __launch_bounds__(256)
void qkv_gemm_kernel(const bf16* __restrict__ Ah, QKVArgs a)
{
    int z = blockIdx.z;
    gemm1_core(Ah, a.Wh[z], a.bias[z], nullptr, a.Ch[z],
               Dsz, Dsz, 8, blockIdx.y * 128, blockIdx.x * 128);
}

// ---------------- FF GEMM: BM=128, BN=256, BK=32, 3-stage, TERMS in {2,3} ------
// TERMS=3: Ah*Wh + Al*Wh + Ah*Wl.  TERMS=2: Ah*Wh + Al*Wh (no Wl).
#define AP2 40              // 32 + 8 pad (80B stride, conflict-free)
#define WP2 264             // 256 + 8 pad
#define FSA (128*AP2*2)     // 10240
#define FSW (32*WP2*2)      // 16896
#define FSMEM3 (3*(2*FSA + 2*FSW))   // 162816
#define FSMEM2 (3*(2*FSA + FSW))     // 112128

template<int TERMS>
__device__ __forceinline__
void ff_core(const bf16* __restrict__ Ah, const bf16* __restrict__ Al,
             const bf16* __restrict__ Wh, const bf16* __restrict__ Wl,
             const float* __restrict__ bias, float* __restrict__ C,
             bf16* __restrict__ Ch, bf16* __restrict__ Cl,
             int N, int K, int mode, int row0, int col0)
{
    extern __shared__ __align__(16) char gdsm[];
    const uint32_t aAh = (uint32_t)__cvta_generic_to_shared(gdsm);
    const uint32_t aAl = aAh + 3*FSA;
    const uint32_t aWh = aAl + 3*FSA;
    const uint32_t aWl = aWh + 3*FSW;   // TERMS==3 only

    const int tid = threadIdx.x;

    // A: row = tid>>1, chunks (tid&1)*2 + {0,1}
    const int arow = tid >> 1;
    const int ach0 = (tid & 1) * 2;
    const char* pAh = (const char*)(Ah + (size_t)(row0 + arow) * K);
    const char* pAl = (const char*)(Al + (size_t)(row0 + arow) * K);
    const uint32_t dA0 = (uint32_t)((arow*AP2 + ach0*8) * 2);

    // W: col = (tid&31)*8, krows tid>>5 + {0,8,16,24}
    const int wk0 = tid >> 5;
    const int wcol = (tid & 31) * 8;
    const char* pWh = (const char*)(Wh + (size_t)wk0 * N + col0 + wcol);
    const char* pWl = (TERMS == 3) ? (const char*)(Wl + (size_t)wk0 * N + col0 + wcol) : nullptr;
    const uint32_t dW0 = (uint32_t)((wk0*WP2 + wcol) * 2);

    float acc[4][8][4];
    #pragma unroll
    for (int i = 0; i < 4; i++)
        #pragma unroll
        for (int j = 0; j < 8; j++)
            #pragma unroll
            for (int t = 0; t < 4; t++) acc[i][j][t] = 0.0f;

    const int wid = tid >> 5, lane = tid & 31;
    const int wm = wid & 1;
    const int wn = wid >> 1;
    const int lrow = lane & 15, lk = (lane >> 4) * 8;
    const uint32_t offA0 = (uint32_t)(((wm*64 + lrow) * AP2 + lk) * 2);
    const uint32_t offB0 = (uint32_t)(((lane & 15) * WP2 + wn*64 + (lane>>4)*8) * 2);

    const int nit = K / 32;

    auto load_stage = [&](int st, int it2) {
        size_t ka = (size_t)it2 * 32 * 2;
        size_t kw = (size_t)it2 * 32 * (size_t)N * 2;
        uint32_t sa = aAh + (uint32_t)(st*FSA);
        uint32_t sl = aAl + (uint32_t)(st*FSA);
        #pragma unroll
        for (int j = 0; j < 2; j++) {
            uint32_t so = dA0 + (uint32_t)(j*16);       // +8 elems
            size_t  go = ka + (size_t)(ach0 + j) * 16;  // +8 elems = 16 B
            cp16(sa + so, pAh + go);
            cp16(sl + so, pAl + go);
        }
        uint32_t swh = aWh + (uint32_t)(st*FSW);
        #pragma unroll
        for (int j = 0; j < 4; j++) {
            uint32_t so = dW0 + (uint32_t)(j*8*WP2*2);
            size_t  go = kw + (size_t)(j*8) * N * 2;
            cp16(swh + so, pWh + go);
        }
        if (TERMS == 3) {
            uint32_t swl = aWl + (uint32_t)(st*FSW);
            #pragma unroll
            for (int j = 0; j < 4; j++) {
                uint32_t so = dW0 + (uint32_t)(j*8*WP2*2);
                size_t  go = kw + (size_t)(j*8) * N * 2;
                cp16(swl + so, pWl + go);
            }
        }
        cp_commit();
    };

    load_stage(0, 0);
    load_stage(1, 1);

    for (int it = 0; it < nit; ++it) {
        int rem = nit - 1 - it;
        if (rem >= 1) cp_wait1(); else cp_wait0();
        __syncthreads();
        if (it + 2 < nit) {
            int st = (it + 2) % 3;
            load_stage(st, it + 2);
        }
        const uint32_t s = (uint32_t)(it % 3);

        #pragma unroll
        for (int kh = 0; kh < 2; kh++) {
            const uint32_t kaoff = (uint32_t)(kh * 16 * 2);         // A: +16 elems
            const uint32_t kwoff = (uint32_t)(kh * 16 * WP2 * 2);   // W: +16 k-rows

            uint32_t afh[4][4];
            #pragma unroll
            for (int mi = 0; mi < 4; mi++)
                ldsm4(afh[mi], aAh + s*FSA + offA0 + kaoff + (uint32_t)(mi*16*AP2*2));
            uint32_t afl[4][4];
            #pragma unroll
            for (int mi = 0; mi < 4; mi++)
                ldsm4(afl[mi], aAl + s*FSA + offA0 + kaoff + (uint32_t)(mi*16*AP2*2));

            uint32_t bfr[8][2];
            #pragma unroll
            for (int ng = 0; ng < 4; ng++)
                ldsm4t(bfr[2*ng][0], bfr[2*ng][1], bfr[2*ng+1][0], bfr[2*ng+1][1],
                       aWh + s*FSW + offB0 + kwoff + (uint32_t)(ng*16*2));

            #pragma unroll
            for (int mi = 0; mi < 4; mi++)
                #pragma unroll
                for (int ni = 0; ni < 8; ni++) {
                    mma16816(acc[mi][ni], afh[mi], bfr[ni][0], bfr[ni][1]);
                    mma16816(acc[mi][ni], afl[mi], bfr[ni][0], bfr[ni][1]);
                }

            if (TERMS == 3) {
                #pragma unroll
                for (int ng = 0; ng < 4; ng++)
                    ldsm4t(bfr[2*ng][0], bfr[2*ng][1], bfr[2*ng+1][0], bfr[2*ng+1][1],
                           aWl + s*FSW + offB0 + kwoff + (uint32_t)(ng*16*2));
                #pragma unroll
                for (int mi = 0; mi < 4; mi++)
                    #pragma unroll
                    for (int ni = 0; ni < 8; ni++)
                        mma16816(acc[mi][ni], afh[mi], bfr[ni][0], bfr[ni][1]);
            }
        }
    }

    #pragma unroll
    for (int mi = 0; mi < 4; mi++) {
        #pragma unroll
        for (int ni = 0; ni < 8; ni++) {
            int c = col0 + wn*64 + ni*8 + (lane & 3)*2;
            float bx = bias[c], by = bias[c + 1];
            #pragma unroll
            for (int rh = 0; rh < 2; rh++) {
                size_t r = (size_t)(row0 + wm*64 + mi*16 + (lane >> 2) + rh*8);
                float v0 = acc[mi][ni][2*rh]     + bx;
                float v1 = acc[mi][ni][2*rh + 1] + by;
                if (mode & 1) {
                    v0 = 0.5f * v0 * (1.0f + erff(v0 * 0.70710678118654752f));
                    v1 = 0.5f * v1 * (1.0f + erff(v1 * 0.70710678118654752f));
                }
                if (mode & 2) {
                    float2 o; o.x = v0; o.y = v1;
                    *(float2*)&C[r * N + c] = o;
                }
                if (mode & 4) {
                    uint32_t hp, lp;
                    pack_pair(v0, v1, hp, lp);
                    *(uint32_t*)&Ch[r * N + c] = hp;
                    *(uint32_t*)&Cl[r * N + c] = lp;
                }
            }
        }
    }
}

__global__ __launch_bounds__(256, 1)
void ff3_gemm_kernel(const bf16* __restrict__ Ah, const bf16* __restrict__ Al,
                     const bf16* __restrict__ Wh, const bf16* __restrict__ Wl,
                     const float* __restrict__ bias,
                     bf16* __restrict__ Ch, bf16* __restrict__ Cl,
                     int N, int K, int mode)
{
    ff_core<3>(Ah, Al, Wh, Wl, bias, nullptr, Ch, Cl, N, K, mode,
               blockIdx.y * 128, blockIdx.x * 256);
}

__global__ __launch_bounds__(256, 1)
void ff2_gemm_kernel(const bf16* __restrict__ Ah, const bf16* __restrict__ Al,
                     const bf16* __restrict__ Wh,
                     const float* __restrict__ bias, float* __restrict__ C,
                     int N, int K, int mode)
{
    ff_core<2>(Ah, Al, Wh, nullptr, bias, C, nullptr, nullptr, N, K, mode,
               blockIdx.y * 128, blockIdx.x * 256);
}

// ---------------- sigmoid gate ----------------------
__global__ __launch_bounds__(256)
void gate_kernel(const float* __restrict__ x, const float* __restrict__ wg,
                 const float* __restrict__ bg, float* __restrict__ gate)
{
    __shared__ float wgs[Dsz][8];
    int hg = blockIdx.y;
    int tid = threadIdx.x;
    for (int idx = tid; idx < Dsz*8; idx += 256)
        wgs[idx >> 3][idx & 7] = wg[(idx >> 3) * Hsz + hg*8 + (idx & 7)];
    __syncthreads();

    int h = tid & 7, r = tid >> 3;
    int m = blockIdx.x * 32 + r;
    const float4* xr = (const float4*)(x + (size_t)m * Dsz);
    float s = 0.0f;
    #pragma unroll 4
    for (int d4 = 0; d4 < Dsz/4; d4++) {
        float4 xv = xr[d4];
        s = fmaf(xv.x, wgs[d4*4 + 0][h], s);
        s = fmaf(xv.y, wgs[d4*4 + 1][h], s);
        s = fmaf(xv.z, wgs[d4*4 + 2][h], s);
        s = fmaf(xv.w, wgs[d4*4 + 3][h], s);
    }
    s += bg[hg*8 + h];
    gate[(size_t)m * Hsz + hg*8 + h] = 1.0f / (1.0f + __expf(-s));
}

// ---------------- tensor-core flash attention (bf16, 128-q tile, 8 warps) ------
#define FPAD 72
#define KV_STRIDE (64*FPAD)
#define Q_STRIDE  (128*FPAD)
#define KV_STAGE  (2*KV_STRIDE)
#define FLASH_SMEM (Q_STRIDE*2 + 2*KV_STAGE*2 + 2*64*4)

__global__ __launch_bounds__(256, 2)
void flash_tc_kernel(const bf16* __restrict__ Qh,
                     const bf16* __restrict__ Kh,
                     const bf16* __restrict__ Vh,
                     const float* __restrict__ gate, const int* __restrict__ mask,
                     bf16* __restrict__ Ch)
{
    extern __shared__ __align__(16) char dynsmem[];
    const uint32_t qbase = (uint32_t)__cvta_generic_to_shared(dynsmem);
    const uint32_t kvbase = qbase + Q_STRIDE*2;
    const uint32_t mbase = kvbase + 2*KV_STAGE*2;
    int* smsk = (int*)(dynsmem + (size_t)Q_STRIDE*2 + (size_t)2*KV_STAGE*2);

    const int tid = threadIdx.x, lane = tid & 31, warp = tid >> 5;
    const int qt = blockIdx.x, h = blockIdx.y, b = blockIdx.z;
    const size_t rowbase = (size_t)b * Ssz;
    const size_t hoff = (size_t)h * DKsz;

    {
        int r = tid >> 1;
        size_t gq = (rowbase + qt*128 + r) * Dsz + hoff;
        #pragma unroll
        for (int j = 0; j < 4; j++) {
            int c8 = (tid & 1)*4 + j;
            uint32_t dof = (uint32_t)((r*FPAD + c8*8)*2);
            cp16(qbase + dof, Qh + gq + c8*8);
        }
        cp_commit(); cp_wait0();
    }
    __syncthreads();

    uint32_t qfh[4][4];
    {
        uint32_t arow = (uint32_t)((warp*16 + (lane&15))*FPAD*2);
        #pragma unroll
        for (int ks = 0; ks < 4; ks++) {
            uint32_t acol = (uint32_t)((16*ks + (lane>>4)*8)*2);
            ldsm4(qfh[ks], qbase + arow + acol);
        }
    }
    __syncthreads();

    float oacc[8][4];
    #pragma unroll
    for (int i = 0; i < 8; i++)
        #pragma unroll
        for (int j = 0; j < 4; j++) oacc[i][j] = 0.0f;
    float m0 = -1e30f, m1 = -1e30f, l0 = 0.0f, l1 = 0.0f;

    const int r_ld = tid >> 2;
    const int cbase = (tid & 3)*2;

    {
        size_t g = (rowbase + r_ld) * Dsz + hoff;
        #pragma unroll
        for (int j = 0; j < 2; j++) {
            int c8 = cbase + j;
            uint32_t dof = (uint32_t)((r_ld*FPAD + c8*8)*2);
            cp16(kvbase + dof, Kh + g + c8*8);
            cp16(kvbase + KV_STRIDE*2 + dof, Vh + g + c8*8);
        }
        if (tid < 16) cp16(mbase + tid*16, mask + rowbase + tid*4);
        cp_commit();
    }

    const int col0 = 2*(lane & 3);

    for (int kt = 0; kt < Ssz/64; kt++) {
        cp_wait0();
        __syncthreads();
        if (kt + 1 < Ssz/64) {
            int st = (kt + 1) & 1;
            size_t g = (rowbase + (kt+1)*64 + r_ld) * Dsz + hoff;
            uint32_t sb = kvbase + (uint32_t)(st*KV_STAGE*2);
            #pragma unroll
            for (int j = 0; j < 2; j++) {
                int c8 = cbase + j;
                uint32_t dof = (uint32_t)((r_ld*FPAD + c8*8)*2);
                cp16(sb + dof, Kh + g + c8*8);
                cp16(sb + KV_STRIDE*2 + dof, Vh + g + c8*8);
            }
            if (tid < 16) cp16(mbase + st*256 + tid*16, mask + rowbase + (kt+1)*64 + tid*4);
            cp_commit();
        }
        const int st = kt & 1;
        const uint32_t kb = kvbase + (uint32_t)(st*KV_STAGE*2);

        float sc[8][4];
        #pragma unroll
        for (int i = 0; i < 8; i++)
            #pragma unroll
            for (int j = 0; j < 4; j++) sc[i][j] = 0.0f;

        const uint32_t brow = (uint32_t)(((lane&7) + ((lane>>1)&8)) * FPAD * 2);
        const uint32_t bcol = (uint32_t)((lane & 8) * 2);
        #pragma unroll
        for (int ng = 0; ng < 4; ng++) {
            #pragma unroll
            for (int ks = 0; ks < 4; ks++) {
                uint32_t ba = kb + brow + (uint32_t)(16*ng*FPAD*2) + bcol + (uint32_t)(16*ks*2);
                uint32_t bh4[4];
                ldsm4(bh4, ba);
                mma16816(sc[2*ng],   qfh[ks], bh4[0], bh4[1]);
                mma16816(sc[2*ng+1], qfh[ks], bh4[2], bh4[3]);
            }
        }

        const int* mk = smsk + st*64;
        float mx0 = -1e30f, mx1 = -1e30f;
        #pragma unroll
        for (int ni = 0; ni < 8; ni++) {
            int c = 8*ni + col0;
            bool z0 = (mk[c] == 0), z1 = (mk[c+1] == 0);
            sc[ni][0] = z0 ? -1e9f : sc[ni][0]*0.125f;
            sc[ni][1] = z1 ? -1e9f : sc[ni][1]*0.125f;
            sc[ni][2] = z0 ? -1e9f : sc[ni][2]*0.125f;
            sc[ni][3] = z1 ? -1e9f : sc[ni][3]*0.125f;
            mx0 = fmaxf(mx0, fmaxf(sc[ni][0], sc[ni][1]));
            mx1 = fmaxf(mx1, fmaxf(sc[ni][2], sc[ni][3]));
        }
        mx0 = fmaxf(mx0, __shfl_xor_sync(0xffffffffu, mx0, 1));
        mx0 = fmaxf(mx0, __shfl_xor_sync(0xffffffffu, mx0, 2));
        mx1 = fmaxf(mx1, __shfl_xor_sync(0xffffffffu, mx1, 1));
        mx1 = fmaxf(mx1, __shfl_xor_sync(0xffffffffu, mx1, 2));
        float mn0 = fmaxf(m0, mx0), mn1 = fmaxf(m1, mx1);
        float al0 = __expf(m0 - mn0), al1 = __expf(m1 - mn1);
        float rs0 = 0.0f, rs1 = 0.0f;
        #pragma unroll
        for (int ni = 0; ni < 8; ni++) {
            sc[ni][0] = __expf(sc[ni][0] - mn0);
            sc[ni][1] = __expf(sc[ni][1] - mn0);
            sc[ni][2] = __expf(sc[ni][2] - mn1);
            sc[ni][3] = __expf(sc[ni][3] - mn1);
            rs0 += sc[ni][0] + sc[ni][1];
            rs1 += sc[ni][2] + sc[ni][3];
        }
        rs0 += __shfl_xor_sync(0xffffffffu, rs0, 1);
        rs0 += __shfl_xor_sync(0xffffffffu, rs0, 2);
        rs1 += __shfl_xor_sync(0xffffffffu, rs1, 1);
        rs1 += __shfl_xor_sync(0xffffffffu, rs1, 2);
        l0 = l0*al0 + rs0; l1 = l1*al1 + rs1;
        m0 = mn0; m1 = mn1;
        #pragma unroll
        for (int ni = 0; ni < 8; ni++) {
            oacc[ni][0] *= al0; oacc[ni][1] *= al0;
            oacc[ni][2] *= al1; oacc[ni][3] *= al1;
        }

        const uint32_t vrow0 = (uint32_t)((lane&15)*FPAD*2);
        const uint32_t vcol0 = (uint32_t)(((lane>>4)*8)*2);
        #pragma unroll
        for (int ki = 0; ki < 4; ki++) {
            uint32_t ph[4];
            ph[0] = pack_hi(sc[2*ki][0],   sc[2*ki][1]);
            ph[1] = pack_hi(sc[2*ki][2],   sc[2*ki][3]);
            ph[2] = pack_hi(sc[2*ki+1][0], sc[2*ki+1][1]);
            ph[3] = pack_hi(sc[2*ki+1][2], sc[2*ki+1][3]);
            uint32_t va0 = kb + KV_STRIDE*2 + vrow0 + (uint32_t)(16*ki*FPAD*2) + vcol0;
            #pragma unroll
            for (int ngd = 0; ngd < 4; ngd++) {
                uint32_t vh4[4];
                ldsm4t(vh4[0], vh4[1], vh4[2], vh4[3], va0 + (uint32_t)(16*ngd*2));
                mma16816(oacc[2*ngd],   ph, vh4[0], vh4[1]);
                mma16816(oacc[2*ngd+1], ph, vh4[2], vh4[3]);
            }
        }
    }

    int q0 = qt*128 + warp*16 + (lane >> 2);
    float f0 = gate[(rowbase + q0)*Hsz + h] / l0;
    float f1 = gate[(rowbase + q0 + 8)*Hsz + h] / l1;
    #pragma unroll
    for (int ni = 0; ni < 8; ni++) {
        size_t o0 = (rowbase + q0) * Dsz + hoff + 8*ni + col0;
        size_t o1 = o0 + (size_t)8 * Dsz;
        *(uint32_t*)&Ch[o0] = pack_hi(oacc[ni][0]*f0, oacc[ni][1]*f0);
        *(uint32_t*)&Ch[o1] = pack_hi(oacc[ni][2]*f1, oacc[ni][3]*f1);
    }
}

// ---------------- fused residual add + LayerNorm (+ optional bf16 split out) ----
__global__ __launch_bounds__(256)
void add_ln_kernel(const float* __restrict__ a, const float* __restrict__ bsrc,
                   const float* __restrict__ g, const float* __restrict__ beta,
                   float* __restrict__ out, bf16* __restrict__ oh, bf16* __restrict__ ol)
{
    int row = blockIdx.x;
    int tid = threadIdx.x;
    __shared__ float buf[Dsz];
    __shared__ float rsum[8], rsq[8];

    size_t base = (size_t)row * Dsz;
    float ls = 0.0f, lq = 0.0f;
    for (int d = tid; d < Dsz; d += 256) {
        float v = a[base + d] + bsrc[base + d];
        buf[d] = v;
        ls += v; lq += v * v;
    }
    int warp = tid >> 5, lane = tid & 31;
    for (int off = 16; off; off >>= 1) {
        ls += __shfl_xor_sync(0xffffffffu, ls, off);
        lq += __shfl_xor_sync(0xffffffffu, lq, off);
    }
    if (lane == 0) { rsum[warp] = ls; rsq[warp] = lq; }
    __syncthreads();
    float ts = 0.0f, tq = 0.0f;
    #pragma unroll
    for (int w = 0; w < 8; w++) { ts += rsum[w]; tq += rsq[w]; }
    float mean = ts * (1.0f / Dsz);
    float var  = tq * (1.0f / Dsz) - mean * mean;
    float rstd = rsqrtf(var + 1e-5f);
    for (int d = tid; d < Dsz; d += 256) {
        float v = (buf[d] - mean) * rstd * g[d] + beta[d];
        out[base + d] = v;
        if (oh) {
            bf16 hv = __float2bfloat16(v);
            oh[base + d] = hv;
            ol[base + d] = __float2bfloat16(v - __bfloat162float(hv));
        }
    }
}

// ---------------- launch ----------------
extern "C" void kernel_launch(void* const* d_in, const int* in_sizes, int n_in,
                              void* d_out, int out_size)
{
    const float* x     = (const float*)d_in[0];
    const float* w_q   = (const float*)d_in[1];
    const float* b_q   = (const float*)d_in[2];
    const float* w_k   = (const float*)d_in[3];
    const float* b_k   = (const float*)d_in[4];
    const float* w_v   = (const float*)d_in[5];
    const float* b_v   = (const float*)d_in[6];
    const float* w_o   = (const float*)d_in[7];
    const float* b_o   = (const float*)d_in[8];
    const float* w_g   = (const float*)d_in[9];
    const float* b_g   = (const float*)d_in[10];
    const float* w1    = (const float*)d_in[11];
    const float* b1    = (const float*)d_in[12];
    const float* w2    = (const float*)d_in[13];
    const float* b2    = (const float*)d_in[14];
    const float* g1    = (const float*)d_in[15];
    const float* beta1 = (const float*)d_in[16];
    const float* g2    = (const float*)d_in[17];
    const float* beta2 = (const float*)d_in[18];
    const int*   mask  = (const int*)  d_in[19];
    float* out = (float*)d_out;

    float *tmp, *x1, *gate;
    cudaGetSymbolAddress((void**)&tmp,  g_tmp);
    cudaGetSymbolAddress((void**)&x1,   g_x1);
    cudaGetSymbolAddress((void**)&gate, g_gate);

    bf16 *xh,*xl,*qh,*kh,*vh,*ctxh,*x1h,*x1l,*ffh,*ffl;
    bf16 *wqh,*wkh,*wvh,*woh,*w1h,*w1l,*w2h;
    cudaGetSymbolAddress((void**)&xh,  g_xh);   cudaGetSymbolAddress((void**)&xl,  g_xl);
    cudaGetSymbolAddress((void**)&qh,  g_qh);
    cudaGetSymbolAddress((void**)&kh,  g_kh);
    cudaGetSymbolAddress((void**)&vh,  g_vh);
    cudaGetSymbolAddress((void**)&ctxh,g_ctxh);
    cudaGetSymbolAddress((void**)&x1h, g_x1h);  cudaGetSymbolAddress((void**)&x1l, g_x1l);
    cudaGetSymbolAddress((void**)&ffh, g_ffh);  cudaGetSymbolAddress((void**)&ffl, g_ffl);
    cudaGetSymbolAddress((void**)&wqh, g_wqh);
    cudaGetSymbolAddress((void**)&wkh, g_wkh);
    cudaGetSymbolAddress((void**)&wvh, g_wvh);
    cudaGetSymbolAddress((void**)&woh, g_woh);
    cudaGetSymbolAddress((void**)&w1h, g_w1h);  cudaGetSymbolAddress((void**)&w1l, g_w1l);
    cudaGetSymbolAddress((void**)&w2h, g_w2h);

    cudaFuncSetAttribute(flash_tc_kernel,
                         cudaFuncAttributeMaxDynamicSharedMemorySize, FLASH_SMEM);
    cudaFuncSetAttribute(gemm_bf16x1_kernel,
                         cudaFuncAttributeMaxDynamicSharedMemorySize, GSMEM1);
    cudaFuncSetAttribute(qkv_gemm_kernel,
                         cudaFuncAttributeMaxDynamicSharedMemorySize, GSMEM1);
    cudaFuncSetAttribute(ff3_gemm_kernel,
                         cudaFuncAttributeMaxDynamicSharedMemorySize, FSMEM3);
    cudaFuncSetAttribute(ff2_gemm_kernel,
                         cudaFuncAttributeMaxDynamicSharedMemorySize, FSMEM2);

    // 0: split x (hi+lo)
    split_x_kernel<<<Msz*Dsz/(4*512), 256>>>(x, xh, xl);

    // 1: split weights (w1 hi+lo; others hi only)
    SplitWArgs sw;
    sw.src[0] = w_q; sw.hi[0] = wqh; sw.lo[0] = nullptr;
    sw.src[1] = w_k; sw.hi[1] = wkh; sw.lo[1] = nullptr;
    sw.src[2] = w_v; sw.hi[2] = wvh; sw.lo[2] = nullptr;
    sw.src[3] = w_o; sw.hi[3] = woh; sw.lo[3] = nullptr;
    sw.src[4] = w1;  sw.hi[4] = w1h; sw.lo[4] = w1l;
    sw.src[5] = w2;  sw.hi[5] = w2h; sw.lo[5] = nullptr;
    split_w_kernel<<<6144, 256>>>(sw);

    // 2: gate
    gate_kernel<<<dim3(Msz/32, 2), 256>>>(x, w_g, b_g, gate);

    // 3: merged QKV GEMM (1-term, BN=128) <- profiled slot
    QKVArgs qa;
    qa.Wh[0] = wqh; qa.bias[0] = b_q; qa.Ch[0] = qh;
    qa.Wh[1] = wkh; qa.bias[1] = b_k; qa.Ch[1] = kh;
    qa.Wh[2] = wvh; qa.bias[2] = b_v; qa.Ch[2] = vh;
    qkv_gemm_kernel<<<dim3(Dsz/128, Msz/128, 3), 256, GSMEM1>>>(xh, qa);

    // 4: flash attention
    flash_tc_kernel<<<dim3(Ssz/128, Hsz, Bsz), 256, FLASH_SMEM>>>(
        qh, kh, vh, gate, mask, ctxh);

    // 5: O-proj (1-term, BN=128)
    gemm_bf16x1_kernel<<<dim3(Dsz/128, Msz/128), 256, GSMEM1>>>(
        ctxh, woh, b_o, tmp, nullptr, Dsz, Dsz, 2);
    // 6: LN1
    add_ln_kernel<<<Msz, 256>>>(x, tmp, g1, beta1, x1, x1h, x1l);
    // 7: FF1 (3-term, BK=32, GELU -> ffh/ffl)
    ff3_gemm_kernel<<<dim3(DFFsz/256, Msz/128), 256, FSMEM3>>>(
        x1h, x1l, w1h, w1l, b1, ffh, ffl, DFFsz, Dsz, 5);
    // 8: FF2 (2-term, BK=32 -> fp32 tmp)
    ff2_gemm_kernel<<<dim3(Dsz/256, Msz/128), 256, FSMEM2>>>(
        ffh, ffl, w2h, b2, tmp, Dsz, DFFsz, 2);
    // 9: LN2
    add_ln_kernel<<<Msz, 256>>>(x1, tmp, g2, beta2, out, nullptr, nullptr);
}